// round 6
// baseline (speedup 1.0000x reference)
#include <cuda_runtime.h>
#include <cuda_fp16.h>
#include <math.h>

#define MAXN 50000

// scratch (device globals — no allocation allowed)
__device__ float g_chis[MAXN];
__device__ float g_sigA[MAXN];
__device__ float g_epsA[MAXN];
__device__ float g_w[MAXN * 16];
__device__ float g_scal[2];   // pot, vdw

// ---- constant-bank weight slices for phase1/nodes (unchanged from R5) ----
__constant__ float cWc1[40 * 16];   // Wc1 rows 24..63
__constant__ float cWs1[40 * 32];   // Ws1 rows 24..63
__constant__ float cWe1[40 * 32];   // We1 rows 24..63
__constant__ float cWc2[16];
__constant__ float cWs2[32];
__constant__ float cWe2[32];
__constant__ float cWw1[17 * 16];

__device__ __forceinline__ float siluf(float z) {
    return __fdividef(z, 1.0f + __expf(-z));
}
__device__ __forceinline__ float sigmf(float z) {
    return __fdividef(1.0f, 1.0f + __expf(-z));
}

// ---- packed f32x2 helpers (SASS FFMA2) for phase1 ----
__device__ __forceinline__ unsigned long long dup2(float v) {
    unsigned long long r;
    asm("mov.b64 %0, {%1, %1};" : "=l"(r) : "f"(v));
    return r;
}
__device__ __forceinline__ void ffma2(unsigned long long& d,
                                      unsigned long long a,
                                      unsigned long long b) {
    asm("fma.rn.f32x2 %0, %1, %2, %0;" : "+l"(d) : "l"(a), "l"(b));
}
__device__ __forceinline__ float2 unpk(unsigned long long v) {
    float2 f;
    asm("mov.b64 {%0, %1}, %2;" : "=f"(f.x), "=f"(f.y) : "l"(v));
    return f;
}
__device__ __forceinline__ float sel4(float4 v, int sub) {
    return (sub == 0) ? v.x : (sub == 1) ? v.y : (sub == 2) ? v.z : v.w;
}

// ---- MMA helpers (phase3) ----
__device__ __forceinline__ unsigned smaddr(const void* p) {
    unsigned a;
    asm("{ .reg .u64 t; cvta.to.shared.u64 t, %1; cvt.u32.u64 %0, t; }"
        : "=r"(a) : "l"(p));
    return a;
}
__device__ __forceinline__ void ldsm_x4(unsigned& r0, unsigned& r1,
                                        unsigned& r2, unsigned& r3, unsigned addr) {
    asm volatile("ldmatrix.sync.aligned.m8n8.x4.shared.b16 {%0,%1,%2,%3}, [%4];"
                 : "=r"(r0), "=r"(r1), "=r"(r2), "=r"(r3) : "r"(addr));
}
__device__ __forceinline__ void ldsm_x2t(unsigned& r0, unsigned& r1, unsigned addr) {
    asm volatile("ldmatrix.sync.aligned.m8n8.x2.trans.shared.b16 {%0,%1}, [%2];"
                 : "=r"(r0), "=r"(r1) : "r"(addr));
}
__device__ __forceinline__ void mma16816(float* c,
                                         unsigned a0, unsigned a1, unsigned a2, unsigned a3,
                                         unsigned b0, unsigned b1) {
    asm volatile(
        "mma.sync.aligned.m16n8k16.row.col.f32.f16.f16.f32 "
        "{%0,%1,%2,%3}, {%4,%5,%6,%7}, {%8,%9}, {%0,%1,%2,%3};"
        : "+f"(c[0]), "+f"(c[1]), "+f"(c[2]), "+f"(c[3])
        : "r"(a0), "r"(a1), "r"(a2), "r"(a3), "r"(b0), "r"(b1));
}
// split (a,b) into packed fp16 hi + lo (error compensation)
__device__ __forceinline__ void split2(float a, float b, unsigned& hi, unsigned& lo) {
    __half ha = __float2half_rn(a), hb = __float2half_rn(b);
    float ra = a - __half2float(ha);
    float rb = b - __half2float(hb);
    __half2 H = __halves2half2(ha, hb);
    __half2 L = __floats2half2_rn(ra, rb);
    hi = *reinterpret_cast<unsigned*>(&H);
    lo = *reinterpret_cast<unsigned*>(&L);
}

__global__ void k_zero(int N) {
    int i = blockIdx.x * blockDim.x + threadIdx.x;
    if (i < N) { g_chis[i] = 0.f; g_sigA[i] = 0.f; g_epsA[i] = 0.f; }
    if (i < 2) g_scal[i] = 0.f;
}

// ---------------------------------------------------------------------------
// Phase 1 (unchanged from R5): fused chi/sigma/eps MLPs, M=2, dual-port.
// ---------------------------------------------------------------------------
__global__ __launch_bounds__(256) void k_phase1(
    const float* __restrict__ x, const int* __restrict__ senders,
    const float* __restrict__ Wc1, const float* __restrict__ Ws1,
    const float* __restrict__ We1, int E)
{
    __shared__ __align__(16) float sW[24 * 80];
    for (int i = threadIdx.x; i < 24 * 80; i += 256) {
        int k = i / 80, h = i - (i / 80) * 80;
        float v;
        if (h < 16)      v = Wc1[k * 16 + h];
        else if (h < 48) v = Ws1[k * 32 + (h - 16)];
        else             v = We1[k * 32 + (h - 48)];
        sW[i] = v;
    }
    __syncthreads();

    int lane = threadIdx.x & 127;
    int sel  = threadIdx.x >> 7;
    int e0 = blockIdx.x * 256 + lane;
    if (e0 >= E) return;
    int e1 = e0 + 128;
    bool has1 = (e1 < E);

    const float s64 = 0.125f;
    const float s32 = 0.17677669529663689f;

    unsigned long long acc[40];
#pragma unroll
    for (int i = 0; i < 40; i++) acc[i] = 0ull;

    const float4* x0 = reinterpret_cast<const float4*>(x) + (size_t)e0 * 16;
    const float4* x1 = reinterpret_cast<const float4*>(x) + (size_t)(has1 ? e1 : e0) * 16;

#pragma unroll 1
    for (int kc = 0; kc < 6; kc++) {
        float4 a0 = x0[kc], a1 = x1[kc];
#pragma unroll
        for (int sub = 0; sub < 4; sub++) {
            int k = kc * 4 + sub;
            unsigned long long xd0 = dup2(sel4(a0, sub) * s64);
            unsigned long long xd1 = dup2(sel4(a1, sub) * s64);
            const ulonglong2* w =
                reinterpret_cast<const ulonglong2*>(sW + k * 80 + sel * 40);
#pragma unroll
            for (int j = 0; j < 10; j++) {
                ulonglong2 wv = w[j];
                ffma2(acc[2 * j],          xd0, wv.x);
                ffma2(acc[2 * j + 1],      xd0, wv.y);
                ffma2(acc[20 + 2 * j],     xd1, wv.x);
                ffma2(acc[20 + 2 * j + 1], xd1, wv.y);
            }
        }
    }

    if (sel == 0) {
#pragma unroll 1
        for (int kc = 6; kc < 16; kc++) {
            float4 a0 = x0[kc], a1 = x1[kc];
#pragma unroll
            for (int sub = 0; sub < 4; sub++) {
                int kk = kc * 4 + sub - 24;
                unsigned long long xd0 = dup2(sel4(a0, sub) * s64);
                unsigned long long xd1 = dup2(sel4(a1, sub) * s64);
                const ulonglong2* wa =
                    reinterpret_cast<const ulonglong2*>(cWc1 + kk * 16);
                const ulonglong2* wb =
                    reinterpret_cast<const ulonglong2*>(cWs1 + kk * 32);
#pragma unroll
                for (int j = 0; j < 4; j++) {
                    ulonglong2 wv = wa[j];
                    ffma2(acc[2 * j],          xd0, wv.x);
                    ffma2(acc[2 * j + 1],      xd0, wv.y);
                    ffma2(acc[20 + 2 * j],     xd1, wv.x);
                    ffma2(acc[20 + 2 * j + 1], xd1, wv.y);
                }
#pragma unroll
                for (int j = 0; j < 6; j++) {
                    ulonglong2 wv = wb[j];
                    ffma2(acc[8 + 2 * j],      xd0, wv.x);
                    ffma2(acc[9 + 2 * j],      xd0, wv.y);
                    ffma2(acc[28 + 2 * j],     xd1, wv.x);
                    ffma2(acc[29 + 2 * j],     xd1, wv.y);
                }
            }
        }
    } else {
#pragma unroll 1
        for (int kc = 6; kc < 16; kc++) {
            float4 a0 = x0[kc], a1 = x1[kc];
#pragma unroll
            for (int sub = 0; sub < 4; sub++) {
                int kk = kc * 4 + sub - 24;
                unsigned long long xd0 = dup2(sel4(a0, sub) * s64);
                unsigned long long xd1 = dup2(sel4(a1, sub) * s64);
                const ulonglong2* wa =
                    reinterpret_cast<const ulonglong2*>(cWs1 + kk * 32 + 24);
                const ulonglong2* wb =
                    reinterpret_cast<const ulonglong2*>(cWe1 + kk * 32);
#pragma unroll
                for (int j = 0; j < 2; j++) {
                    ulonglong2 wv = wa[j];
                    ffma2(acc[2 * j],          xd0, wv.x);
                    ffma2(acc[2 * j + 1],      xd0, wv.y);
                    ffma2(acc[20 + 2 * j],     xd1, wv.x);
                    ffma2(acc[20 + 2 * j + 1], xd1, wv.y);
                }
#pragma unroll
                for (int j = 0; j < 8; j++) {
                    ulonglong2 wv = wb[j];
                    ffma2(acc[4 + 2 * j],      xd0, wv.x);
                    ffma2(acc[5 + 2 * j],      xd0, wv.y);
                    ffma2(acc[24 + 2 * j],     xd1, wv.x);
                    ffma2(acc[25 + 2 * j],     xd1, wv.y);
                }
            }
        }
    }

    int s0 = senders[e0];
    int s1 = has1 ? senders[e1] : 0;

#pragma unroll
    for (int eidx = 0; eidx < 2; eidx++) {
        if (eidx == 1 && !has1) break;
        int base = eidx * 20;
        float pA = 0.f, pB = 0.f;
        if (sel == 0) {
#pragma unroll
            for (int j = 0; j < 8; j++) {
                float2 f = unpk(acc[base + j]);
                pA += siluf(f.x) * cWc2[2 * j] + siluf(f.y) * cWc2[2 * j + 1];
            }
#pragma unroll
            for (int j = 8; j < 20; j++) {
                float2 f = unpk(acc[base + j]);
                pB += siluf(f.x) * cWs2[2 * (j - 8)] + siluf(f.y) * cWs2[2 * (j - 8) + 1];
            }
            pA *= 0.25f;
            pB *= s32;
            int s = eidx ? s1 : s0;
            atomicAdd(&g_chis[s], pA);
            atomicAdd(&g_sigA[s], pB);
        } else {
#pragma unroll
            for (int j = 0; j < 4; j++) {
                float2 f = unpk(acc[base + j]);
                pA += siluf(f.x) * cWs2[24 + 2 * j] + siluf(f.y) * cWs2[24 + 2 * j + 1];
            }
#pragma unroll
            for (int j = 4; j < 20; j++) {
                float2 f = unpk(acc[base + j]);
                pB += siluf(f.x) * cWe2[2 * (j - 4)] + siluf(f.y) * cWe2[2 * (j - 4) + 1];
            }
            pA *= s32;
            pB *= s32;
            int s = eidx ? s1 : s0;
            atomicAdd(&g_sigA[s], pA);
            atomicAdd(&g_epsA[s], pB);
        }
    }
}

// ---------------------------------------------------------------------------
// Phase 2 (unchanged): per-node charges / pot / vdw / w embedding.
// ---------------------------------------------------------------------------
__global__ __launch_bounds__(256) void k_nodes(
    const int* __restrict__ species, const float* __restrict__ radius,
    const float* __restrict__ hardness, const float* __restrict__ charge_embed,
    float* __restrict__ out_charges, int N)
{
    int n = blockIdx.x * 256 + threadIdx.x;
    float potc = 0.f, vdwc = 0.f;
    if (n < N) {
        int sp = species[n];
        float gamma = fmaf(4.f, radius[sp], 0.5f);
        float hv = hardness[sp];
        float hard = fmaxf(hv, 0.f) + log1pf(__expf(-fabsf(hv)));
        float chis = g_chis[n];
        float q = -chis / hard;
        potc = 0.5f * (hard + 1.f / gamma) * q * q + chis * q;
        float sgv = sigmf(g_sigA[n]) * 0.15f + 0.15f;
        float epv = sigmf(g_epsA[n]) * 1.7f + 0.3f;
        vdwc = sgv * epv;
        out_charges[n] = q;

        const float s17 = 0.24253562503633297f;
        const float* ce = charge_embed + (size_t)sp * 16;
        float wv[16];
        float qs = q * s17;
#pragma unroll
        for (int j = 0; j < 16; j++) wv[j] = qs * cWw1[j];
#pragma unroll
        for (int i = 0; i < 16; i++) {
            float c = ce[i] * s17;
#pragma unroll
            for (int j = 0; j < 16; j++)
                wv[j] = fmaf(c, cWw1[(1 + i) * 16 + j], wv[j]);
        }
        float4* wout = reinterpret_cast<float4*>(g_w) + (size_t)n * 4;
#pragma unroll
        for (int j = 0; j < 4; j++)
            wout[j] = make_float4(wv[4 * j], wv[4 * j + 1], wv[4 * j + 2], wv[4 * j + 3]);
    }
#pragma unroll
    for (int off = 16; off > 0; off >>= 1) {
        potc += __shfl_down_sync(0xffffffffu, potc, off);
        vdwc += __shfl_down_sync(0xffffffffu, vdwc, off);
    }
    if ((threadIdx.x & 31) == 0) {
        atomicAdd(&g_scal[0], potc);
        atomicAdd(&g_scal[1], vdwc);
    }
}

// ---------------------------------------------------------------------------
// Phase 3: tensor-core version. 128 threads / 4 warps / 64 edges per CTA.
// A = [x | w_gather] split into fp16 hi+lo (K=160 logical), weights hi+lo.
// 3-term compensated fp16 MMA chain: 80->32 silu ->32 silu ->32, envelope.
// ---------------------------------------------------------------------------
#define LDA 168   // A row stride in halfs (80*2 = 160 cols + 8 pad)
#define LDW 40    // W row stride in halfs (32 cols + 8 pad)

__global__ __launch_bounds__(128) void k_phase3(
    const float* __restrict__ x, const float* __restrict__ vectors,
    const float* __restrict__ V, const int* __restrict__ senders,
    const float* __restrict__ Wx1, const float* __restrict__ Wx2,
    const float* __restrict__ Wx3,
    float* __restrict__ out_x, float* __restrict__ out_V,
    float* __restrict__ out_pv, int E)
{
    __shared__ __align__(16) __half sA[64 * LDA];
    __shared__ __align__(16) __half sW1h[80 * LDW], sW1l[80 * LDW];
    __shared__ __align__(16) __half sW2h[32 * LDW], sW2l[32 * LDW];
    __shared__ __align__(16) __half sW3h[32 * LDW], sW3l[32 * LDW];

    const float s80 = 0.11180339887498949f;   // 1/sqrt(80)
    const float s32 = 0.17677669529663689f;   // 1/sqrt(32)

    int tid = threadIdx.x;
    int eb = blockIdx.x * 64;

    if (blockIdx.x == 0 && tid == 0) {
        out_pv[0] = g_scal[0];
        out_pv[1] = g_scal[1];
    }

    // ---- stage weights (scale-folded, hi/lo split) ----
    for (int i = tid; i < 80 * 32; i += 128) {
        int k = i >> 5, n = i & 31;
        float v = Wx1[i] * s80;
        unsigned hi, lo;
        split2(v, 0.f, hi, lo);
        sW1h[k * LDW + n] = __ushort_as_half((unsigned short)(hi & 0xffff));
        sW1l[k * LDW + n] = __ushort_as_half((unsigned short)(lo & 0xffff));
    }
    for (int i = tid; i < 32 * 32; i += 128) {
        int k = i >> 5, n = i & 31;
        float v2 = Wx2[i] * s32;
        float v3 = Wx3[i] * s32;
        unsigned hi, lo;
        split2(v2, 0.f, hi, lo);
        sW2h[k * LDW + n] = __ushort_as_half((unsigned short)(hi & 0xffff));
        sW2l[k * LDW + n] = __ushort_as_half((unsigned short)(lo & 0xffff));
        split2(v3, 0.f, hi, lo);
        sW3h[k * LDW + n] = __ushort_as_half((unsigned short)(hi & 0xffff));
        sW3l[k * LDW + n] = __ushort_as_half((unsigned short)(lo & 0xffff));
    }

    // ---- stage A: x part (cols 0..63 hi, 80..143 lo) ----
    for (int i = tid; i < 64 * 16; i += 128) {
        int r = i >> 4, q = i & 15;
        int e = eb + r;
        float4 v = make_float4(0.f, 0.f, 0.f, 0.f);
        if (e < E) v = reinterpret_cast<const float4*>(x)[(size_t)e * 16 + q];
        unsigned h01, l01, h23, l23;
        split2(v.x, v.y, h01, l01);
        split2(v.z, v.w, h23, l23);
        __half* Ar = sA + r * LDA;
        *reinterpret_cast<unsigned*>(Ar + q * 4)       = h01;
        *reinterpret_cast<unsigned*>(Ar + q * 4 + 2)   = h23;
        *reinterpret_cast<unsigned*>(Ar + 80 + q * 4)     = l01;
        *reinterpret_cast<unsigned*>(Ar + 80 + q * 4 + 2) = l23;
    }
    // ---- stage A: w-gather part (cols 64..79 hi, 144..159 lo) ----
    for (int i = tid; i < 64 * 4; i += 128) {
        int r = i >> 2, q = i & 3;
        int e = eb + r;
        float4 v = make_float4(0.f, 0.f, 0.f, 0.f);
        if (e < E) {
            int s = senders[e];
            v = reinterpret_cast<const float4*>(g_w)[(size_t)s * 4 + q];
        }
        unsigned h01, l01, h23, l23;
        split2(v.x, v.y, h01, l01);
        split2(v.z, v.w, h23, l23);
        __half* Ar = sA + r * LDA;
        *reinterpret_cast<unsigned*>(Ar + 64 + q * 4)      = h01;
        *reinterpret_cast<unsigned*>(Ar + 64 + q * 4 + 2)  = h23;
        *reinterpret_cast<unsigned*>(Ar + 144 + q * 4)     = l01;
        *reinterpret_cast<unsigned*>(Ar + 144 + q * 4 + 2) = l23;
    }
    __syncthreads();

    int lane = tid & 31;
    int wid  = tid >> 5;
    int rb   = wid * 16;   // warp's 16 edge-rows

    // ---- A fragments: 10 k-blocks of 16 (0..4 = hi, 5..9 = lo) ----
    unsigned a[10][4];
    {
        const __half* ap = sA + (rb + (lane & 15)) * LDA + (lane >> 4) * 8;
#pragma unroll
        for (int kb = 0; kb < 10; kb++)
            ldsm_x4(a[kb][0], a[kb][1], a[kb][2], a[kb][3], smaddr(ap + kb * 16));
    }

    // ---- layer 1: c1 = xhi*W1hi + xlo*W1hi + xhi*W1lo ----
    float c1[4][4];
#pragma unroll
    for (int nt = 0; nt < 4; nt++)
#pragma unroll
        for (int j = 0; j < 4; j++) c1[nt][j] = 0.f;

    int brow = lane & 15;
#pragma unroll
    for (int nt = 0; nt < 4; nt++) {
#pragma unroll
        for (int k5 = 0; k5 < 5; k5++) {
            unsigned bh0, bh1, bl0, bl1;
            ldsm_x2t(bh0, bh1, smaddr(sW1h + (k5 * 16 + brow) * LDW + nt * 8));
            ldsm_x2t(bl0, bl1, smaddr(sW1l + (k5 * 16 + brow) * LDW + nt * 8));
            mma16816(c1[nt], a[k5][0], a[k5][1], a[k5][2], a[k5][3], bh0, bh1);
            mma16816(c1[nt], a[k5 + 5][0], a[k5 + 5][1], a[k5 + 5][2], a[k5 + 5][3], bh0, bh1);
            mma16816(c1[nt], a[k5][0], a[k5][1], a[k5][2], a[k5][3], bl0, bl1);
        }
    }

    // ---- silu -> hi/lo A-fragments (register-level, FA-style) ----
    unsigned ah[2][4], al[2][4];
#pragma unroll
    for (int p = 0; p < 2; p++) {
        split2(siluf(c1[2 * p][0]),     siluf(c1[2 * p][1]),     ah[p][0], al[p][0]);
        split2(siluf(c1[2 * p][2]),     siluf(c1[2 * p][3]),     ah[p][1], al[p][1]);
        split2(siluf(c1[2 * p + 1][0]), siluf(c1[2 * p + 1][1]), ah[p][2], al[p][2]);
        split2(siluf(c1[2 * p + 1][2]), siluf(c1[2 * p + 1][3]), ah[p][3], al[p][3]);
    }

    // ---- layer 2 ----
    float c2[4][4];
#pragma unroll
    for (int nt = 0; nt < 4; nt++)
#pragma unroll
        for (int j = 0; j < 4; j++) c2[nt][j] = 0.f;
#pragma unroll
    for (int nt = 0; nt < 4; nt++) {
#pragma unroll
        for (int kb = 0; kb < 2; kb++) {
            unsigned bh0, bh1, bl0, bl1;
            ldsm_x2t(bh0, bh1, smaddr(sW2h + (kb * 16 + brow) * LDW + nt * 8));
            ldsm_x2t(bl0, bl1, smaddr(sW2l + (kb * 16 + brow) * LDW + nt * 8));
            mma16816(c2[nt], ah[kb][0], ah[kb][1], ah[kb][2], ah[kb][3], bh0, bh1);
            mma16816(c2[nt], al[kb][0], al[kb][1], al[kb][2], al[kb][3], bh0, bh1);
            mma16816(c2[nt], ah[kb][0], ah[kb][1], ah[kb][2], ah[kb][3], bl0, bl1);
        }
    }
#pragma unroll
    for (int p = 0; p < 2; p++) {
        split2(siluf(c2[2 * p][0]),     siluf(c2[2 * p][1]),     ah[p][0], al[p][0]);
        split2(siluf(c2[2 * p][2]),     siluf(c2[2 * p][3]),     ah[p][1], al[p][1]);
        split2(siluf(c2[2 * p + 1][0]), siluf(c2[2 * p + 1][1]), ah[p][2], al[p][2]);
        split2(siluf(c2[2 * p + 1][2]), siluf(c2[2 * p + 1][3]), ah[p][3], al[p][3]);
    }

    // ---- layer 3 (no activation) ----
    float c3[4][4];
#pragma unroll
    for (int nt = 0; nt < 4; nt++)
#pragma unroll
        for (int j = 0; j < 4; j++) c3[nt][j] = 0.f;
#pragma unroll
    for (int nt = 0; nt < 4; nt++) {
#pragma unroll
        for (int kb = 0; kb < 2; kb++) {
            unsigned bh0, bh1, bl0, bl1;
            ldsm_x2t(bh0, bh1, smaddr(sW3h + (kb * 16 + brow) * LDW + nt * 8));
            ldsm_x2t(bl0, bl1, smaddr(sW3l + (kb * 16 + brow) * LDW + nt * 8));
            mma16816(c3[nt], ah[kb][0], ah[kb][1], ah[kb][2], ah[kb][3], bh0, bh1);
            mma16816(c3[nt], al[kb][0], al[kb][1], al[kb][2], al[kb][3], bh0, bh1);
            mma16816(c3[nt], ah[kb][0], ah[kb][1], ah[kb][2], ah[kb][3], bl0, bl1);
        }
    }

    // ---- envelope + store ----
    int r0 = rb + (lane >> 2);
    int e0 = eb + r0, e1 = e0 + 8;
    float env0 = 0.f, env1 = 0.f;
    if (e0 < E) {
        const float* vp = vectors + (size_t)e0 * 3;
        float u = sqrtf(vp[0] * vp[0] + vp[1] * vp[1] + vp[2] * vp[2]);
        if (u < 1.f) {
            float u2 = u * u, u6 = u2 * u2 * u2;
            env0 = 1.f + u6 * (-28.f + u * (48.f - 21.f * u));
        }
    }
    if (e1 < E) {
        const float* vp = vectors + (size_t)e1 * 3;
        float u = sqrtf(vp[0] * vp[0] + vp[1] * vp[1] + vp[2] * vp[2]);
        if (u < 1.f) {
            float u2 = u * u, u6 = u2 * u2 * u2;
            env1 = 1.f + u6 * (-28.f + u * (48.f - 21.f * u));
        }
    }
    int col0 = (lane & 3) * 2;
#pragma unroll
    for (int nt = 0; nt < 4; nt++) {
        int c = nt * 8 + col0;
        if (e0 < E) {
            float2 v = make_float2(env0 * c3[nt][0], env0 * c3[nt][1]);
            *reinterpret_cast<float2*>(out_x + (size_t)e0 * 32 + c) = v;
        }
        if (e1 < E) {
            float2 v = make_float2(env1 * c3[nt][2], env1 * c3[nt][3]);
            *reinterpret_cast<float2*>(out_x + (size_t)e1 * 32 + c) = v;
        }
    }

    // ---- V copy (CTA-wide, coalesced) ----
    for (int i = tid; i < 64 * 4; i += 128) {
        int e = eb + (i >> 2);
        if (e < E) {
            reinterpret_cast<float4*>(out_V)[(size_t)e * 4 + (i & 3)] =
                reinterpret_cast<const float4*>(V)[(size_t)e * 4 + (i & 3)];
        }
    }
}

// ---------------------------------------------------------------------------
// Launch. Output layout: x_out[E*32] | V[E*16] | charges[N] | pot | vdw
// ---------------------------------------------------------------------------
extern "C" void kernel_launch(void* const* d_in, const int* in_sizes, int n_in,
                              void* d_out, int out_size) {
    const float* vectors = (const float*)d_in[0];
    const float* x       = (const float*)d_in[1];
    const float* V       = (const float*)d_in[2];
    const int*   senders = (const int*)d_in[3];
    const int*   species = (const int*)d_in[4];
    const float* radius  = (const float*)d_in[5];
    const float* hardness= (const float*)d_in[6];
    const float* cembed  = (const float*)d_in[7];
    const float* Wc1 = (const float*)d_in[8];
    const float* Ws1 = (const float*)d_in[10];
    const float* We1 = (const float*)d_in[12];
    const float* Ww1 = (const float*)d_in[14];
    const float* Wx1 = (const float*)d_in[15];
    const float* Wx2 = (const float*)d_in[16];
    const float* Wx3 = (const float*)d_in[17];

    const int E = in_sizes[3];
    const int N = in_sizes[4];

    // constant-bank slices for phase1/nodes
    cudaMemcpyToSymbolAsync(cWc1, Wc1 + 24 * 16, 40 * 16 * 4, 0, cudaMemcpyDeviceToDevice, 0);
    cudaMemcpyToSymbolAsync(cWs1, Ws1 + 24 * 32, 40 * 32 * 4, 0, cudaMemcpyDeviceToDevice, 0);
    cudaMemcpyToSymbolAsync(cWe1, We1 + 24 * 32, 40 * 32 * 4, 0, cudaMemcpyDeviceToDevice, 0);
    cudaMemcpyToSymbolAsync(cWc2, d_in[9],  16 * 4, 0, cudaMemcpyDeviceToDevice, 0);
    cudaMemcpyToSymbolAsync(cWs2, d_in[11], 32 * 4, 0, cudaMemcpyDeviceToDevice, 0);
    cudaMemcpyToSymbolAsync(cWe2, d_in[13], 32 * 4, 0, cudaMemcpyDeviceToDevice, 0);
    cudaMemcpyToSymbolAsync(cWw1, Ww1, 17 * 16 * 4, 0, cudaMemcpyDeviceToDevice, 0);

    float* out = (float*)d_out;
    float* out_x       = out;
    float* out_V       = out + (size_t)E * 32;
    float* out_charges = out + (size_t)E * 48;
    float* out_pv      = out + (size_t)E * 48 + N;

    int nb_n  = (N + 255) / 256;
    int nb_e1 = (E + 255) / 256;
    int nb_e3 = (E + 63) / 64;

    k_zero<<<nb_n, 256>>>(N);
    k_phase1<<<nb_e1, 256>>>(x, senders, Wc1, Ws1, We1, E);
    k_nodes<<<nb_n, 256>>>(species, radius, hardness, cembed, out_charges, N);
    k_phase3<<<nb_e3, 128>>>(x, vectors, V, senders, Wx1, Wx2, Wx3,
                             out_x, out_V, out_pv, E);
}

// round 7
// speedup vs baseline: 1.1980x; 1.1980x over previous
#include <cuda_runtime.h>
#include <cuda_fp16.h>
#include <math.h>

#define MAXN 50000

// scratch (device globals — no allocation allowed)
__device__ float g_chis[MAXN];
__device__ float g_sigA[MAXN];
__device__ float g_epsA[MAXN];
__device__ float g_w[MAXN * 16];
__device__ float g_scal[2];   // pot, vdw

// pre-split phase3 weights: hi region [0,5760), lo region [5760,11520)
// rows 0..79 = W1 (stride 40), 80..111 = W2, 112..143 = W3
__device__ __half gWall[11520];

// ---- constant-bank weight slices for phase1/nodes ----
__constant__ float cWc1[40 * 16];
__constant__ float cWs1[40 * 32];
__constant__ float cWe1[40 * 32];
__constant__ float cWc2[16];
__constant__ float cWs2[32];
__constant__ float cWe2[32];
__constant__ float cWw1[17 * 16];

__device__ __forceinline__ float siluf(float z) {
    return __fdividef(z, 1.0f + __expf(-z));
}
__device__ __forceinline__ float sigmf(float z) {
    return __fdividef(1.0f, 1.0f + __expf(-z));
}

// ---- packed f32x2 helpers (SASS FFMA2) for phase1 ----
__device__ __forceinline__ unsigned long long dup2(float v) {
    unsigned long long r;
    asm("mov.b64 %0, {%1, %1};" : "=l"(r) : "f"(v));
    return r;
}
__device__ __forceinline__ void ffma2(unsigned long long& d,
                                      unsigned long long a,
                                      unsigned long long b) {
    asm("fma.rn.f32x2 %0, %1, %2, %0;" : "+l"(d) : "l"(a), "l"(b));
}
__device__ __forceinline__ float2 unpk(unsigned long long v) {
    float2 f;
    asm("mov.b64 {%0, %1}, %2;" : "=f"(f.x), "=f"(f.y) : "l"(v));
    return f;
}
__device__ __forceinline__ float sel4(float4 v, int sub) {
    return (sub == 0) ? v.x : (sub == 1) ? v.y : (sub == 2) ? v.z : v.w;
}

// ---- MMA helpers (phase3) ----
__device__ __forceinline__ unsigned smaddr(const void* p) {
    unsigned a;
    asm("{ .reg .u64 t; cvta.to.shared.u64 t, %1; cvt.u32.u64 %0, t; }"
        : "=r"(a) : "l"(p));
    return a;
}
__device__ __forceinline__ void ldsm_x4(unsigned& r0, unsigned& r1,
                                        unsigned& r2, unsigned& r3, unsigned addr) {
    asm volatile("ldmatrix.sync.aligned.m8n8.x4.shared.b16 {%0,%1,%2,%3}, [%4];"
                 : "=r"(r0), "=r"(r1), "=r"(r2), "=r"(r3) : "r"(addr));
}
__device__ __forceinline__ void ldsm_x2t(unsigned& r0, unsigned& r1, unsigned addr) {
    asm volatile("ldmatrix.sync.aligned.m8n8.x2.trans.shared.b16 {%0,%1}, [%2];"
                 : "=r"(r0), "=r"(r1) : "r"(addr));
}
__device__ __forceinline__ void mma16816(float* c,
                                         unsigned a0, unsigned a1, unsigned a2, unsigned a3,
                                         unsigned b0, unsigned b1) {
    asm volatile(
        "mma.sync.aligned.m16n8k16.row.col.f32.f16.f16.f32 "
        "{%0,%1,%2,%3}, {%4,%5,%6,%7}, {%8,%9}, {%0,%1,%2,%3};"
        : "+f"(c[0]), "+f"(c[1]), "+f"(c[2]), "+f"(c[3])
        : "r"(a0), "r"(a1), "r"(a2), "r"(a3), "r"(b0), "r"(b1));
}
__device__ __forceinline__ void split2(float a, float b, unsigned& hi, unsigned& lo) {
    __half ha = __float2half_rn(a), hb = __float2half_rn(b);
    float ra = a - __half2float(ha);
    float rb = b - __half2float(hb);
    __half2 H = __halves2half2(ha, hb);
    __half2 L = __floats2half2_rn(ra, rb);
    hi = *reinterpret_cast<unsigned*>(&H);
    lo = *reinterpret_cast<unsigned*>(&L);
}

__global__ void k_zero(int N) {
    int i = blockIdx.x * blockDim.x + threadIdx.x;
    if (i < N) { g_chis[i] = 0.f; g_sigA[i] = 0.f; g_epsA[i] = 0.f; }
    if (i < 2) g_scal[i] = 0.f;
}

// ---------------------------------------------------------------------------
// Prep: split phase3 weights (scale-folded) into fp16 hi/lo, padded layout.
// ---------------------------------------------------------------------------
__global__ void k_prep(const float* __restrict__ Wx1, const float* __restrict__ Wx2,
                       const float* __restrict__ Wx3) {
    int i = blockIdx.x * blockDim.x + threadIdx.x;
    if (i >= 5760) return;
    int row = i / 40, n = i - row * 40;
    const float s80 = 0.11180339887498949f;
    const float s32 = 0.17677669529663689f;
    float v = 0.f;
    if (n < 32) {
        if (row < 80)       v = Wx1[row * 32 + n] * s80;
        else if (row < 112) v = Wx2[(row - 80) * 32 + n] * s32;
        else                v = Wx3[(row - 112) * 32 + n] * s32;
    }
    __half h = __float2half_rn(v);
    gWall[i] = h;
    gWall[5760 + i] = __float2half_rn(v - __half2float(h));
}

// ---------------------------------------------------------------------------
// Phase 1 (unchanged winner from R5): fused chi/sigma/eps MLPs, M=2, dual-port.
// ---------------------------------------------------------------------------
__global__ __launch_bounds__(256) void k_phase1(
    const float* __restrict__ x, const int* __restrict__ senders,
    const float* __restrict__ Wc1, const float* __restrict__ Ws1,
    const float* __restrict__ We1, int E)
{
    __shared__ __align__(16) float sW[24 * 80];
    for (int i = threadIdx.x; i < 24 * 80; i += 256) {
        int k = i / 80, h = i - (i / 80) * 80;
        float v;
        if (h < 16)      v = Wc1[k * 16 + h];
        else if (h < 48) v = Ws1[k * 32 + (h - 16)];
        else             v = We1[k * 32 + (h - 48)];
        sW[i] = v;
    }
    __syncthreads();

    int lane = threadIdx.x & 127;
    int sel  = threadIdx.x >> 7;
    int e0 = blockIdx.x * 256 + lane;
    if (e0 >= E) return;
    int e1 = e0 + 128;
    bool has1 = (e1 < E);

    const float s64 = 0.125f;
    const float s32 = 0.17677669529663689f;

    unsigned long long acc[40];
#pragma unroll
    for (int i = 0; i < 40; i++) acc[i] = 0ull;

    const float4* x0 = reinterpret_cast<const float4*>(x) + (size_t)e0 * 16;
    const float4* x1 = reinterpret_cast<const float4*>(x) + (size_t)(has1 ? e1 : e0) * 16;

#pragma unroll 1
    for (int kc = 0; kc < 6; kc++) {
        float4 a0 = x0[kc], a1 = x1[kc];
#pragma unroll
        for (int sub = 0; sub < 4; sub++) {
            int k = kc * 4 + sub;
            unsigned long long xd0 = dup2(sel4(a0, sub) * s64);
            unsigned long long xd1 = dup2(sel4(a1, sub) * s64);
            const ulonglong2* w =
                reinterpret_cast<const ulonglong2*>(sW + k * 80 + sel * 40);
#pragma unroll
            for (int j = 0; j < 10; j++) {
                ulonglong2 wv = w[j];
                ffma2(acc[2 * j],          xd0, wv.x);
                ffma2(acc[2 * j + 1],      xd0, wv.y);
                ffma2(acc[20 + 2 * j],     xd1, wv.x);
                ffma2(acc[20 + 2 * j + 1], xd1, wv.y);
            }
        }
    }

    if (sel == 0) {
#pragma unroll 1
        for (int kc = 6; kc < 16; kc++) {
            float4 a0 = x0[kc], a1 = x1[kc];
#pragma unroll
            for (int sub = 0; sub < 4; sub++) {
                int kk = kc * 4 + sub - 24;
                unsigned long long xd0 = dup2(sel4(a0, sub) * s64);
                unsigned long long xd1 = dup2(sel4(a1, sub) * s64);
                const ulonglong2* wa =
                    reinterpret_cast<const ulonglong2*>(cWc1 + kk * 16);
                const ulonglong2* wb =
                    reinterpret_cast<const ulonglong2*>(cWs1 + kk * 32);
#pragma unroll
                for (int j = 0; j < 4; j++) {
                    ulonglong2 wv = wa[j];
                    ffma2(acc[2 * j],          xd0, wv.x);
                    ffma2(acc[2 * j + 1],      xd0, wv.y);
                    ffma2(acc[20 + 2 * j],     xd1, wv.x);
                    ffma2(acc[20 + 2 * j + 1], xd1, wv.y);
                }
#pragma unroll
                for (int j = 0; j < 6; j++) {
                    ulonglong2 wv = wb[j];
                    ffma2(acc[8 + 2 * j],      xd0, wv.x);
                    ffma2(acc[9 + 2 * j],      xd0, wv.y);
                    ffma2(acc[28 + 2 * j],     xd1, wv.x);
                    ffma2(acc[29 + 2 * j],     xd1, wv.y);
                }
            }
        }
    } else {
#pragma unroll 1
        for (int kc = 6; kc < 16; kc++) {
            float4 a0 = x0[kc], a1 = x1[kc];
#pragma unroll
            for (int sub = 0; sub < 4; sub++) {
                int kk = kc * 4 + sub - 24;
                unsigned long long xd0 = dup2(sel4(a0, sub) * s64);
                unsigned long long xd1 = dup2(sel4(a1, sub) * s64);
                const ulonglong2* wa =
                    reinterpret_cast<const ulonglong2*>(cWs1 + kk * 32 + 24);
                const ulonglong2* wb =
                    reinterpret_cast<const ulonglong2*>(cWe1 + kk * 32);
#pragma unroll
                for (int j = 0; j < 2; j++) {
                    ulonglong2 wv = wa[j];
                    ffma2(acc[2 * j],          xd0, wv.x);
                    ffma2(acc[2 * j + 1],      xd0, wv.y);
                    ffma2(acc[20 + 2 * j],     xd1, wv.x);
                    ffma2(acc[20 + 2 * j + 1], xd1, wv.y);
                }
#pragma unroll
                for (int j = 0; j < 8; j++) {
                    ulonglong2 wv = wb[j];
                    ffma2(acc[4 + 2 * j],      xd0, wv.x);
                    ffma2(acc[5 + 2 * j],      xd0, wv.y);
                    ffma2(acc[24 + 2 * j],     xd1, wv.x);
                    ffma2(acc[25 + 2 * j],     xd1, wv.y);
                }
            }
        }
    }

    int s0 = senders[e0];
    int s1 = has1 ? senders[e1] : 0;

#pragma unroll
    for (int eidx = 0; eidx < 2; eidx++) {
        if (eidx == 1 && !has1) break;
        int base = eidx * 20;
        float pA = 0.f, pB = 0.f;
        if (sel == 0) {
#pragma unroll
            for (int j = 0; j < 8; j++) {
                float2 f = unpk(acc[base + j]);
                pA += siluf(f.x) * cWc2[2 * j] + siluf(f.y) * cWc2[2 * j + 1];
            }
#pragma unroll
            for (int j = 8; j < 20; j++) {
                float2 f = unpk(acc[base + j]);
                pB += siluf(f.x) * cWs2[2 * (j - 8)] + siluf(f.y) * cWs2[2 * (j - 8) + 1];
            }
            pA *= 0.25f;
            pB *= s32;
            int s = eidx ? s1 : s0;
            atomicAdd(&g_chis[s], pA);
            atomicAdd(&g_sigA[s], pB);
        } else {
#pragma unroll
            for (int j = 0; j < 4; j++) {
                float2 f = unpk(acc[base + j]);
                pA += siluf(f.x) * cWs2[24 + 2 * j] + siluf(f.y) * cWs2[24 + 2 * j + 1];
            }
#pragma unroll
            for (int j = 4; j < 20; j++) {
                float2 f = unpk(acc[base + j]);
                pB += siluf(f.x) * cWe2[2 * (j - 4)] + siluf(f.y) * cWe2[2 * (j - 4) + 1];
            }
            pA *= s32;
            pB *= s32;
            int s = eidx ? s1 : s0;
            atomicAdd(&g_sigA[s], pA);
            atomicAdd(&g_epsA[s], pB);
        }
    }
}

// ---------------------------------------------------------------------------
// Phase 2 (unchanged): per-node charges / pot / vdw / w embedding.
// ---------------------------------------------------------------------------
__global__ __launch_bounds__(256) void k_nodes(
    const int* __restrict__ species, const float* __restrict__ radius,
    const float* __restrict__ hardness, const float* __restrict__ charge_embed,
    float* __restrict__ out_charges, int N)
{
    int n = blockIdx.x * 256 + threadIdx.x;
    float potc = 0.f, vdwc = 0.f;
    if (n < N) {
        int sp = species[n];
        float gamma = fmaf(4.f, radius[sp], 0.5f);
        float hv = hardness[sp];
        float hard = fmaxf(hv, 0.f) + log1pf(__expf(-fabsf(hv)));
        float chis = g_chis[n];
        float q = -chis / hard;
        potc = 0.5f * (hard + 1.f / gamma) * q * q + chis * q;
        float sgv = sigmf(g_sigA[n]) * 0.15f + 0.15f;
        float epv = sigmf(g_epsA[n]) * 1.7f + 0.3f;
        vdwc = sgv * epv;
        out_charges[n] = q;

        const float s17 = 0.24253562503633297f;
        const float* ce = charge_embed + (size_t)sp * 16;
        float wv[16];
        float qs = q * s17;
#pragma unroll
        for (int j = 0; j < 16; j++) wv[j] = qs * cWw1[j];
#pragma unroll
        for (int i = 0; i < 16; i++) {
            float c = ce[i] * s17;
#pragma unroll
            for (int j = 0; j < 16; j++)
                wv[j] = fmaf(c, cWw1[(1 + i) * 16 + j], wv[j]);
        }
        float4* wout = reinterpret_cast<float4*>(g_w) + (size_t)n * 4;
#pragma unroll
        for (int j = 0; j < 4; j++)
            wout[j] = make_float4(wv[4 * j], wv[4 * j + 1], wv[4 * j + 2], wv[4 * j + 3]);
    }
#pragma unroll
    for (int off = 16; off > 0; off >>= 1) {
        potc += __shfl_down_sync(0xffffffffu, potc, off);
        vdwc += __shfl_down_sync(0xffffffffu, vdwc, off);
    }
    if ((threadIdx.x & 31) == 0) {
        atomicAdd(&g_scal[0], potc);
        atomicAdd(&g_scal[1], vdwc);
    }
}

// ---------------------------------------------------------------------------
// Phase 3: tensor-core version, 4 tiles x 64 edges per CTA, pre-split weights.
// ---------------------------------------------------------------------------
#define LDA 168   // A row stride in halfs (160 cols + 8 pad)
#define LDW 40    // W row stride in halfs (32 cols + 8 pad)
#define TILES_PER_CTA 4

__global__ __launch_bounds__(128) void k_phase3(
    const float* __restrict__ x, const float* __restrict__ vectors,
    const float* __restrict__ V, const int* __restrict__ senders,
    float* __restrict__ out_x, float* __restrict__ out_V,
    float* __restrict__ out_pv, int E)
{
    __shared__ __align__(16) __half sA[64 * LDA];
    __shared__ __align__(16) __half sW[11520];

    int tid = threadIdx.x;

    if (blockIdx.x == 0 && tid == 0) {
        out_pv[0] = g_scal[0];
        out_pv[1] = g_scal[1];
    }

    // ---- copy pre-split weights (uint4 vectorized, once per CTA) ----
    {
        const uint4* src = reinterpret_cast<const uint4*>(gWall);
        uint4* dst = reinterpret_cast<uint4*>(sW);
        for (int i = tid; i < 11520 / 8; i += 128) dst[i] = src[i];
    }

    const __half* sW1h = sW;                // rows 0..79,  stride LDW
    const __half* sW2h = sW + 80 * LDW;     // rows 0..31
    const __half* sW3h = sW + 112 * LDW;
    const __half* sW1l = sW + 5760;
    const __half* sW2l = sW + 5760 + 80 * LDW;
    const __half* sW3l = sW + 5760 + 112 * LDW;

    int lane = tid & 31;
    int wid  = tid >> 5;
    int rb   = wid * 16;
    int brow = lane & 15;

#pragma unroll 1
    for (int t = 0; t < TILES_PER_CTA; t++) {
        int eb = (blockIdx.x * TILES_PER_CTA + t) * 64;
        if (eb >= E) break;

        // ---- stage A: x part (cols 0..63 hi, 80..143 lo) ----
        for (int i = tid; i < 64 * 16; i += 128) {
            int r = i >> 4, q = i & 15;
            int e = eb + r;
            float4 v = make_float4(0.f, 0.f, 0.f, 0.f);
            if (e < E) v = reinterpret_cast<const float4*>(x)[(size_t)e * 16 + q];
            unsigned h01, l01, h23, l23;
            split2(v.x, v.y, h01, l01);
            split2(v.z, v.w, h23, l23);
            __half* Ar = sA + r * LDA;
            *reinterpret_cast<unsigned*>(Ar + q * 4)          = h01;
            *reinterpret_cast<unsigned*>(Ar + q * 4 + 2)      = h23;
            *reinterpret_cast<unsigned*>(Ar + 80 + q * 4)     = l01;
            *reinterpret_cast<unsigned*>(Ar + 80 + q * 4 + 2) = l23;
        }
        // ---- stage A: w-gather part (cols 64..79 hi, 144..159 lo) ----
        for (int i = tid; i < 64 * 4; i += 128) {
            int r = i >> 2, q = i & 3;
            int e = eb + r;
            float4 v = make_float4(0.f, 0.f, 0.f, 0.f);
            if (e < E) {
                int s = senders[e];
                v = reinterpret_cast<const float4*>(g_w)[(size_t)s * 4 + q];
            }
            unsigned h01, l01, h23, l23;
            split2(v.x, v.y, h01, l01);
            split2(v.z, v.w, h23, l23);
            __half* Ar = sA + r * LDA;
            *reinterpret_cast<unsigned*>(Ar + 64 + q * 4)      = h01;
            *reinterpret_cast<unsigned*>(Ar + 64 + q * 4 + 2)  = h23;
            *reinterpret_cast<unsigned*>(Ar + 144 + q * 4)     = l01;
            *reinterpret_cast<unsigned*>(Ar + 144 + q * 4 + 2) = l23;
        }
        __syncthreads();

        // ---- A fragments: 10 k-blocks of 16 (0..4 hi, 5..9 lo) ----
        unsigned a[10][4];
        {
            const __half* ap = sA + (rb + (lane & 15)) * LDA + (lane >> 4) * 8;
#pragma unroll
            for (int kb = 0; kb < 10; kb++)
                ldsm_x4(a[kb][0], a[kb][1], a[kb][2], a[kb][3], smaddr(ap + kb * 16));
        }

        // ---- layer 1 ----
        float c1[4][4];
#pragma unroll
        for (int nt = 0; nt < 4; nt++)
#pragma unroll
            for (int j = 0; j < 4; j++) c1[nt][j] = 0.f;
#pragma unroll
        for (int nt = 0; nt < 4; nt++) {
#pragma unroll
            for (int k5 = 0; k5 < 5; k5++) {
                unsigned bh0, bh1, bl0, bl1;
                ldsm_x2t(bh0, bh1, smaddr(sW1h + (k5 * 16 + brow) * LDW + nt * 8));
                ldsm_x2t(bl0, bl1, smaddr(sW1l + (k5 * 16 + brow) * LDW + nt * 8));
                mma16816(c1[nt], a[k5][0], a[k5][1], a[k5][2], a[k5][3], bh0, bh1);
                mma16816(c1[nt], a[k5 + 5][0], a[k5 + 5][1], a[k5 + 5][2], a[k5 + 5][3], bh0, bh1);
                mma16816(c1[nt], a[k5][0], a[k5][1], a[k5][2], a[k5][3], bl0, bl1);
            }
        }

        unsigned ah[2][4], al[2][4];
#pragma unroll
        for (int p = 0; p < 2; p++) {
            split2(siluf(c1[2 * p][0]),     siluf(c1[2 * p][1]),     ah[p][0], al[p][0]);
            split2(siluf(c1[2 * p][2]),     siluf(c1[2 * p][3]),     ah[p][1], al[p][1]);
            split2(siluf(c1[2 * p + 1][0]), siluf(c1[2 * p + 1][1]), ah[p][2], al[p][2]);
            split2(siluf(c1[2 * p + 1][2]), siluf(c1[2 * p + 1][3]), ah[p][3], al[p][3]);
        }

        // ---- layer 2 ----
        float c2[4][4];
#pragma unroll
        for (int nt = 0; nt < 4; nt++)
#pragma unroll
            for (int j = 0; j < 4; j++) c2[nt][j] = 0.f;
#pragma unroll
        for (int nt = 0; nt < 4; nt++) {
#pragma unroll
            for (int kb = 0; kb < 2; kb++) {
                unsigned bh0, bh1, bl0, bl1;
                ldsm_x2t(bh0, bh1, smaddr(sW2h + (kb * 16 + brow) * LDW + nt * 8));
                ldsm_x2t(bl0, bl1, smaddr(sW2l + (kb * 16 + brow) * LDW + nt * 8));
                mma16816(c2[nt], ah[kb][0], ah[kb][1], ah[kb][2], ah[kb][3], bh0, bh1);
                mma16816(c2[nt], al[kb][0], al[kb][1], al[kb][2], al[kb][3], bh0, bh1);
                mma16816(c2[nt], ah[kb][0], ah[kb][1], ah[kb][2], ah[kb][3], bl0, bl1);
            }
        }
#pragma unroll
        for (int p = 0; p < 2; p++) {
            split2(siluf(c2[2 * p][0]),     siluf(c2[2 * p][1]),     ah[p][0], al[p][0]);
            split2(siluf(c2[2 * p][2]),     siluf(c2[2 * p][3]),     ah[p][1], al[p][1]);
            split2(siluf(c2[2 * p + 1][0]), siluf(c2[2 * p + 1][1]), ah[p][2], al[p][2]);
            split2(siluf(c2[2 * p + 1][2]), siluf(c2[2 * p + 1][3]), ah[p][3], al[p][3]);
        }

        // ---- layer 3 (no activation) ----
        float c3[4][4];
#pragma unroll
        for (int nt = 0; nt < 4; nt++)
#pragma unroll
            for (int j = 0; j < 4; j++) c3[nt][j] = 0.f;
#pragma unroll
        for (int nt = 0; nt < 4; nt++) {
#pragma unroll
            for (int kb = 0; kb < 2; kb++) {
                unsigned bh0, bh1, bl0, bl1;
                ldsm_x2t(bh0, bh1, smaddr(sW3h + (kb * 16 + brow) * LDW + nt * 8));
                ldsm_x2t(bl0, bl1, smaddr(sW3l + (kb * 16 + brow) * LDW + nt * 8));
                mma16816(c3[nt], ah[kb][0], ah[kb][1], ah[kb][2], ah[kb][3], bh0, bh1);
                mma16816(c3[nt], al[kb][0], al[kb][1], al[kb][2], al[kb][3], bh0, bh1);
                mma16816(c3[nt], ah[kb][0], ah[kb][1], ah[kb][2], ah[kb][3], bl0, bl1);
            }
        }

        // ---- envelope + store ----
        int r0 = rb + (lane >> 2);
        int e0 = eb + r0, e1 = e0 + 8;
        float env0 = 0.f, env1 = 0.f;
        if (e0 < E) {
            const float* vp = vectors + (size_t)e0 * 3;
            float u = sqrtf(vp[0] * vp[0] + vp[1] * vp[1] + vp[2] * vp[2]);
            if (u < 1.f) {
                float u2 = u * u, u6 = u2 * u2 * u2;
                env0 = 1.f + u6 * (-28.f + u * (48.f - 21.f * u));
            }
        }
        if (e1 < E) {
            const float* vp = vectors + (size_t)e1 * 3;
            float u = sqrtf(vp[0] * vp[0] + vp[1] * vp[1] + vp[2] * vp[2]);
            if (u < 1.f) {
                float u2 = u * u, u6 = u2 * u2 * u2;
                env1 = 1.f + u6 * (-28.f + u * (48.f - 21.f * u));
            }
        }
        int col0 = (lane & 3) * 2;
#pragma unroll
        for (int nt = 0; nt < 4; nt++) {
            int c = nt * 8 + col0;
            if (e0 < E) {
                float2 v = make_float2(env0 * c3[nt][0], env0 * c3[nt][1]);
                *reinterpret_cast<float2*>(out_x + (size_t)e0 * 32 + c) = v;
            }
            if (e1 < E) {
                float2 v = make_float2(env1 * c3[nt][2], env1 * c3[nt][3]);
                *reinterpret_cast<float2*>(out_x + (size_t)e1 * 32 + c) = v;
            }
        }

        // ---- V copy ----
        for (int i = tid; i < 64 * 4; i += 128) {
            int e = eb + (i >> 2);
            if (e < E) {
                reinterpret_cast<float4*>(out_V)[(size_t)e * 4 + (i & 3)] =
                    reinterpret_cast<const float4*>(V)[(size_t)e * 4 + (i & 3)];
            }
        }
        __syncthreads();   // protect sA before next tile overwrites
    }
}

// ---------------------------------------------------------------------------
// Launch. Output layout: x_out[E*32] | V[E*16] | charges[N] | pot | vdw
// ---------------------------------------------------------------------------
extern "C" void kernel_launch(void* const* d_in, const int* in_sizes, int n_in,
                              void* d_out, int out_size) {
    const float* vectors = (const float*)d_in[0];
    const float* x       = (const float*)d_in[1];
    const float* V       = (const float*)d_in[2];
    const int*   senders = (const int*)d_in[3];
    const int*   species = (const int*)d_in[4];
    const float* radius  = (const float*)d_in[5];
    const float* hardness= (const float*)d_in[6];
    const float* cembed  = (const float*)d_in[7];
    const float* Wc1 = (const float*)d_in[8];
    const float* Ws1 = (const float*)d_in[10];
    const float* We1 = (const float*)d_in[12];
    const float* Ww1 = (const float*)d_in[14];
    const float* Wx1 = (const float*)d_in[15];
    const float* Wx2 = (const float*)d_in[16];
    const float* Wx3 = (const float*)d_in[17];

    const int E = in_sizes[3];
    const int N = in_sizes[4];

    cudaMemcpyToSymbolAsync(cWc1, Wc1 + 24 * 16, 40 * 16 * 4, 0, cudaMemcpyDeviceToDevice, 0);
    cudaMemcpyToSymbolAsync(cWs1, Ws1 + 24 * 32, 40 * 32 * 4, 0, cudaMemcpyDeviceToDevice, 0);
    cudaMemcpyToSymbolAsync(cWe1, We1 + 24 * 32, 40 * 32 * 4, 0, cudaMemcpyDeviceToDevice, 0);
    cudaMemcpyToSymbolAsync(cWc2, d_in[9],  16 * 4, 0, cudaMemcpyDeviceToDevice, 0);
    cudaMemcpyToSymbolAsync(cWs2, d_in[11], 32 * 4, 0, cudaMemcpyDeviceToDevice, 0);
    cudaMemcpyToSymbolAsync(cWe2, d_in[13], 32 * 4, 0, cudaMemcpyDeviceToDevice, 0);
    cudaMemcpyToSymbolAsync(cWw1, Ww1, 17 * 16 * 4, 0, cudaMemcpyDeviceToDevice, 0);

    float* out = (float*)d_out;
    float* out_x       = out;
    float* out_V       = out + (size_t)E * 32;
    float* out_charges = out + (size_t)E * 48;
    float* out_pv      = out + (size_t)E * 48 + N;

    int nb_n  = (N + 255) / 256;
    int nb_e1 = (E + 255) / 256;
    int nb_e3 = (E + 64 * TILES_PER_CTA - 1) / (64 * TILES_PER_CTA);

    k_zero<<<nb_n, 256>>>(N);
    k_prep<<<(5760 + 255) / 256, 256>>>(Wx1, Wx2, Wx3);
    k_phase1<<<nb_e1, 256>>>(x, senders, Wc1, Ws1, We1, E);
    k_nodes<<<nb_n, 256>>>(species, radius, hardness, cembed, out_charges, N);
    k_phase3<<<nb_e3, 128>>>(x, vectors, V, senders, out_x, out_V, out_pv, E);
}

// round 8
// speedup vs baseline: 1.6550x; 1.3815x over previous
#include <cuda_runtime.h>
#include <cuda_fp16.h>
#include <math.h>

#define MAXN 50000

// scratch (device globals — no allocation allowed)
__device__ float g_chis[MAXN];
__device__ float g_sigA[MAXN];
__device__ float g_epsA[MAXN];
__device__ float g_w[MAXN * 16];
__device__ float g_scal[2];   // pot, vdw

// pre-split phase3 weights: hi [0,5760), lo [5760,11520)
// rows 0..79 = W1 (stride 40), 80..111 = W2, 112..143 = W3
__device__ __half gWall[11520];
// pre-split phase1 combined W1 [k=64][h=80 pad 88], scaled by 1/sqrt(64):
// hi [0,5632), lo [5632,11264)
__device__ __half gW1all[11264];

// ---- constant weights for epilogues / nodes ----
__constant__ float cWc2[16];
__constant__ float cWs2[32];
__constant__ float cWe2[32];
__constant__ float cWw1[17 * 16];

__device__ __forceinline__ float siluf(float z) {
    return __fdividef(z, 1.0f + __expf(-z));
}
__device__ __forceinline__ float sigmf(float z) {
    return __fdividef(1.0f, 1.0f + __expf(-z));
}

// ---- MMA helpers ----
__device__ __forceinline__ unsigned smaddr(const void* p) {
    unsigned a;
    asm("{ .reg .u64 t; cvta.to.shared.u64 t, %1; cvt.u32.u64 %0, t; }"
        : "=r"(a) : "l"(p));
    return a;
}
__device__ __forceinline__ void ldsm_x4(unsigned& r0, unsigned& r1,
                                        unsigned& r2, unsigned& r3, unsigned addr) {
    asm volatile("ldmatrix.sync.aligned.m8n8.x4.shared.b16 {%0,%1,%2,%3}, [%4];"
                 : "=r"(r0), "=r"(r1), "=r"(r2), "=r"(r3) : "r"(addr));
}
__device__ __forceinline__ void ldsm_x2t(unsigned& r0, unsigned& r1, unsigned addr) {
    asm volatile("ldmatrix.sync.aligned.m8n8.x2.trans.shared.b16 {%0,%1}, [%2];"
                 : "=r"(r0), "=r"(r1) : "r"(addr));
}
__device__ __forceinline__ void mma16816(float* c,
                                         unsigned a0, unsigned a1, unsigned a2, unsigned a3,
                                         unsigned b0, unsigned b1) {
    asm volatile(
        "mma.sync.aligned.m16n8k16.row.col.f32.f16.f16.f32 "
        "{%0,%1,%2,%3}, {%4,%5,%6,%7}, {%8,%9}, {%0,%1,%2,%3};"
        : "+f"(c[0]), "+f"(c[1]), "+f"(c[2]), "+f"(c[3])
        : "r"(a0), "r"(a1), "r"(a2), "r"(a3), "r"(b0), "r"(b1));
}
__device__ __forceinline__ void split2(float a, float b, unsigned& hi, unsigned& lo) {
    __half ha = __float2half_rn(a), hb = __float2half_rn(b);
    float ra = a - __half2float(ha);
    float rb = b - __half2float(hb);
    __half2 H = __halves2half2(ha, hb);
    __half2 L = __floats2half2_rn(ra, rb);
    hi = *reinterpret_cast<unsigned*>(&H);
    lo = *reinterpret_cast<unsigned*>(&L);
}

__global__ void k_zero(int N) {
    int i = blockIdx.x * blockDim.x + threadIdx.x;
    if (i < N) { g_chis[i] = 0.f; g_sigA[i] = 0.f; g_epsA[i] = 0.f; }
    if (i < 2) g_scal[i] = 0.f;
}

// ---------------------------------------------------------------------------
// Prep: split phase3 weights (scale-folded) into fp16 hi/lo, padded layout.
// ---------------------------------------------------------------------------
__global__ void k_prep(const float* __restrict__ Wx1, const float* __restrict__ Wx2,
                       const float* __restrict__ Wx3) {
    int i = blockIdx.x * blockDim.x + threadIdx.x;
    if (i >= 5760) return;
    int row = i / 40, n = i - row * 40;
    const float s80 = 0.11180339887498949f;
    const float s32 = 0.17677669529663689f;
    float v = 0.f;
    if (n < 32) {
        if (row < 80)       v = Wx1[row * 32 + n] * s80;
        else if (row < 112) v = Wx2[(row - 80) * 32 + n] * s32;
        else                v = Wx3[(row - 112) * 32 + n] * s32;
    }
    __half h = __float2half_rn(v);
    gWall[i] = h;
    gWall[5760 + i] = __float2half_rn(v - __half2float(h));
}

// ---------------------------------------------------------------------------
// Prep1: split phase1 combined W1 [64][80 pad 88] * 1/sqrt(64) into hi/lo.
// ---------------------------------------------------------------------------
__global__ void k_prep1(const float* __restrict__ Wc1, const float* __restrict__ Ws1,
                        const float* __restrict__ We1) {
    int i = blockIdx.x * blockDim.x + threadIdx.x;
    if (i >= 5632) return;
    int k = i / 88, h = i - k * 88;
    const float s64 = 0.125f;
    float v = 0.f;
    if (h < 16)      v = Wc1[k * 16 + h] * s64;
    else if (h < 48) v = Ws1[k * 32 + (h - 16)] * s64;
    else if (h < 80) v = We1[k * 32 + (h - 48)] * s64;
    __half hh = __float2half_rn(v);
    gW1all[i] = hh;
    gW1all[5632 + i] = __float2half_rn(v - __half2float(hh));
}

// ---------------------------------------------------------------------------
// Phase 1 (tensor cores): [64 edges/tile x 4 tiles]/CTA.
// C[64,80] = x[64,64] @ W1[64,80] (compensated fp16), then
// chi/sig/eps = sum_h silu(C)*w2 per category, quad-reduced, atomic scatter.
// ---------------------------------------------------------------------------
#define LDA1 136   // 128 (64 hi + 64 lo) + 8 pad
#define LDW1 88    // 80 + 8 pad
#define P1_TILES 4

__global__ __launch_bounds__(128) void k_phase1(
    const float* __restrict__ x, const int* __restrict__ senders, int E)
{
    __shared__ __align__(16) __half sA[64 * LDA1];
    __shared__ __align__(16) __half sW[11264];

    int tid = threadIdx.x;

    // copy pre-split weights once per CTA
    {
        const uint4* src = reinterpret_cast<const uint4*>(gW1all);
        uint4* dst = reinterpret_cast<uint4*>(sW);
        for (int i = tid; i < 11264 / 8; i += 128) dst[i] = src[i];
    }
    const __half* sWh = sW;
    const __half* sWl = sW + 5632;

    int lane = tid & 31;
    int wid  = tid >> 5;
    int rb   = wid * 16;
    int brow = lane & 15;
    const float s32 = 0.17677669529663689f;

#pragma unroll 1
    for (int t = 0; t < P1_TILES; t++) {
        int eb = (blockIdx.x * P1_TILES + t) * 64;
        if (eb >= E) break;

        // ---- stage A: x (cols 0..63 hi, 64..127 lo) ----
        for (int i = tid; i < 64 * 16; i += 128) {
            int r = i >> 4, q = i & 15;
            int e = eb + r;
            float4 v = make_float4(0.f, 0.f, 0.f, 0.f);
            if (e < E) v = reinterpret_cast<const float4*>(x)[(size_t)e * 16 + q];
            unsigned h01, l01, h23, l23;
            split2(v.x, v.y, h01, l01);
            split2(v.z, v.w, h23, l23);
            __half* Ar = sA + r * LDA1;
            *reinterpret_cast<unsigned*>(Ar + q * 4)          = h01;
            *reinterpret_cast<unsigned*>(Ar + q * 4 + 2)      = h23;
            *reinterpret_cast<unsigned*>(Ar + 64 + q * 4)     = l01;
            *reinterpret_cast<unsigned*>(Ar + 64 + q * 4 + 2) = l23;
        }
        __syncthreads();

        // ---- A fragments: 8 k-blocks (0..3 hi, 4..7 lo) ----
        unsigned a[8][4];
        {
            const __half* ap = sA + (rb + (lane & 15)) * LDA1 + (lane >> 4) * 8;
#pragma unroll
            for (int kb = 0; kb < 8; kb++)
                ldsm_x4(a[kb][0], a[kb][1], a[kb][2], a[kb][3], smaddr(ap + kb * 16));
        }

        // ---- C = 3-term compensated MMA over 10 n-tiles ----
        float c[10][4];
#pragma unroll
        for (int nt = 0; nt < 10; nt++)
#pragma unroll
            for (int j = 0; j < 4; j++) c[nt][j] = 0.f;
#pragma unroll
        for (int nt = 0; nt < 10; nt++) {
#pragma unroll
            for (int kb = 0; kb < 4; kb++) {
                unsigned bh0, bh1, bl0, bl1;
                ldsm_x2t(bh0, bh1, smaddr(sWh + (kb * 16 + brow) * LDW1 + nt * 8));
                ldsm_x2t(bl0, bl1, smaddr(sWl + (kb * 16 + brow) * LDW1 + nt * 8));
                mma16816(c[nt], a[kb][0], a[kb][1], a[kb][2], a[kb][3], bh0, bh1);
                mma16816(c[nt], a[kb + 4][0], a[kb + 4][1], a[kb + 4][2], a[kb + 4][3], bh0, bh1);
                mma16816(c[nt], a[kb][0], a[kb][1], a[kb][2], a[kb][3], bl0, bl1);
            }
        }

        // ---- epilogue: silu * w2, category sums (nt 0-1 chi, 2-5 sig, 6-9 eps) ----
        float sc0 = 0.f, sc1 = 0.f, ss0 = 0.f, ss1 = 0.f, se0 = 0.f, se1 = 0.f;
        int col = (lane & 3) * 2;
#pragma unroll
        for (int nt = 0; nt < 10; nt++) {
            float w0, w1;
            if (nt < 2)      { w0 = cWc2[nt * 8 + col] * 0.25f;
                               w1 = cWc2[nt * 8 + col + 1] * 0.25f; }
            else if (nt < 6) { w0 = cWs2[nt * 8 + col - 16] * s32;
                               w1 = cWs2[nt * 8 + col + 1 - 16] * s32; }
            else             { w0 = cWe2[nt * 8 + col - 48] * s32;
                               w1 = cWe2[nt * 8 + col + 1 - 48] * s32; }
            float v0 = siluf(c[nt][0]) * w0 + siluf(c[nt][1]) * w1;  // row r
            float v1 = siluf(c[nt][2]) * w0 + siluf(c[nt][3]) * w1;  // row r+8
            if (nt < 2)      { sc0 += v0; sc1 += v1; }
            else if (nt < 6) { ss0 += v0; ss1 += v1; }
            else             { se0 += v0; se1 += v1; }
        }
        // quad reduce (lanes differing in lane&3 hold different columns)
#pragma unroll
        for (int m = 1; m < 4; m <<= 1) {
            sc0 += __shfl_xor_sync(0xffffffffu, sc0, m);
            sc1 += __shfl_xor_sync(0xffffffffu, sc1, m);
            ss0 += __shfl_xor_sync(0xffffffffu, ss0, m);
            ss1 += __shfl_xor_sync(0xffffffffu, ss1, m);
            se0 += __shfl_xor_sync(0xffffffffu, se0, m);
            se1 += __shfl_xor_sync(0xffffffffu, se1, m);
        }
        if ((lane & 3) == 0) {
            int e0 = eb + rb + (lane >> 2);
            int e1 = e0 + 8;
            if (e0 < E) {
                int s = senders[e0];
                atomicAdd(&g_chis[s], sc0);
                atomicAdd(&g_sigA[s], ss0);
                atomicAdd(&g_epsA[s], se0);
            }
            if (e1 < E) {
                int s = senders[e1];
                atomicAdd(&g_chis[s], sc1);
                atomicAdd(&g_sigA[s], ss1);
                atomicAdd(&g_epsA[s], se1);
            }
        }
        __syncthreads();
    }
}

// ---------------------------------------------------------------------------
// Phase 2 (unchanged): per-node charges / pot / vdw / w embedding.
// ---------------------------------------------------------------------------
__global__ __launch_bounds__(256) void k_nodes(
    const int* __restrict__ species, const float* __restrict__ radius,
    const float* __restrict__ hardness, const float* __restrict__ charge_embed,
    float* __restrict__ out_charges, int N)
{
    int n = blockIdx.x * 256 + threadIdx.x;
    float potc = 0.f, vdwc = 0.f;
    if (n < N) {
        int sp = species[n];
        float gamma = fmaf(4.f, radius[sp], 0.5f);
        float hv = hardness[sp];
        float hard = fmaxf(hv, 0.f) + log1pf(__expf(-fabsf(hv)));
        float chis = g_chis[n];
        float q = -chis / hard;
        potc = 0.5f * (hard + 1.f / gamma) * q * q + chis * q;
        float sgv = sigmf(g_sigA[n]) * 0.15f + 0.15f;
        float epv = sigmf(g_epsA[n]) * 1.7f + 0.3f;
        vdwc = sgv * epv;
        out_charges[n] = q;

        const float s17 = 0.24253562503633297f;
        const float* ce = charge_embed + (size_t)sp * 16;
        float wv[16];
        float qs = q * s17;
#pragma unroll
        for (int j = 0; j < 16; j++) wv[j] = qs * cWw1[j];
#pragma unroll
        for (int i = 0; i < 16; i++) {
            float c = ce[i] * s17;
#pragma unroll
            for (int j = 0; j < 16; j++)
                wv[j] = fmaf(c, cWw1[(1 + i) * 16 + j], wv[j]);
        }
        float4* wout = reinterpret_cast<float4*>(g_w) + (size_t)n * 4;
#pragma unroll
        for (int j = 0; j < 4; j++)
            wout[j] = make_float4(wv[4 * j], wv[4 * j + 1], wv[4 * j + 2], wv[4 * j + 3]);
    }
#pragma unroll
    for (int off = 16; off > 0; off >>= 1) {
        potc += __shfl_down_sync(0xffffffffu, potc, off);
        vdwc += __shfl_down_sync(0xffffffffu, vdwc, off);
    }
    if ((threadIdx.x & 31) == 0) {
        atomicAdd(&g_scal[0], potc);
        atomicAdd(&g_scal[1], vdwc);
    }
}

// ---------------------------------------------------------------------------
// Phase 3 (unchanged from R7): tensor cores, 4 tiles x 64 edges per CTA.
// ---------------------------------------------------------------------------
#define LDA 168
#define LDW 40
#define TILES_PER_CTA 4

__global__ __launch_bounds__(128) void k_phase3(
    const float* __restrict__ x, const float* __restrict__ vectors,
    const float* __restrict__ V, const int* __restrict__ senders,
    float* __restrict__ out_x, float* __restrict__ out_V,
    float* __restrict__ out_pv, int E)
{
    __shared__ __align__(16) __half sA[64 * LDA];
    __shared__ __align__(16) __half sW[11520];

    int tid = threadIdx.x;

    if (blockIdx.x == 0 && tid == 0) {
        out_pv[0] = g_scal[0];
        out_pv[1] = g_scal[1];
    }

    {
        const uint4* src = reinterpret_cast<const uint4*>(gWall);
        uint4* dst = reinterpret_cast<uint4*>(sW);
        for (int i = tid; i < 11520 / 8; i += 128) dst[i] = src[i];
    }

    const __half* sW1h = sW;
    const __half* sW2h = sW + 80 * LDW;
    const __half* sW3h = sW + 112 * LDW;
    const __half* sW1l = sW + 5760;
    const __half* sW2l = sW + 5760 + 80 * LDW;
    const __half* sW3l = sW + 5760 + 112 * LDW;

    int lane = tid & 31;
    int wid  = tid >> 5;
    int rb   = wid * 16;
    int brow = lane & 15;

#pragma unroll 1
    for (int t = 0; t < TILES_PER_CTA; t++) {
        int eb = (blockIdx.x * TILES_PER_CTA + t) * 64;
        if (eb >= E) break;

        for (int i = tid; i < 64 * 16; i += 128) {
            int r = i >> 4, q = i & 15;
            int e = eb + r;
            float4 v = make_float4(0.f, 0.f, 0.f, 0.f);
            if (e < E) v = reinterpret_cast<const float4*>(x)[(size_t)e * 16 + q];
            unsigned h01, l01, h23, l23;
            split2(v.x, v.y, h01, l01);
            split2(v.z, v.w, h23, l23);
            __half* Ar = sA + r * LDA;
            *reinterpret_cast<unsigned*>(Ar + q * 4)          = h01;
            *reinterpret_cast<unsigned*>(Ar + q * 4 + 2)      = h23;
            *reinterpret_cast<unsigned*>(Ar + 80 + q * 4)     = l01;
            *reinterpret_cast<unsigned*>(Ar + 80 + q * 4 + 2) = l23;
        }
        for (int i = tid; i < 64 * 4; i += 128) {
            int r = i >> 2, q = i & 3;
            int e = eb + r;
            float4 v = make_float4(0.f, 0.f, 0.f, 0.f);
            if (e < E) {
                int s = senders[e];
                v = reinterpret_cast<const float4*>(g_w)[(size_t)s * 4 + q];
            }
            unsigned h01, l01, h23, l23;
            split2(v.x, v.y, h01, l01);
            split2(v.z, v.w, h23, l23);
            __half* Ar = sA + r * LDA;
            *reinterpret_cast<unsigned*>(Ar + 64 + q * 4)      = h01;
            *reinterpret_cast<unsigned*>(Ar + 64 + q * 4 + 2)  = h23;
            *reinterpret_cast<unsigned*>(Ar + 144 + q * 4)     = l01;
            *reinterpret_cast<unsigned*>(Ar + 144 + q * 4 + 2) = l23;
        }
        __syncthreads();

        unsigned a[10][4];
        {
            const __half* ap = sA + (rb + (lane & 15)) * LDA + (lane >> 4) * 8;
#pragma unroll
            for (int kb = 0; kb < 10; kb++)
                ldsm_x4(a[kb][0], a[kb][1], a[kb][2], a[kb][3], smaddr(ap + kb * 16));
        }

        float c1[4][4];
#pragma unroll
        for (int nt = 0; nt < 4; nt++)
#pragma unroll
            for (int j = 0; j < 4; j++) c1[nt][j] = 0.f;
#pragma unroll
        for (int nt = 0; nt < 4; nt++) {
#pragma unroll
            for (int k5 = 0; k5 < 5; k5++) {
                unsigned bh0, bh1, bl0, bl1;
                ldsm_x2t(bh0, bh1, smaddr(sW1h + (k5 * 16 + brow) * LDW + nt * 8));
                ldsm_x2t(bl0, bl1, smaddr(sW1l + (k5 * 16 + brow) * LDW + nt * 8));
                mma16816(c1[nt], a[k5][0], a[k5][1], a[k5][2], a[k5][3], bh0, bh1);
                mma16816(c1[nt], a[k5 + 5][0], a[k5 + 5][1], a[k5 + 5][2], a[k5 + 5][3], bh0, bh1);
                mma16816(c1[nt], a[k5][0], a[k5][1], a[k5][2], a[k5][3], bl0, bl1);
            }
        }

        unsigned ah[2][4], al[2][4];
#pragma unroll
        for (int p = 0; p < 2; p++) {
            split2(siluf(c1[2 * p][0]),     siluf(c1[2 * p][1]),     ah[p][0], al[p][0]);
            split2(siluf(c1[2 * p][2]),     siluf(c1[2 * p][3]),     ah[p][1], al[p][1]);
            split2(siluf(c1[2 * p + 1][0]), siluf(c1[2 * p + 1][1]), ah[p][2], al[p][2]);
            split2(siluf(c1[2 * p + 1][2]), siluf(c1[2 * p + 1][3]), ah[p][3], al[p][3]);
        }

        float c2[4][4];
#pragma unroll
        for (int nt = 0; nt < 4; nt++)
#pragma unroll
            for (int j = 0; j < 4; j++) c2[nt][j] = 0.f;
#pragma unroll
        for (int nt = 0; nt < 4; nt++) {
#pragma unroll
            for (int kb = 0; kb < 2; kb++) {
                unsigned bh0, bh1, bl0, bl1;
                ldsm_x2t(bh0, bh1, smaddr(sW2h + (kb * 16 + brow) * LDW + nt * 8));
                ldsm_x2t(bl0, bl1, smaddr(sW2l + (kb * 16 + brow) * LDW + nt * 8));
                mma16816(c2[nt], ah[kb][0], ah[kb][1], ah[kb][2], ah[kb][3], bh0, bh1);
                mma16816(c2[nt], al[kb][0], al[kb][1], al[kb][2], al[kb][3], bh0, bh1);
                mma16816(c2[nt], ah[kb][0], ah[kb][1], ah[kb][2], ah[kb][3], bl0, bl1);
            }
        }
#pragma unroll
        for (int p = 0; p < 2; p++) {
            split2(siluf(c2[2 * p][0]),     siluf(c2[2 * p][1]),     ah[p][0], al[p][0]);
            split2(siluf(c2[2 * p][2]),     siluf(c2[2 * p][3]),     ah[p][1], al[p][1]);
            split2(siluf(c2[2 * p + 1][0]), siluf(c2[2 * p + 1][1]), ah[p][2], al[p][2]);
            split2(siluf(c2[2 * p + 1][2]), siluf(c2[2 * p + 1][3]), ah[p][3], al[p][3]);
        }

        float c3[4][4];
#pragma unroll
        for (int nt = 0; nt < 4; nt++)
#pragma unroll
            for (int j = 0; j < 4; j++) c3[nt][j] = 0.f;
#pragma unroll
        for (int nt = 0; nt < 4; nt++) {
#pragma unroll
            for (int kb = 0; kb < 2; kb++) {
                unsigned bh0, bh1, bl0, bl1;
                ldsm_x2t(bh0, bh1, smaddr(sW3h + (kb * 16 + brow) * LDW + nt * 8));
                ldsm_x2t(bl0, bl1, smaddr(sW3l + (kb * 16 + brow) * LDW + nt * 8));
                mma16816(c3[nt], ah[kb][0], ah[kb][1], ah[kb][2], ah[kb][3], bh0, bh1);
                mma16816(c3[nt], al[kb][0], al[kb][1], al[kb][2], al[kb][3], bh0, bh1);
                mma16816(c3[nt], ah[kb][0], ah[kb][1], ah[kb][2], ah[kb][3], bl0, bl1);
            }
        }

        int r0 = rb + (lane >> 2);
        int e0 = eb + r0, e1 = e0 + 8;
        float env0 = 0.f, env1 = 0.f;
        if (e0 < E) {
            const float* vp = vectors + (size_t)e0 * 3;
            float u = sqrtf(vp[0] * vp[0] + vp[1] * vp[1] + vp[2] * vp[2]);
            if (u < 1.f) {
                float u2 = u * u, u6 = u2 * u2 * u2;
                env0 = 1.f + u6 * (-28.f + u * (48.f - 21.f * u));
            }
        }
        if (e1 < E) {
            const float* vp = vectors + (size_t)e1 * 3;
            float u = sqrtf(vp[0] * vp[0] + vp[1] * vp[1] + vp[2] * vp[2]);
            if (u < 1.f) {
                float u2 = u * u, u6 = u2 * u2 * u2;
                env1 = 1.f + u6 * (-28.f + u * (48.f - 21.f * u));
            }
        }
        int col0 = (lane & 3) * 2;
#pragma unroll
        for (int nt = 0; nt < 4; nt++) {
            int c = nt * 8 + col0;
            if (e0 < E) {
                float2 v = make_float2(env0 * c3[nt][0], env0 * c3[nt][1]);
                *reinterpret_cast<float2*>(out_x + (size_t)e0 * 32 + c) = v;
            }
            if (e1 < E) {
                float2 v = make_float2(env1 * c3[nt][2], env1 * c3[nt][3]);
                *reinterpret_cast<float2*>(out_x + (size_t)e1 * 32 + c) = v;
            }
        }

        for (int i = tid; i < 64 * 4; i += 128) {
            int e = eb + (i >> 2);
            if (e < E) {
                reinterpret_cast<float4*>(out_V)[(size_t)e * 4 + (i & 3)] =
                    reinterpret_cast<const float4*>(V)[(size_t)e * 4 + (i & 3)];
            }
        }
        __syncthreads();
    }
}

// ---------------------------------------------------------------------------
// Launch. Output layout: x_out[E*32] | V[E*16] | charges[N] | pot | vdw
// ---------------------------------------------------------------------------
extern "C" void kernel_launch(void* const* d_in, const int* in_sizes, int n_in,
                              void* d_out, int out_size) {
    const float* vectors = (const float*)d_in[0];
    const float* x       = (const float*)d_in[1];
    const float* V       = (const float*)d_in[2];
    const int*   senders = (const int*)d_in[3];
    const int*   species = (const int*)d_in[4];
    const float* radius  = (const float*)d_in[5];
    const float* hardness= (const float*)d_in[6];
    const float* cembed  = (const float*)d_in[7];
    const float* Wc1 = (const float*)d_in[8];
    const float* Ws1 = (const float*)d_in[10];
    const float* We1 = (const float*)d_in[12];
    const float* Ww1 = (const float*)d_in[14];
    const float* Wx1 = (const float*)d_in[15];
    const float* Wx2 = (const float*)d_in[16];
    const float* Wx3 = (const float*)d_in[17];

    const int E = in_sizes[3];
    const int N = in_sizes[4];

    cudaMemcpyToSymbolAsync(cWc2, d_in[9],  16 * 4, 0, cudaMemcpyDeviceToDevice, 0);
    cudaMemcpyToSymbolAsync(cWs2, d_in[11], 32 * 4, 0, cudaMemcpyDeviceToDevice, 0);
    cudaMemcpyToSymbolAsync(cWe2, d_in[13], 32 * 4, 0, cudaMemcpyDeviceToDevice, 0);
    cudaMemcpyToSymbolAsync(cWw1, Ww1, 17 * 16 * 4, 0, cudaMemcpyDeviceToDevice, 0);

    float* out = (float*)d_out;
    float* out_x       = out;
    float* out_V       = out + (size_t)E * 32;
    float* out_charges = out + (size_t)E * 48;
    float* out_pv      = out + (size_t)E * 48 + N;

    int nb_n  = (N + 255) / 256;
    int nb_e1 = (E + 64 * P1_TILES - 1) / (64 * P1_TILES);
    int nb_e3 = (E + 64 * TILES_PER_CTA - 1) / (64 * TILES_PER_CTA);

    k_zero<<<nb_n, 256>>>(N);
    k_prep<<<(5760 + 255) / 256, 256>>>(Wx1, Wx2, Wx3);
    k_prep1<<<(5632 + 255) / 256, 256>>>(Wc1, Ws1, We1);
    k_phase1<<<nb_e1, 128>>>(x, senders, E);
    k_nodes<<<nb_n, 256>>>(species, radius, hardness, cembed, out_charges, N);
    k_phase3<<<nb_e3, 128>>>(x, vectors, V, senders, out_x, out_V, out_pv, E);
}

// round 9
// speedup vs baseline: 1.7185x; 1.0384x over previous
#include <cuda_runtime.h>
#include <cuda_fp16.h>
#include <math.h>

#define MAXN 50000

// scratch (device globals — no allocation allowed)
__device__ float g_chis[MAXN];
__device__ float g_sigA[MAXN];
__device__ float g_epsA[MAXN];
__device__ float g_w[MAXN * 16];
__device__ float g_scal[2];   // pot, vdw

// pre-split phase3 weights: hi [0,5760), lo [5760,11520)
__device__ __half gWall[11520];
// pre-split phase1 combined W1 [k=64][h=80 pad 88] * 1/sqrt(64): hi/lo
__device__ __half gW1all[11264];

// ---- constant weights for epilogues / nodes ----
__constant__ float cWc2[16];
__constant__ float cWs2[32];
__constant__ float cWe2[32];
__constant__ float cWw1[17 * 16];

__device__ __forceinline__ float siluf(float z) {
    return __fdividef(z, 1.0f + __expf(-z));
}
__device__ __forceinline__ float sigmf(float z) {
    return __fdividef(1.0f, 1.0f + __expf(-z));
}

// ---- MMA helpers ----
__device__ __forceinline__ unsigned smaddr(const void* p) {
    unsigned a;
    asm("{ .reg .u64 t; cvta.to.shared.u64 t, %1; cvt.u32.u64 %0, t; }"
        : "=r"(a) : "l"(p));
    return a;
}
__device__ __forceinline__ void ldsm_x4(unsigned& r0, unsigned& r1,
                                        unsigned& r2, unsigned& r3, unsigned addr) {
    asm volatile("ldmatrix.sync.aligned.m8n8.x4.shared.b16 {%0,%1,%2,%3}, [%4];"
                 : "=r"(r0), "=r"(r1), "=r"(r2), "=r"(r3) : "r"(addr));
}
__device__ __forceinline__ void ldsm_x2t(unsigned& r0, unsigned& r1, unsigned addr) {
    asm volatile("ldmatrix.sync.aligned.m8n8.x2.trans.shared.b16 {%0,%1}, [%2];"
                 : "=r"(r0), "=r"(r1) : "r"(addr));
}
__device__ __forceinline__ void mma16816(float* c,
                                         unsigned a0, unsigned a1, unsigned a2, unsigned a3,
                                         unsigned b0, unsigned b1) {
    asm volatile(
        "mma.sync.aligned.m16n8k16.row.col.f32.f16.f16.f32 "
        "{%0,%1,%2,%3}, {%4,%5,%6,%7}, {%8,%9}, {%0,%1,%2,%3};"
        : "+f"(c[0]), "+f"(c[1]), "+f"(c[2]), "+f"(c[3])
        : "r"(a0), "r"(a1), "r"(a2), "r"(a3), "r"(b0), "r"(b1));
}
__device__ __forceinline__ void split2(float a, float b, unsigned& hi, unsigned& lo) {
    __half ha = __float2half_rn(a), hb = __float2half_rn(b);
    float ra = a - __half2float(ha);
    float rb = b - __half2float(hb);
    __half2 H = __halves2half2(ha, hb);
    __half2 L = __floats2half2_rn(ra, rb);
    hi = *reinterpret_cast<unsigned*>(&H);
    lo = *reinterpret_cast<unsigned*>(&L);
}

__global__ void k_zero(int N) {
    int i = blockIdx.x * blockDim.x + threadIdx.x;
    if (i < N) { g_chis[i] = 0.f; g_sigA[i] = 0.f; g_epsA[i] = 0.f; }
    if (i < 2) g_scal[i] = 0.f;
}

__global__ void k_prep(const float* __restrict__ Wx1, const float* __restrict__ Wx2,
                       const float* __restrict__ Wx3) {
    int i = blockIdx.x * blockDim.x + threadIdx.x;
    if (i >= 5760) return;
    int row = i / 40, n = i - row * 40;
    const float s80 = 0.11180339887498949f;
    const float s32 = 0.17677669529663689f;
    float v = 0.f;
    if (n < 32) {
        if (row < 80)       v = Wx1[row * 32 + n] * s80;
        else if (row < 112) v = Wx2[(row - 80) * 32 + n] * s32;
        else                v = Wx3[(row - 112) * 32 + n] * s32;
    }
    __half h = __float2half_rn(v);
    gWall[i] = h;
    gWall[5760 + i] = __float2half_rn(v - __half2float(h));
}

__global__ void k_prep1(const float* __restrict__ Wc1, const float* __restrict__ Ws1,
                        const float* __restrict__ We1) {
    int i = blockIdx.x * blockDim.x + threadIdx.x;
    if (i >= 5632) return;
    int k = i / 88, h = i - k * 88;
    const float s64 = 0.125f;
    float v = 0.f;
    if (h < 16)      v = Wc1[k * 16 + h] * s64;
    else if (h < 48) v = Ws1[k * 32 + (h - 16)] * s64;
    else if (h < 80) v = We1[k * 32 + (h - 48)] * s64;
    __half hh = __float2half_rn(v);
    gW1all[i] = hh;
    gW1all[5632 + i] = __float2half_rn(v - __half2float(hh));
}

// ---------------------------------------------------------------------------
// Phase 1 (tensor cores): interleaved per-nt epilogue, precomputed w2 regs.
// ---------------------------------------------------------------------------
#define LDA1 136
#define LDW1 88
#define P1_TILES 4

__global__ __launch_bounds__(128, 3) void k_phase1(
    const float* __restrict__ x, const int* __restrict__ senders, int E)
{
    __shared__ __align__(16) __half sA[64 * LDA1];
    __shared__ __align__(16) __half sW[11264];

    int tid = threadIdx.x;
    {
        const uint4* src = reinterpret_cast<const uint4*>(gW1all);
        uint4* dst = reinterpret_cast<uint4*>(sW);
        for (int i = tid; i < 11264 / 8; i += 128) dst[i] = src[i];
    }
    const __half* sWh = sW;
    const __half* sWl = sW + 5632;

    int lane = tid & 31;
    int wid  = tid >> 5;
    int rb   = wid * 16;
    int brow = lane & 15;
    const float s32 = 0.17677669529663689f;

    // per-lane epilogue weights, computed once (nt 0-1 chi, 2-5 sig, 6-9 eps)
    float w0r[10], w1r[10];
    {
        int col = (lane & 3) * 2;
#pragma unroll
        for (int nt = 0; nt < 10; nt++) {
            if (nt < 2) {
                w0r[nt] = cWc2[nt * 8 + col] * 0.25f;
                w1r[nt] = cWc2[nt * 8 + col + 1] * 0.25f;
            } else if (nt < 6) {
                w0r[nt] = cWs2[nt * 8 + col - 16] * s32;
                w1r[nt] = cWs2[nt * 8 + col + 1 - 16] * s32;
            } else {
                w0r[nt] = cWe2[nt * 8 + col - 48] * s32;
                w1r[nt] = cWe2[nt * 8 + col + 1 - 48] * s32;
            }
        }
    }

#pragma unroll 1
    for (int t = 0; t < P1_TILES; t++) {
        int eb = (blockIdx.x * P1_TILES + t) * 64;
        if (eb >= E) break;

        // ---- stage A: x (cols 0..63 hi, 64..127 lo) ----
        for (int i = tid; i < 64 * 16; i += 128) {
            int r = i >> 4, q = i & 15;
            int e = eb + r;
            float4 v = make_float4(0.f, 0.f, 0.f, 0.f);
            if (e < E) v = reinterpret_cast<const float4*>(x)[(size_t)e * 16 + q];
            unsigned h01, l01, h23, l23;
            split2(v.x, v.y, h01, l01);
            split2(v.z, v.w, h23, l23);
            __half* Ar = sA + r * LDA1;
            *reinterpret_cast<unsigned*>(Ar + q * 4)          = h01;
            *reinterpret_cast<unsigned*>(Ar + q * 4 + 2)      = h23;
            *reinterpret_cast<unsigned*>(Ar + 64 + q * 4)     = l01;
            *reinterpret_cast<unsigned*>(Ar + 64 + q * 4 + 2) = l23;
        }
        __syncthreads();

        // ---- A fragments: 8 k-blocks (0..3 hi, 4..7 lo) ----
        unsigned a[8][4];
        {
            const __half* ap = sA + (rb + (lane & 15)) * LDA1 + (lane >> 4) * 8;
#pragma unroll
            for (int kb = 0; kb < 8; kb++)
                ldsm_x4(a[kb][0], a[kb][1], a[kb][2], a[kb][3], smaddr(ap + kb * 16));
        }

        // ---- per-nt: MMA chain then immediate epilogue ----
        float sc0 = 0.f, sc1 = 0.f, ss0 = 0.f, ss1 = 0.f, se0 = 0.f, se1 = 0.f;
#pragma unroll
        for (int nt = 0; nt < 10; nt++) {
            float c[4] = {0.f, 0.f, 0.f, 0.f};
#pragma unroll
            for (int kb = 0; kb < 4; kb++) {
                unsigned bh0, bh1, bl0, bl1;
                ldsm_x2t(bh0, bh1, smaddr(sWh + (kb * 16 + brow) * LDW1 + nt * 8));
                ldsm_x2t(bl0, bl1, smaddr(sWl + (kb * 16 + brow) * LDW1 + nt * 8));
                mma16816(c, a[kb][0], a[kb][1], a[kb][2], a[kb][3], bh0, bh1);
                mma16816(c, a[kb + 4][0], a[kb + 4][1], a[kb + 4][2], a[kb + 4][3], bh0, bh1);
                mma16816(c, a[kb][0], a[kb][1], a[kb][2], a[kb][3], bl0, bl1);
            }
            float v0 = siluf(c[0]) * w0r[nt] + siluf(c[1]) * w1r[nt];
            float v1 = siluf(c[2]) * w0r[nt] + siluf(c[3]) * w1r[nt];
            if (nt < 2)      { sc0 += v0; sc1 += v1; }
            else if (nt < 6) { ss0 += v0; ss1 += v1; }
            else             { se0 += v0; se1 += v1; }
        }

        // quad reduce
#pragma unroll
        for (int m = 1; m < 4; m <<= 1) {
            sc0 += __shfl_xor_sync(0xffffffffu, sc0, m);
            sc1 += __shfl_xor_sync(0xffffffffu, sc1, m);
            ss0 += __shfl_xor_sync(0xffffffffu, ss0, m);
            ss1 += __shfl_xor_sync(0xffffffffu, ss1, m);
            se0 += __shfl_xor_sync(0xffffffffu, se0, m);
            se1 += __shfl_xor_sync(0xffffffffu, se1, m);
        }
        if ((lane & 3) == 0) {
            int e0 = eb + rb + (lane >> 2);
            int e1 = e0 + 8;
            if (e0 < E) {
                int s = senders[e0];
                atomicAdd(&g_chis[s], sc0);
                atomicAdd(&g_sigA[s], ss0);
                atomicAdd(&g_epsA[s], se0);
            }
            if (e1 < E) {
                int s = senders[e1];
                atomicAdd(&g_chis[s], sc1);
                atomicAdd(&g_sigA[s], ss1);
                atomicAdd(&g_epsA[s], se1);
            }
        }
        __syncthreads();
    }
}

// ---------------------------------------------------------------------------
// Phase 2 (unchanged): per-node charges / pot / vdw / w embedding.
// ---------------------------------------------------------------------------
__global__ __launch_bounds__(256) void k_nodes(
    const int* __restrict__ species, const float* __restrict__ radius,
    const float* __restrict__ hardness, const float* __restrict__ charge_embed,
    float* __restrict__ out_charges, int N)
{
    int n = blockIdx.x * 256 + threadIdx.x;
    float potc = 0.f, vdwc = 0.f;
    if (n < N) {
        int sp = species[n];
        float gamma = fmaf(4.f, radius[sp], 0.5f);
        float hv = hardness[sp];
        float hard = fmaxf(hv, 0.f) + log1pf(__expf(-fabsf(hv)));
        float chis = g_chis[n];
        float q = -chis / hard;
        potc = 0.5f * (hard + 1.f / gamma) * q * q + chis * q;
        float sgv = sigmf(g_sigA[n]) * 0.15f + 0.15f;
        float epv = sigmf(g_epsA[n]) * 1.7f + 0.3f;
        vdwc = sgv * epv;
        out_charges[n] = q;

        const float s17 = 0.24253562503633297f;
        const float* ce = charge_embed + (size_t)sp * 16;
        float wv[16];
        float qs = q * s17;
#pragma unroll
        for (int j = 0; j < 16; j++) wv[j] = qs * cWw1[j];
#pragma unroll
        for (int i = 0; i < 16; i++) {
            float c = ce[i] * s17;
#pragma unroll
            for (int j = 0; j < 16; j++)
                wv[j] = fmaf(c, cWw1[(1 + i) * 16 + j], wv[j]);
        }
        float4* wout = reinterpret_cast<float4*>(g_w) + (size_t)n * 4;
#pragma unroll
        for (int j = 0; j < 4; j++)
            wout[j] = make_float4(wv[4 * j], wv[4 * j + 1], wv[4 * j + 2], wv[4 * j + 3]);
    }
#pragma unroll
    for (int off = 16; off > 0; off >>= 1) {
        potc += __shfl_down_sync(0xffffffffu, potc, off);
        vdwc += __shfl_down_sync(0xffffffffu, vdwc, off);
    }
    if ((threadIdx.x & 31) == 0) {
        atomicAdd(&g_scal[0], potc);
        atomicAdd(&g_scal[1], vdwc);
    }
}

// ---------------------------------------------------------------------------
// Phase 3 (unchanged from R7/R8): tensor cores, 4 tiles x 64 edges per CTA.
// ---------------------------------------------------------------------------
#define LDA 168
#define LDW 40
#define TILES_PER_CTA 4

__global__ __launch_bounds__(128) void k_phase3(
    const float* __restrict__ x, const float* __restrict__ vectors,
    const float* __restrict__ V, const int* __restrict__ senders,
    float* __restrict__ out_x, float* __restrict__ out_V,
    float* __restrict__ out_pv, int E)
{
    __shared__ __align__(16) __half sA[64 * LDA];
    __shared__ __align__(16) __half sW[11520];

    int tid = threadIdx.x;

    if (blockIdx.x == 0 && tid == 0) {
        out_pv[0] = g_scal[0];
        out_pv[1] = g_scal[1];
    }

    {
        const uint4* src = reinterpret_cast<const uint4*>(gWall);
        uint4* dst = reinterpret_cast<uint4*>(sW);
        for (int i = tid; i < 11520 / 8; i += 128) dst[i] = src[i];
    }

    const __half* sW1h = sW;
    const __half* sW2h = sW + 80 * LDW;
    const __half* sW3h = sW + 112 * LDW;
    const __half* sW1l = sW + 5760;
    const __half* sW2l = sW + 5760 + 80 * LDW;
    const __half* sW3l = sW + 5760 + 112 * LDW;

    int lane = tid & 31;
    int wid  = tid >> 5;
    int rb   = wid * 16;
    int brow = lane & 15;

#pragma unroll 1
    for (int t = 0; t < TILES_PER_CTA; t++) {
        int eb = (blockIdx.x * TILES_PER_CTA + t) * 64;
        if (eb >= E) break;

        for (int i = tid; i < 64 * 16; i += 128) {
            int r = i >> 4, q = i & 15;
            int e = eb + r;
            float4 v = make_float4(0.f, 0.f, 0.f, 0.f);
            if (e < E) v = reinterpret_cast<const float4*>(x)[(size_t)e * 16 + q];
            unsigned h01, l01, h23, l23;
            split2(v.x, v.y, h01, l01);
            split2(v.z, v.w, h23, l23);
            __half* Ar = sA + r * LDA;
            *reinterpret_cast<unsigned*>(Ar + q * 4)          = h01;
            *reinterpret_cast<unsigned*>(Ar + q * 4 + 2)      = h23;
            *reinterpret_cast<unsigned*>(Ar + 80 + q * 4)     = l01;
            *reinterpret_cast<unsigned*>(Ar + 80 + q * 4 + 2) = l23;
        }
        for (int i = tid; i < 64 * 4; i += 128) {
            int r = i >> 2, q = i & 3;
            int e = eb + r;
            float4 v = make_float4(0.f, 0.f, 0.f, 0.f);
            if (e < E) {
                int s = senders[e];
                v = reinterpret_cast<const float4*>(g_w)[(size_t)s * 4 + q];
            }
            unsigned h01, l01, h23, l23;
            split2(v.x, v.y, h01, l01);
            split2(v.z, v.w, h23, l23);
            __half* Ar = sA + r * LDA;
            *reinterpret_cast<unsigned*>(Ar + 64 + q * 4)      = h01;
            *reinterpret_cast<unsigned*>(Ar + 64 + q * 4 + 2)  = h23;
            *reinterpret_cast<unsigned*>(Ar + 144 + q * 4)     = l01;
            *reinterpret_cast<unsigned*>(Ar + 144 + q * 4 + 2) = l23;
        }
        __syncthreads();

        unsigned a[10][4];
        {
            const __half* ap = sA + (rb + (lane & 15)) * LDA + (lane >> 4) * 8;
#pragma unroll
            for (int kb = 0; kb < 10; kb++)
                ldsm_x4(a[kb][0], a[kb][1], a[kb][2], a[kb][3], smaddr(ap + kb * 16));
        }

        float c1[4][4];
#pragma unroll
        for (int nt = 0; nt < 4; nt++)
#pragma unroll
            for (int j = 0; j < 4; j++) c1[nt][j] = 0.f;
#pragma unroll
        for (int nt = 0; nt < 4; nt++) {
#pragma unroll
            for (int k5 = 0; k5 < 5; k5++) {
                unsigned bh0, bh1, bl0, bl1;
                ldsm_x2t(bh0, bh1, smaddr(sW1h + (k5 * 16 + brow) * LDW + nt * 8));
                ldsm_x2t(bl0, bl1, smaddr(sW1l + (k5 * 16 + brow) * LDW + nt * 8));
                mma16816(c1[nt], a[k5][0], a[k5][1], a[k5][2], a[k5][3], bh0, bh1);
                mma16816(c1[nt], a[k5 + 5][0], a[k5 + 5][1], a[k5 + 5][2], a[k5 + 5][3], bh0, bh1);
                mma16816(c1[nt], a[k5][0], a[k5][1], a[k5][2], a[k5][3], bl0, bl1);
            }
        }

        unsigned ah[2][4], al[2][4];
#pragma unroll
        for (int p = 0; p < 2; p++) {
            split2(siluf(c1[2 * p][0]),     siluf(c1[2 * p][1]),     ah[p][0], al[p][0]);
            split2(siluf(c1[2 * p][2]),     siluf(c1[2 * p][3]),     ah[p][1], al[p][1]);
            split2(siluf(c1[2 * p + 1][0]), siluf(c1[2 * p + 1][1]), ah[p][2], al[p][2]);
            split2(siluf(c1[2 * p + 1][2]), siluf(c1[2 * p + 1][3]), ah[p][3], al[p][3]);
        }

        float c2[4][4];
#pragma unroll
        for (int nt = 0; nt < 4; nt++)
#pragma unroll
            for (int j = 0; j < 4; j++) c2[nt][j] = 0.f;
#pragma unroll
        for (int nt = 0; nt < 4; nt++) {
#pragma unroll
            for (int kb = 0; kb < 2; kb++) {
                unsigned bh0, bh1, bl0, bl1;
                ldsm_x2t(bh0, bh1, smaddr(sW2h + (kb * 16 + brow) * LDW + nt * 8));
                ldsm_x2t(bl0, bl1, smaddr(sW2l + (kb * 16 + brow) * LDW + nt * 8));
                mma16816(c2[nt], ah[kb][0], ah[kb][1], ah[kb][2], ah[kb][3], bh0, bh1);
                mma16816(c2[nt], al[kb][0], al[kb][1], al[kb][2], al[kb][3], bh0, bh1);
                mma16816(c2[nt], ah[kb][0], ah[kb][1], ah[kb][2], ah[kb][3], bl0, bl1);
            }
        }
#pragma unroll
        for (int p = 0; p < 2; p++) {
            split2(siluf(c2[2 * p][0]),     siluf(c2[2 * p][1]),     ah[p][0], al[p][0]);
            split2(siluf(c2[2 * p][2]),     siluf(c2[2 * p][3]),     ah[p][1], al[p][1]);
            split2(siluf(c2[2 * p + 1][0]), siluf(c2[2 * p + 1][1]), ah[p][2], al[p][2]);
            split2(siluf(c2[2 * p + 1][2]), siluf(c2[2 * p + 1][3]), ah[p][3], al[p][3]);
        }

        float c3[4][4];
#pragma unroll
        for (int nt = 0; nt < 4; nt++)
#pragma unroll
            for (int j = 0; j < 4; j++) c3[nt][j] = 0.f;
#pragma unroll
        for (int nt = 0; nt < 4; nt++) {
#pragma unroll
            for (int kb = 0; kb < 2; kb++) {
                unsigned bh0, bh1, bl0, bl1;
                ldsm_x2t(bh0, bh1, smaddr(sW3h + (kb * 16 + brow) * LDW + nt * 8));
                ldsm_x2t(bl0, bl1, smaddr(sW3l + (kb * 16 + brow) * LDW + nt * 8));
                mma16816(c3[nt], ah[kb][0], ah[kb][1], ah[kb][2], ah[kb][3], bh0, bh1);
                mma16816(c3[nt], al[kb][0], al[kb][1], al[kb][2], al[kb][3], bh0, bh1);
                mma16816(c3[nt], ah[kb][0], ah[kb][1], ah[kb][2], ah[kb][3], bl0, bl1);
            }
        }

        int r0 = rb + (lane >> 2);
        int e0 = eb + r0, e1 = e0 + 8;
        float env0 = 0.f, env1 = 0.f;
        if (e0 < E) {
            const float* vp = vectors + (size_t)e0 * 3;
            float u = sqrtf(vp[0] * vp[0] + vp[1] * vp[1] + vp[2] * vp[2]);
            if (u < 1.f) {
                float u2 = u * u, u6 = u2 * u2 * u2;
                env0 = 1.f + u6 * (-28.f + u * (48.f - 21.f * u));
            }
        }
        if (e1 < E) {
            const float* vp = vectors + (size_t)e1 * 3;
            float u = sqrtf(vp[0] * vp[0] + vp[1] * vp[1] + vp[2] * vp[2]);
            if (u < 1.f) {
                float u2 = u * u, u6 = u2 * u2 * u2;
                env1 = 1.f + u6 * (-28.f + u * (48.f - 21.f * u));
            }
        }
        int col0 = (lane & 3) * 2;
#pragma unroll
        for (int nt = 0; nt < 4; nt++) {
            int c = nt * 8 + col0;
            if (e0 < E) {
                float2 v = make_float2(env0 * c3[nt][0], env0 * c3[nt][1]);
                *reinterpret_cast<float2*>(out_x + (size_t)e0 * 32 + c) = v;
            }
            if (e1 < E) {
                float2 v = make_float2(env1 * c3[nt][2], env1 * c3[nt][3]);
                *reinterpret_cast<float2*>(out_x + (size_t)e1 * 32 + c) = v;
            }
        }

        for (int i = tid; i < 64 * 4; i += 128) {
            int e = eb + (i >> 2);
            if (e < E) {
                reinterpret_cast<float4*>(out_V)[(size_t)e * 4 + (i & 3)] =
                    reinterpret_cast<const float4*>(V)[(size_t)e * 4 + (i & 3)];
            }
        }
        __syncthreads();
    }
}

// ---------------------------------------------------------------------------
// Launch. Output layout: x_out[E*32] | V[E*16] | charges[N] | pot | vdw
// ---------------------------------------------------------------------------
extern "C" void kernel_launch(void* const* d_in, const int* in_sizes, int n_in,
                              void* d_out, int out_size) {
    const float* vectors = (const float*)d_in[0];
    const float* x       = (const float*)d_in[1];
    const float* V       = (const float*)d_in[2];
    const int*   senders = (const int*)d_in[3];
    const int*   species = (const int*)d_in[4];
    const float* radius  = (const float*)d_in[5];
    const float* hardness= (const float*)d_in[6];
    const float* cembed  = (const float*)d_in[7];
    const float* Wc1 = (const float*)d_in[8];
    const float* Ws1 = (const float*)d_in[10];
    const float* We1 = (const float*)d_in[12];
    const float* Ww1 = (const float*)d_in[14];
    const float* Wx1 = (const float*)d_in[15];
    const float* Wx2 = (const float*)d_in[16];
    const float* Wx3 = (const float*)d_in[17];

    const int E = in_sizes[3];
    const int N = in_sizes[4];

    cudaMemcpyToSymbolAsync(cWc2, d_in[9],  16 * 4, 0, cudaMemcpyDeviceToDevice, 0);
    cudaMemcpyToSymbolAsync(cWs2, d_in[11], 32 * 4, 0, cudaMemcpyDeviceToDevice, 0);
    cudaMemcpyToSymbolAsync(cWe2, d_in[13], 32 * 4, 0, cudaMemcpyDeviceToDevice, 0);
    cudaMemcpyToSymbolAsync(cWw1, Ww1, 17 * 16 * 4, 0, cudaMemcpyDeviceToDevice, 0);

    float* out = (float*)d_out;
    float* out_x       = out;
    float* out_V       = out + (size_t)E * 32;
    float* out_charges = out + (size_t)E * 48;
    float* out_pv      = out + (size_t)E * 48 + N;

    int nb_n  = (N + 255) / 256;
    int nb_e1 = (E + 64 * P1_TILES - 1) / (64 * P1_TILES);
    int nb_e3 = (E + 64 * TILES_PER_CTA - 1) / (64 * TILES_PER_CTA);

    k_zero<<<nb_n, 256>>>(N);
    k_prep<<<(5760 + 255) / 256, 256>>>(Wx1, Wx2, Wx3);
    k_prep1<<<(5632 + 255) / 256, 256>>>(Wc1, Ws1, We1);
    k_phase1<<<nb_e1, 128>>>(x, senders, E);
    k_nodes<<<nb_n, 256>>>(species, radius, hardness, cembed, out_charges, N);
    k_phase3<<<nb_e3, 128>>>(x, vectors, V, senders, out_x, out_V, out_pv, E);
}

// round 10
// speedup vs baseline: 1.7244x; 1.0034x over previous
#include <cuda_runtime.h>
#include <cuda_fp16.h>
#include <math.h>

#define MAXN 50000

// scratch (device globals — no allocation allowed)
__device__ float g_chis[MAXN];
__device__ float g_sigA[MAXN];
__device__ float g_epsA[MAXN];
__device__ float g_w[MAXN * 16];
__device__ float g_scal[2];   // pot, vdw

// pre-split phase3 weights: hi [0,5760), lo [5760,11520)
__device__ __half gWall[11520];
// pre-split phase1 combined W1 [k=64][h=80 pad 88] * 1/sqrt(64): hi/lo
__device__ __half gW1all[11264];

// ---- constant weights for epilogues / nodes ----
__constant__ float cWc2[16];
__constant__ float cWs2[32];
__constant__ float cWe2[32];
__constant__ float cWw1[17 * 16];

__device__ __forceinline__ float siluf(float z) {
    return __fdividef(z, 1.0f + __expf(-z));
}
__device__ __forceinline__ float sigmf(float z) {
    return __fdividef(1.0f, 1.0f + __expf(-z));
}

// ---- MMA helpers ----
__device__ __forceinline__ unsigned smaddr(const void* p) {
    unsigned a;
    asm("{ .reg .u64 t; cvta.to.shared.u64 t, %1; cvt.u32.u64 %0, t; }"
        : "=r"(a) : "l"(p));
    return a;
}
__device__ __forceinline__ void ldsm_x4(unsigned& r0, unsigned& r1,
                                        unsigned& r2, unsigned& r3, unsigned addr) {
    asm volatile("ldmatrix.sync.aligned.m8n8.x4.shared.b16 {%0,%1,%2,%3}, [%4];"
                 : "=r"(r0), "=r"(r1), "=r"(r2), "=r"(r3) : "r"(addr));
}
__device__ __forceinline__ void ldsm_x2t(unsigned& r0, unsigned& r1, unsigned addr) {
    asm volatile("ldmatrix.sync.aligned.m8n8.x2.trans.shared.b16 {%0,%1}, [%2];"
                 : "=r"(r0), "=r"(r1) : "r"(addr));
}
__device__ __forceinline__ void mma16816(float* c,
                                         unsigned a0, unsigned a1, unsigned a2, unsigned a3,
                                         unsigned b0, unsigned b1) {
    asm volatile(
        "mma.sync.aligned.m16n8k16.row.col.f32.f16.f16.f32 "
        "{%0,%1,%2,%3}, {%4,%5,%6,%7}, {%8,%9}, {%0,%1,%2,%3};"
        : "+f"(c[0]), "+f"(c[1]), "+f"(c[2]), "+f"(c[3])
        : "r"(a0), "r"(a1), "r"(a2), "r"(a3), "r"(b0), "r"(b1));
}
__device__ __forceinline__ void split2(float a, float b, unsigned& hi, unsigned& lo) {
    __half ha = __float2half_rn(a), hb = __float2half_rn(b);
    float ra = a - __half2float(ha);
    float rb = b - __half2float(hb);
    __half2 H = __halves2half2(ha, hb);
    __half2 L = __floats2half2_rn(ra, rb);
    hi = *reinterpret_cast<unsigned*>(&H);
    lo = *reinterpret_cast<unsigned*>(&L);
}

__global__ void k_zero(int N) {
    int i = blockIdx.x * blockDim.x + threadIdx.x;
    if (i < N) { g_chis[i] = 0.f; g_sigA[i] = 0.f; g_epsA[i] = 0.f; }
    if (i < 2) g_scal[i] = 0.f;
}

__global__ void k_prep(const float* __restrict__ Wx1, const float* __restrict__ Wx2,
                       const float* __restrict__ Wx3) {
    int i = blockIdx.x * blockDim.x + threadIdx.x;
    if (i >= 5760) return;
    int row = i / 40, n = i - row * 40;
    const float s80 = 0.11180339887498949f;
    const float s32 = 0.17677669529663689f;
    float v = 0.f;
    if (n < 32) {
        if (row < 80)       v = Wx1[row * 32 + n] * s80;
        else if (row < 112) v = Wx2[(row - 80) * 32 + n] * s32;
        else                v = Wx3[(row - 112) * 32 + n] * s32;
    }
    __half h = __float2half_rn(v);
    gWall[i] = h;
    gWall[5760 + i] = __float2half_rn(v - __half2float(h));
}

__global__ void k_prep1(const float* __restrict__ Wc1, const float* __restrict__ Ws1,
                        const float* __restrict__ We1) {
    int i = blockIdx.x * blockDim.x + threadIdx.x;
    if (i >= 5632) return;
    int k = i / 88, h = i - k * 88;
    const float s64 = 0.125f;
    float v = 0.f;
    if (h < 16)      v = Wc1[k * 16 + h] * s64;
    else if (h < 48) v = Ws1[k * 32 + (h - 16)] * s64;
    else if (h < 80) v = We1[k * 32 + (h - 48)] * s64;
    __half hh = __float2half_rn(v);
    gW1all[i] = hh;
    gW1all[5632 + i] = __float2half_rn(v - __half2float(hh));
}

// ---------------------------------------------------------------------------
// Phase 1 (tensor cores): warp = 32 rows x 5 n-tiles.
// warps 0/1: rows 0-31, nt [0,5)/[5,10); warps 2/3: rows 32-63 same split.
// B-ldsm amortized over 2 row-blocks; 2 independent MMA chains per nt.
// ---------------------------------------------------------------------------
#define LDA1 136
#define LDW1 88
#define P1_TILES 4

__global__ __launch_bounds__(128, 3) void k_phase1(
    const float* __restrict__ x, const int* __restrict__ senders, int E)
{
    __shared__ __align__(16) __half sA[64 * LDA1];
    __shared__ __align__(16) __half sW[11264];

    int tid = threadIdx.x;
    {
        const uint4* src = reinterpret_cast<const uint4*>(gW1all);
        uint4* dst = reinterpret_cast<uint4*>(sW);
        for (int i = tid; i < 11264 / 8; i += 128) dst[i] = src[i];
    }
    const __half* sWh = sW;
    const __half* sWl = sW + 5632;

    int lane  = tid & 31;
    int wid   = tid >> 5;
    int rbase = (wid >> 1) * 32;    // rows 0-31 or 32-63
    int nh    = (wid & 1) * 5;      // nt offset: 0 or 5
    int brow  = lane & 15;
    const float s32 = 0.17677669529663689f;

    // per-lane epilogue weights for this warp's 5 global n-tiles
    // g = nh+nt: g<2 -> chi (catA of nh=0), 2<=g<6 -> sig, g>=6 -> eps
    float w0r[5], w1r[5];
    {
        int col = (lane & 3) * 2;
#pragma unroll
        for (int nt = 0; nt < 5; nt++) {
            int g = nh + nt;
            if (g < 2) {
                w0r[nt] = cWc2[g * 8 + col] * 0.25f;
                w1r[nt] = cWc2[g * 8 + col + 1] * 0.25f;
            } else if (g < 6) {
                w0r[nt] = cWs2[g * 8 + col - 16] * s32;
                w1r[nt] = cWs2[g * 8 + col + 1 - 16] * s32;
            } else {
                w0r[nt] = cWe2[g * 8 + col - 48] * s32;
                w1r[nt] = cWe2[g * 8 + col + 1 - 48] * s32;
            }
        }
    }

#pragma unroll 1
    for (int t = 0; t < P1_TILES; t++) {
        int eb = (blockIdx.x * P1_TILES + t) * 64;
        if (eb >= E) break;

        // ---- stage A: x (cols 0..63 hi, 64..127 lo) ----
        for (int i = tid; i < 64 * 16; i += 128) {
            int r = i >> 4, q = i & 15;
            int e = eb + r;
            float4 v = make_float4(0.f, 0.f, 0.f, 0.f);
            if (e < E) v = reinterpret_cast<const float4*>(x)[(size_t)e * 16 + q];
            unsigned h01, l01, h23, l23;
            split2(v.x, v.y, h01, l01);
            split2(v.z, v.w, h23, l23);
            __half* Ar = sA + r * LDA1;
            *reinterpret_cast<unsigned*>(Ar + q * 4)          = h01;
            *reinterpret_cast<unsigned*>(Ar + q * 4 + 2)      = h23;
            *reinterpret_cast<unsigned*>(Ar + 64 + q * 4)     = l01;
            *reinterpret_cast<unsigned*>(Ar + 64 + q * 4 + 2) = l23;
        }
        __syncthreads();

        // ---- A fragments for BOTH 16-row blocks: [rblk][kb 0..7][4] ----
        unsigned a[2][8][4];
#pragma unroll
        for (int rblk = 0; rblk < 2; rblk++) {
            const __half* ap = sA + (rbase + rblk * 16 + (lane & 15)) * LDA1
                             + (lane >> 4) * 8;
#pragma unroll
            for (int kb = 0; kb < 8; kb++)
                ldsm_x4(a[rblk][kb][0], a[rblk][kb][1],
                        a[rblk][kb][2], a[rblk][kb][3], smaddr(ap + kb * 16));
        }

        // ---- per-nt MMA (2 independent row-block chains) + epilogue ----
        // row slots: 0 -> rbase+(lane>>2), 1 -> +8, 2 -> +16, 3 -> +24
        float sAc[4] = {0.f, 0.f, 0.f, 0.f};   // first category of this warp
        float sBc[4] = {0.f, 0.f, 0.f, 0.f};   // second category
#pragma unroll
        for (int nt = 0; nt < 5; nt++) {
            int g = nh + nt;
            float c0[4] = {0.f, 0.f, 0.f, 0.f};
            float c1[4] = {0.f, 0.f, 0.f, 0.f};
#pragma unroll
            for (int kb = 0; kb < 4; kb++) {
                unsigned bh0, bh1, bl0, bl1;
                ldsm_x2t(bh0, bh1, smaddr(sWh + (kb * 16 + brow) * LDW1 + g * 8));
                ldsm_x2t(bl0, bl1, smaddr(sWl + (kb * 16 + brow) * LDW1 + g * 8));
                mma16816(c0, a[0][kb][0], a[0][kb][1], a[0][kb][2], a[0][kb][3], bh0, bh1);
                mma16816(c1, a[1][kb][0], a[1][kb][1], a[1][kb][2], a[1][kb][3], bh0, bh1);
                mma16816(c0, a[0][kb + 4][0], a[0][kb + 4][1], a[0][kb + 4][2], a[0][kb + 4][3], bh0, bh1);
                mma16816(c1, a[1][kb + 4][0], a[1][kb + 4][1], a[1][kb + 4][2], a[1][kb + 4][3], bh0, bh1);
                mma16816(c0, a[0][kb][0], a[0][kb][1], a[0][kb][2], a[0][kb][3], bl0, bl1);
                mma16816(c1, a[1][kb][0], a[1][kb][1], a[1][kb][2], a[1][kb][3], bl0, bl1);
            }
            float v0 = siluf(c0[0]) * w0r[nt] + siluf(c0[1]) * w1r[nt];
            float v1 = siluf(c0[2]) * w0r[nt] + siluf(c0[3]) * w1r[nt];
            float v2 = siluf(c1[0]) * w0r[nt] + siluf(c1[1]) * w1r[nt];
            float v3 = siluf(c1[2]) * w0r[nt] + siluf(c1[3]) * w1r[nt];
            // category select: for nh=0, catA = chi (g<2), catB = sig (g>=2)
            //                  for nh=5, catA = sig (g<6), catB = eps (g>=6)
            bool isA = (nh == 0) ? (g < 2) : (g < 6);
            if (isA) { sAc[0] += v0; sAc[1] += v1; sAc[2] += v2; sAc[3] += v3; }
            else     { sBc[0] += v0; sBc[1] += v1; sBc[2] += v2; sBc[3] += v3; }
        }

        // quad reduce 8 values
#pragma unroll
        for (int m = 1; m < 4; m <<= 1) {
#pragma unroll
            for (int j = 0; j < 4; j++) {
                sAc[j] += __shfl_xor_sync(0xffffffffu, sAc[j], m);
                sBc[j] += __shfl_xor_sync(0xffffffffu, sBc[j], m);
            }
        }
        if ((lane & 3) == 0) {
            int er = eb + rbase + (lane >> 2);
            float* dstA = (nh == 0) ? g_chis : g_sigA;
            float* dstB = (nh == 0) ? g_sigA : g_epsA;
#pragma unroll
            for (int j = 0; j < 4; j++) {
                int e = er + j * 8;
                if (e < E) {
                    int s = senders[e];
                    atomicAdd(&dstA[s], sAc[j]);
                    atomicAdd(&dstB[s], sBc[j]);
                }
            }
        }
        __syncthreads();
    }
}

// ---------------------------------------------------------------------------
// Phase 2 (unchanged): per-node charges / pot / vdw / w embedding.
// ---------------------------------------------------------------------------
__global__ __launch_bounds__(256) void k_nodes(
    const int* __restrict__ species, const float* __restrict__ radius,
    const float* __restrict__ hardness, const float* __restrict__ charge_embed,
    float* __restrict__ out_charges, int N)
{
    int n = blockIdx.x * 256 + threadIdx.x;
    float potc = 0.f, vdwc = 0.f;
    if (n < N) {
        int sp = species[n];
        float gamma = fmaf(4.f, radius[sp], 0.5f);
        float hv = hardness[sp];
        float hard = fmaxf(hv, 0.f) + log1pf(__expf(-fabsf(hv)));
        float chis = g_chis[n];
        float q = -chis / hard;
        potc = 0.5f * (hard + 1.f / gamma) * q * q + chis * q;
        float sgv = sigmf(g_sigA[n]) * 0.15f + 0.15f;
        float epv = sigmf(g_epsA[n]) * 1.7f + 0.3f;
        vdwc = sgv * epv;
        out_charges[n] = q;

        const float s17 = 0.24253562503633297f;
        const float* ce = charge_embed + (size_t)sp * 16;
        float wv[16];
        float qs = q * s17;
#pragma unroll
        for (int j = 0; j < 16; j++) wv[j] = qs * cWw1[j];
#pragma unroll
        for (int i = 0; i < 16; i++) {
            float c = ce[i] * s17;
#pragma unroll
            for (int j = 0; j < 16; j++)
                wv[j] = fmaf(c, cWw1[(1 + i) * 16 + j], wv[j]);
        }
        float4* wout = reinterpret_cast<float4*>(g_w) + (size_t)n * 4;
#pragma unroll
        for (int j = 0; j < 4; j++)
            wout[j] = make_float4(wv[4 * j], wv[4 * j + 1], wv[4 * j + 2], wv[4 * j + 3]);
    }
#pragma unroll
    for (int off = 16; off > 0; off >>= 1) {
        potc += __shfl_down_sync(0xffffffffu, potc, off);
        vdwc += __shfl_down_sync(0xffffffffu, vdwc, off);
    }
    if ((threadIdx.x & 31) == 0) {
        atomicAdd(&g_scal[0], potc);
        atomicAdd(&g_scal[1], vdwc);
    }
}

// ---------------------------------------------------------------------------
// Phase 3 (unchanged): tensor cores, 4 tiles x 64 edges per CTA.
// ---------------------------------------------------------------------------
#define LDA 168
#define LDW 40
#define TILES_PER_CTA 4

__global__ __launch_bounds__(128) void k_phase3(
    const float* __restrict__ x, const float* __restrict__ vectors,
    const float* __restrict__ V, const int* __restrict__ senders,
    float* __restrict__ out_x, float* __restrict__ out_V,
    float* __restrict__ out_pv, int E)
{
    __shared__ __align__(16) __half sA[64 * LDA];
    __shared__ __align__(16) __half sW[11520];

    int tid = threadIdx.x;

    if (blockIdx.x == 0 && tid == 0) {
        out_pv[0] = g_scal[0];
        out_pv[1] = g_scal[1];
    }

    {
        const uint4* src = reinterpret_cast<const uint4*>(gWall);
        uint4* dst = reinterpret_cast<uint4*>(sW);
        for (int i = tid; i < 11520 / 8; i += 128) dst[i] = src[i];
    }

    const __half* sW1h = sW;
    const __half* sW2h = sW + 80 * LDW;
    const __half* sW3h = sW + 112 * LDW;
    const __half* sW1l = sW + 5760;
    const __half* sW2l = sW + 5760 + 80 * LDW;
    const __half* sW3l = sW + 5760 + 112 * LDW;

    int lane = tid & 31;
    int wid  = tid >> 5;
    int rb   = wid * 16;
    int brow = lane & 15;

#pragma unroll 1
    for (int t = 0; t < TILES_PER_CTA; t++) {
        int eb = (blockIdx.x * TILES_PER_CTA + t) * 64;
        if (eb >= E) break;

        for (int i = tid; i < 64 * 16; i += 128) {
            int r = i >> 4, q = i & 15;
            int e = eb + r;
            float4 v = make_float4(0.f, 0.f, 0.f, 0.f);
            if (e < E) v = reinterpret_cast<const float4*>(x)[(size_t)e * 16 + q];
            unsigned h01, l01, h23, l23;
            split2(v.x, v.y, h01, l01);
            split2(v.z, v.w, h23, l23);
            __half* Ar = sA + r * LDA;
            *reinterpret_cast<unsigned*>(Ar + q * 4)          = h01;
            *reinterpret_cast<unsigned*>(Ar + q * 4 + 2)      = h23;
            *reinterpret_cast<unsigned*>(Ar + 80 + q * 4)     = l01;
            *reinterpret_cast<unsigned*>(Ar + 80 + q * 4 + 2) = l23;
        }
        for (int i = tid; i < 64 * 4; i += 128) {
            int r = i >> 2, q = i & 3;
            int e = eb + r;
            float4 v = make_float4(0.f, 0.f, 0.f, 0.f);
            if (e < E) {
                int s = senders[e];
                v = reinterpret_cast<const float4*>(g_w)[(size_t)s * 4 + q];
            }
            unsigned h01, l01, h23, l23;
            split2(v.x, v.y, h01, l01);
            split2(v.z, v.w, h23, l23);
            __half* Ar = sA + r * LDA;
            *reinterpret_cast<unsigned*>(Ar + 64 + q * 4)      = h01;
            *reinterpret_cast<unsigned*>(Ar + 64 + q * 4 + 2)  = h23;
            *reinterpret_cast<unsigned*>(Ar + 144 + q * 4)     = l01;
            *reinterpret_cast<unsigned*>(Ar + 144 + q * 4 + 2) = l23;
        }
        __syncthreads();

        unsigned a[10][4];
        {
            const __half* ap = sA + (rb + (lane & 15)) * LDA + (lane >> 4) * 8;
#pragma unroll
            for (int kb = 0; kb < 10; kb++)
                ldsm_x4(a[kb][0], a[kb][1], a[kb][2], a[kb][3], smaddr(ap + kb * 16));
        }

        float c1[4][4];
#pragma unroll
        for (int nt = 0; nt < 4; nt++)
#pragma unroll
            for (int j = 0; j < 4; j++) c1[nt][j] = 0.f;
#pragma unroll
        for (int nt = 0; nt < 4; nt++) {
#pragma unroll
            for (int k5 = 0; k5 < 5; k5++) {
                unsigned bh0, bh1, bl0, bl1;
                ldsm_x2t(bh0, bh1, smaddr(sW1h + (k5 * 16 + brow) * LDW + nt * 8));
                ldsm_x2t(bl0, bl1, smaddr(sW1l + (k5 * 16 + brow) * LDW + nt * 8));
                mma16816(c1[nt], a[k5][0], a[k5][1], a[k5][2], a[k5][3], bh0, bh1);
                mma16816(c1[nt], a[k5 + 5][0], a[k5 + 5][1], a[k5 + 5][2], a[k5 + 5][3], bh0, bh1);
                mma16816(c1[nt], a[k5][0], a[k5][1], a[k5][2], a[k5][3], bl0, bl1);
            }
        }

        unsigned ah[2][4], al[2][4];
#pragma unroll
        for (int p = 0; p < 2; p++) {
            split2(siluf(c1[2 * p][0]),     siluf(c1[2 * p][1]),     ah[p][0], al[p][0]);
            split2(siluf(c1[2 * p][2]),     siluf(c1[2 * p][3]),     ah[p][1], al[p][1]);
            split2(siluf(c1[2 * p + 1][0]), siluf(c1[2 * p + 1][1]), ah[p][2], al[p][2]);
            split2(siluf(c1[2 * p + 1][2]), siluf(c1[2 * p + 1][3]), ah[p][3], al[p][3]);
        }

        float c2[4][4];
#pragma unroll
        for (int nt = 0; nt < 4; nt++)
#pragma unroll
            for (int j = 0; j < 4; j++) c2[nt][j] = 0.f;
#pragma unroll
        for (int nt = 0; nt < 4; nt++) {
#pragma unroll
            for (int kb = 0; kb < 2; kb++) {
                unsigned bh0, bh1, bl0, bl1;
                ldsm_x2t(bh0, bh1, smaddr(sW2h + (kb * 16 + brow) * LDW + nt * 8));
                ldsm_x2t(bl0, bl1, smaddr(sW2l + (kb * 16 + brow) * LDW + nt * 8));
                mma16816(c2[nt], ah[kb][0], ah[kb][1], ah[kb][2], ah[kb][3], bh0, bh1);
                mma16816(c2[nt], al[kb][0], al[kb][1], al[kb][2], al[kb][3], bh0, bh1);
                mma16816(c2[nt], ah[kb][0], ah[kb][1], ah[kb][2], ah[kb][3], bl0, bl1);
            }
        }
#pragma unroll
        for (int p = 0; p < 2; p++) {
            split2(siluf(c2[2 * p][0]),     siluf(c2[2 * p][1]),     ah[p][0], al[p][0]);
            split2(siluf(c2[2 * p][2]),     siluf(c2[2 * p][3]),     ah[p][1], al[p][1]);
            split2(siluf(c2[2 * p + 1][0]), siluf(c2[2 * p + 1][1]), ah[p][2], al[p][2]);
            split2(siluf(c2[2 * p + 1][2]), siluf(c2[2 * p + 1][3]), ah[p][3], al[p][3]);
        }

        float c3[4][4];
#pragma unroll
        for (int nt = 0; nt < 4; nt++)
#pragma unroll
            for (int j = 0; j < 4; j++) c3[nt][j] = 0.f;
#pragma unroll
        for (int nt = 0; nt < 4; nt++) {
#pragma unroll
            for (int kb = 0; kb < 2; kb++) {
                unsigned bh0, bh1, bl0, bl1;
                ldsm_x2t(bh0, bh1, smaddr(sW3h + (kb * 16 + brow) * LDW + nt * 8));
                ldsm_x2t(bl0, bl1, smaddr(sW3l + (kb * 16 + brow) * LDW + nt * 8));
                mma16816(c3[nt], ah[kb][0], ah[kb][1], ah[kb][2], ah[kb][3], bh0, bh1);
                mma16816(c3[nt], al[kb][0], al[kb][1], al[kb][2], al[kb][3], bh0, bh1);
                mma16816(c3[nt], ah[kb][0], ah[kb][1], ah[kb][2], ah[kb][3], bl0, bl1);
            }
        }

        int r0 = rb + (lane >> 2);
        int e0 = eb + r0, e1 = e0 + 8;
        float env0 = 0.f, env1 = 0.f;
        if (e0 < E) {
            const float* vp = vectors + (size_t)e0 * 3;
            float u = sqrtf(vp[0] * vp[0] + vp[1] * vp[1] + vp[2] * vp[2]);
            if (u < 1.f) {
                float u2 = u * u, u6 = u2 * u2 * u2;
                env0 = 1.f + u6 * (-28.f + u * (48.f - 21.f * u));
            }
        }
        if (e1 < E) {
            const float* vp = vectors + (size_t)e1 * 3;
            float u = sqrtf(vp[0] * vp[0] + vp[1] * vp[1] + vp[2] * vp[2]);
            if (u < 1.f) {
                float u2 = u * u, u6 = u2 * u2 * u2;
                env1 = 1.f + u6 * (-28.f + u * (48.f - 21.f * u));
            }
        }
        int col0 = (lane & 3) * 2;
#pragma unroll
        for (int nt = 0; nt < 4; nt++) {
            int c = nt * 8 + col0;
            if (e0 < E) {
                float2 v = make_float2(env0 * c3[nt][0], env0 * c3[nt][1]);
                *reinterpret_cast<float2*>(out_x + (size_t)e0 * 32 + c) = v;
            }
            if (e1 < E) {
                float2 v = make_float2(env1 * c3[nt][2], env1 * c3[nt][3]);
                *reinterpret_cast<float2*>(out_x + (size_t)e1 * 32 + c) = v;
            }
        }

        for (int i = tid; i < 64 * 4; i += 128) {
            int e = eb + (i >> 2);
            if (e < E) {
                reinterpret_cast<float4*>(out_V)[(size_t)e * 4 + (i & 3)] =
                    reinterpret_cast<const float4*>(V)[(size_t)e * 4 + (i & 3)];
            }
        }
        __syncthreads();
    }
}

// ---------------------------------------------------------------------------
// Launch. Output layout: x_out[E*32] | V[E*16] | charges[N] | pot | vdw
// ---------------------------------------------------------------------------
extern "C" void kernel_launch(void* const* d_in, const int* in_sizes, int n_in,
                              void* d_out, int out_size) {
    const float* vectors = (const float*)d_in[0];
    const float* x       = (const float*)d_in[1];
    const float* V       = (const float*)d_in[2];
    const int*   senders = (const int*)d_in[3];
    const int*   species = (const int*)d_in[4];
    const float* radius  = (const float*)d_in[5];
    const float* hardness= (const float*)d_in[6];
    const float* cembed  = (const float*)d_in[7];
    const float* Wc1 = (const float*)d_in[8];
    const float* Ws1 = (const float*)d_in[10];
    const float* We1 = (const float*)d_in[12];
    const float* Ww1 = (const float*)d_in[14];
    const float* Wx1 = (const float*)d_in[15];
    const float* Wx2 = (const float*)d_in[16];
    const float* Wx3 = (const float*)d_in[17];

    const int E = in_sizes[3];
    const int N = in_sizes[4];

    cudaMemcpyToSymbolAsync(cWc2, d_in[9],  16 * 4, 0, cudaMemcpyDeviceToDevice, 0);
    cudaMemcpyToSymbolAsync(cWs2, d_in[11], 32 * 4, 0, cudaMemcpyDeviceToDevice, 0);
    cudaMemcpyToSymbolAsync(cWe2, d_in[13], 32 * 4, 0, cudaMemcpyDeviceToDevice, 0);
    cudaMemcpyToSymbolAsync(cWw1, Ww1, 17 * 16 * 4, 0, cudaMemcpyDeviceToDevice, 0);

    float* out = (float*)d_out;
    float* out_x       = out;
    float* out_V       = out + (size_t)E * 32;
    float* out_charges = out + (size_t)E * 48;
    float* out_pv      = out + (size_t)E * 48 + N;

    int nb_n  = (N + 255) / 256;
    int nb_e1 = (E + 64 * P1_TILES - 1) / (64 * P1_TILES);
    int nb_e3 = (E + 64 * TILES_PER_CTA - 1) / (64 * TILES_PER_CTA);

    k_zero<<<nb_n, 256>>>(N);
    k_prep<<<(5760 + 255) / 256, 256>>>(Wx1, Wx2, Wx3);
    k_prep1<<<(5632 + 255) / 256, 256>>>(Wc1, Ws1, We1);
    k_phase1<<<nb_e1, 128>>>(x, senders, E);
    k_nodes<<<nb_n, 256>>>(species, radius, hardness, cembed, out_charges, N);
    k_phase3<<<nb_e3, 128>>>(x, vectors, V, senders, out_x, out_V, out_pv, E);
}

// round 11
// speedup vs baseline: 1.8177x; 1.0541x over previous
#include <cuda_runtime.h>
#include <cuda_fp16.h>
#include <math.h>

#define MAXN 50000

// scratch (device globals — no allocation allowed)
__device__ float g_chis[MAXN];
__device__ float g_sigA[MAXN];
__device__ float g_epsA[MAXN];
__device__ float g_w[MAXN * 16];
__device__ float g_scal[2];   // pot, vdw

// pre-split phase3 weights: hi [0,5760), lo [5760,11520)
__device__ __half gWall[11520];
// pre-split phase1 combined W1 [k=64][h=80 pad 88] * 1/sqrt(64): hi/lo
__device__ __half gW1all[11264];

// ---- constant weights for epilogues / nodes ----
__constant__ float cWc2[16];
__constant__ float cWs2[32];
__constant__ float cWe2[32];
__constant__ float cWw1[17 * 16];

__device__ __forceinline__ float siluf(float z) {
    return __fdividef(z, 1.0f + __expf(-z));
}
__device__ __forceinline__ float sigmf(float z) {
    return __fdividef(1.0f, 1.0f + __expf(-z));
}

// ---- MMA helpers ----
__device__ __forceinline__ unsigned smaddr(const void* p) {
    unsigned a;
    asm("{ .reg .u64 t; cvta.to.shared.u64 t, %1; cvt.u32.u64 %0, t; }"
        : "=r"(a) : "l"(p));
    return a;
}
__device__ __forceinline__ void ldsm_x4(unsigned& r0, unsigned& r1,
                                        unsigned& r2, unsigned& r3, unsigned addr) {
    asm volatile("ldmatrix.sync.aligned.m8n8.x4.shared.b16 {%0,%1,%2,%3}, [%4];"
                 : "=r"(r0), "=r"(r1), "=r"(r2), "=r"(r3) : "r"(addr));
}
__device__ __forceinline__ void ldsm_x2t(unsigned& r0, unsigned& r1, unsigned addr) {
    asm volatile("ldmatrix.sync.aligned.m8n8.x2.trans.shared.b16 {%0,%1}, [%2];"
                 : "=r"(r0), "=r"(r1) : "r"(addr));
}
__device__ __forceinline__ void mma16816(float* c,
                                         unsigned a0, unsigned a1, unsigned a2, unsigned a3,
                                         unsigned b0, unsigned b1) {
    asm volatile(
        "mma.sync.aligned.m16n8k16.row.col.f32.f16.f16.f32 "
        "{%0,%1,%2,%3}, {%4,%5,%6,%7}, {%8,%9}, {%0,%1,%2,%3};"
        : "+f"(c[0]), "+f"(c[1]), "+f"(c[2]), "+f"(c[3])
        : "r"(a0), "r"(a1), "r"(a2), "r"(a3), "r"(b0), "r"(b1));
}
__device__ __forceinline__ void split2(float a, float b, unsigned& hi, unsigned& lo) {
    __half ha = __float2half_rn(a), hb = __float2half_rn(b);
    float ra = a - __half2float(ha);
    float rb = b - __half2float(hb);
    __half2 H = __halves2half2(ha, hb);
    __half2 L = __floats2half2_rn(ra, rb);
    hi = *reinterpret_cast<unsigned*>(&H);
    lo = *reinterpret_cast<unsigned*>(&L);
}

__global__ void k_zero(int N) {
    int i = blockIdx.x * blockDim.x + threadIdx.x;
    if (i < N) { g_chis[i] = 0.f; g_sigA[i] = 0.f; g_epsA[i] = 0.f; }
    if (i < 2) g_scal[i] = 0.f;
}

__global__ void k_prep(const float* __restrict__ Wx1, const float* __restrict__ Wx2,
                       const float* __restrict__ Wx3) {
    int i = blockIdx.x * blockDim.x + threadIdx.x;
    if (i >= 5760) return;
    int row = i / 40, n = i - row * 40;
    const float s80 = 0.11180339887498949f;
    const float s32 = 0.17677669529663689f;
    float v = 0.f;
    if (n < 32) {
        if (row < 80)       v = Wx1[row * 32 + n] * s80;
        else if (row < 112) v = Wx2[(row - 80) * 32 + n] * s32;
        else                v = Wx3[(row - 112) * 32 + n] * s32;
    }
    __half h = __float2half_rn(v);
    gWall[i] = h;
    gWall[5760 + i] = __float2half_rn(v - __half2float(h));
}

__global__ void k_prep1(const float* __restrict__ Wc1, const float* __restrict__ Ws1,
                        const float* __restrict__ We1) {
    int i = blockIdx.x * blockDim.x + threadIdx.x;
    if (i >= 5632) return;
    int k = i / 88, h = i - k * 88;
    const float s64 = 0.125f;
    float v = 0.f;
    if (h < 16)      v = Wc1[k * 16 + h] * s64;
    else if (h < 48) v = Ws1[k * 32 + (h - 16)] * s64;
    else if (h < 80) v = We1[k * 32 + (h - 48)] * s64;
    __half hh = __float2half_rn(v);
    gW1all[i] = hh;
    gW1all[5632 + i] = __float2half_rn(v - __half2float(hh));
}

// ---------------------------------------------------------------------------
// Phase 1 (tensor cores): R9 structure (warp = 16 rows x 10 nt, interleaved
// per-nt epilogue) with a hard 4-CTA/SM occupancy cap.
// ---------------------------------------------------------------------------
#define LDA1 136
#define LDW1 88
#define P1_TILES 4

__global__ __launch_bounds__(128, 4) void k_phase1(
    const float* __restrict__ x, const int* __restrict__ senders, int E)
{
    __shared__ __align__(16) __half sA[64 * LDA1];
    __shared__ __align__(16) __half sW[11264];

    int tid = threadIdx.x;
    {
        const uint4* src = reinterpret_cast<const uint4*>(gW1all);
        uint4* dst = reinterpret_cast<uint4*>(sW);
        for (int i = tid; i < 11264 / 8; i += 128) dst[i] = src[i];
    }
    const __half* sWh = sW;
    const __half* sWl = sW + 5632;

    int lane = tid & 31;
    int wid  = tid >> 5;
    int rb   = wid * 16;
    int brow = lane & 15;
    const float s32 = 0.17677669529663689f;

    // per-lane epilogue weights (nt 0-1 chi, 2-5 sig, 6-9 eps)
    float w0r[10], w1r[10];
    {
        int col = (lane & 3) * 2;
#pragma unroll
        for (int nt = 0; nt < 10; nt++) {
            if (nt < 2) {
                w0r[nt] = cWc2[nt * 8 + col] * 0.25f;
                w1r[nt] = cWc2[nt * 8 + col + 1] * 0.25f;
            } else if (nt < 6) {
                w0r[nt] = cWs2[nt * 8 + col - 16] * s32;
                w1r[nt] = cWs2[nt * 8 + col + 1 - 16] * s32;
            } else {
                w0r[nt] = cWe2[nt * 8 + col - 48] * s32;
                w1r[nt] = cWe2[nt * 8 + col + 1 - 48] * s32;
            }
        }
    }

#pragma unroll 1
    for (int t = 0; t < P1_TILES; t++) {
        int eb = (blockIdx.x * P1_TILES + t) * 64;
        if (eb >= E) break;

        // ---- stage A: x (cols 0..63 hi, 64..127 lo) ----
        for (int i = tid; i < 64 * 16; i += 128) {
            int r = i >> 4, q = i & 15;
            int e = eb + r;
            float4 v = make_float4(0.f, 0.f, 0.f, 0.f);
            if (e < E) v = reinterpret_cast<const float4*>(x)[(size_t)e * 16 + q];
            unsigned h01, l01, h23, l23;
            split2(v.x, v.y, h01, l01);
            split2(v.z, v.w, h23, l23);
            __half* Ar = sA + r * LDA1;
            *reinterpret_cast<unsigned*>(Ar + q * 4)          = h01;
            *reinterpret_cast<unsigned*>(Ar + q * 4 + 2)      = h23;
            *reinterpret_cast<unsigned*>(Ar + 64 + q * 4)     = l01;
            *reinterpret_cast<unsigned*>(Ar + 64 + q * 4 + 2) = l23;
        }
        __syncthreads();

        // ---- A fragments: 8 k-blocks (0..3 hi, 4..7 lo) ----
        unsigned a[8][4];
        {
            const __half* ap = sA + (rb + (lane & 15)) * LDA1 + (lane >> 4) * 8;
#pragma unroll
            for (int kb = 0; kb < 8; kb++)
                ldsm_x4(a[kb][0], a[kb][1], a[kb][2], a[kb][3], smaddr(ap + kb * 16));
        }

        // ---- per-nt: MMA chain then immediate epilogue ----
        float sc0 = 0.f, sc1 = 0.f, ss0 = 0.f, ss1 = 0.f, se0 = 0.f, se1 = 0.f;
#pragma unroll
        for (int nt = 0; nt < 10; nt++) {
            float c[4] = {0.f, 0.f, 0.f, 0.f};
#pragma unroll
            for (int kb = 0; kb < 4; kb++) {
                unsigned bh0, bh1, bl0, bl1;
                ldsm_x2t(bh0, bh1, smaddr(sWh + (kb * 16 + brow) * LDW1 + nt * 8));
                ldsm_x2t(bl0, bl1, smaddr(sWl + (kb * 16 + brow) * LDW1 + nt * 8));
                mma16816(c, a[kb][0], a[kb][1], a[kb][2], a[kb][3], bh0, bh1);
                mma16816(c, a[kb + 4][0], a[kb + 4][1], a[kb + 4][2], a[kb + 4][3], bh0, bh1);
                mma16816(c, a[kb][0], a[kb][1], a[kb][2], a[kb][3], bl0, bl1);
            }
            float v0 = siluf(c[0]) * w0r[nt] + siluf(c[1]) * w1r[nt];
            float v1 = siluf(c[2]) * w0r[nt] + siluf(c[3]) * w1r[nt];
            if (nt < 2)      { sc0 += v0; sc1 += v1; }
            else if (nt < 6) { ss0 += v0; ss1 += v1; }
            else             { se0 += v0; se1 += v1; }
        }

        // quad reduce
#pragma unroll
        for (int m = 1; m < 4; m <<= 1) {
            sc0 += __shfl_xor_sync(0xffffffffu, sc0, m);
            sc1 += __shfl_xor_sync(0xffffffffu, sc1, m);
            ss0 += __shfl_xor_sync(0xffffffffu, ss0, m);
            ss1 += __shfl_xor_sync(0xffffffffu, ss1, m);
            se0 += __shfl_xor_sync(0xffffffffu, se0, m);
            se1 += __shfl_xor_sync(0xffffffffu, se1, m);
        }
        if ((lane & 3) == 0) {
            int e0 = eb + rb + (lane >> 2);
            int e1 = e0 + 8;
            if (e0 < E) {
                int s = senders[e0];
                atomicAdd(&g_chis[s], sc0);
                atomicAdd(&g_sigA[s], ss0);
                atomicAdd(&g_epsA[s], se0);
            }
            if (e1 < E) {
                int s = senders[e1];
                atomicAdd(&g_chis[s], sc1);
                atomicAdd(&g_sigA[s], ss1);
                atomicAdd(&g_epsA[s], se1);
            }
        }
        __syncthreads();
    }
}

// ---------------------------------------------------------------------------
// Phase 2 (unchanged): per-node charges / pot / vdw / w embedding.
// ---------------------------------------------------------------------------
__global__ __launch_bounds__(256) void k_nodes(
    const int* __restrict__ species, const float* __restrict__ radius,
    const float* __restrict__ hardness, const float* __restrict__ charge_embed,
    float* __restrict__ out_charges, int N)
{
    int n = blockIdx.x * 256 + threadIdx.x;
    float potc = 0.f, vdwc = 0.f;
    if (n < N) {
        int sp = species[n];
        float gamma = fmaf(4.f, radius[sp], 0.5f);
        float hv = hardness[sp];
        float hard = fmaxf(hv, 0.f) + log1pf(__expf(-fabsf(hv)));
        float chis = g_chis[n];
        float q = -chis / hard;
        potc = 0.5f * (hard + 1.f / gamma) * q * q + chis * q;
        float sgv = sigmf(g_sigA[n]) * 0.15f + 0.15f;
        float epv = sigmf(g_epsA[n]) * 1.7f + 0.3f;
        vdwc = sgv * epv;
        out_charges[n] = q;

        const float s17 = 0.24253562503633297f;
        const float* ce = charge_embed + (size_t)sp * 16;
        float wv[16];
        float qs = q * s17;
#pragma unroll
        for (int j = 0; j < 16; j++) wv[j] = qs * cWw1[j];
#pragma unroll
        for (int i = 0; i < 16; i++) {
            float c = ce[i] * s17;
#pragma unroll
            for (int j = 0; j < 16; j++)
                wv[j] = fmaf(c, cWw1[(1 + i) * 16 + j], wv[j]);
        }
        float4* wout = reinterpret_cast<float4*>(g_w) + (size_t)n * 4;
#pragma unroll
        for (int j = 0; j < 4; j++)
            wout[j] = make_float4(wv[4 * j], wv[4 * j + 1], wv[4 * j + 2], wv[4 * j + 3]);
    }
#pragma unroll
    for (int off = 16; off > 0; off >>= 1) {
        potc += __shfl_down_sync(0xffffffffu, potc, off);
        vdwc += __shfl_down_sync(0xffffffffu, vdwc, off);
    }
    if ((threadIdx.x & 31) == 0) {
        atomicAdd(&g_scal[0], potc);
        atomicAdd(&g_scal[1], vdwc);
    }
}

// ---------------------------------------------------------------------------
// Phase 3: tensor cores, 4 tiles x 64 edges per CTA, 4-CTA/SM cap.
// ---------------------------------------------------------------------------
#define LDA 168
#define LDW 40
#define TILES_PER_CTA 4

__global__ __launch_bounds__(128, 4) void k_phase3(
    const float* __restrict__ x, const float* __restrict__ vectors,
    const float* __restrict__ V, const int* __restrict__ senders,
    float* __restrict__ out_x, float* __restrict__ out_V,
    float* __restrict__ out_pv, int E)
{
    __shared__ __align__(16) __half sA[64 * LDA];
    __shared__ __align__(16) __half sW[11520];

    int tid = threadIdx.x;

    if (blockIdx.x == 0 && tid == 0) {
        out_pv[0] = g_scal[0];
        out_pv[1] = g_scal[1];
    }

    {
        const uint4* src = reinterpret_cast<const uint4*>(gWall);
        uint4* dst = reinterpret_cast<uint4*>(sW);
        for (int i = tid; i < 11520 / 8; i += 128) dst[i] = src[i];
    }

    const __half* sW1h = sW;
    const __half* sW2h = sW + 80 * LDW;
    const __half* sW3h = sW + 112 * LDW;
    const __half* sW1l = sW + 5760;
    const __half* sW2l = sW + 5760 + 80 * LDW;
    const __half* sW3l = sW + 5760 + 112 * LDW;

    int lane = tid & 31;
    int wid  = tid >> 5;
    int rb   = wid * 16;
    int brow = lane & 15;

#pragma unroll 1
    for (int t = 0; t < TILES_PER_CTA; t++) {
        int eb = (blockIdx.x * TILES_PER_CTA + t) * 64;
        if (eb >= E) break;

        for (int i = tid; i < 64 * 16; i += 128) {
            int r = i >> 4, q = i & 15;
            int e = eb + r;
            float4 v = make_float4(0.f, 0.f, 0.f, 0.f);
            if (e < E) v = reinterpret_cast<const float4*>(x)[(size_t)e * 16 + q];
            unsigned h01, l01, h23, l23;
            split2(v.x, v.y, h01, l01);
            split2(v.z, v.w, h23, l23);
            __half* Ar = sA + r * LDA;
            *reinterpret_cast<unsigned*>(Ar + q * 4)          = h01;
            *reinterpret_cast<unsigned*>(Ar + q * 4 + 2)      = h23;
            *reinterpret_cast<unsigned*>(Ar + 80 + q * 4)     = l01;
            *reinterpret_cast<unsigned*>(Ar + 80 + q * 4 + 2) = l23;
        }
        for (int i = tid; i < 64 * 4; i += 128) {
            int r = i >> 2, q = i & 3;
            int e = eb + r;
            float4 v = make_float4(0.f, 0.f, 0.f, 0.f);
            if (e < E) {
                int s = senders[e];
                v = reinterpret_cast<const float4*>(g_w)[(size_t)s * 4 + q];
            }
            unsigned h01, l01, h23, l23;
            split2(v.x, v.y, h01, l01);
            split2(v.z, v.w, h23, l23);
            __half* Ar = sA + r * LDA;
            *reinterpret_cast<unsigned*>(Ar + 64 + q * 4)      = h01;
            *reinterpret_cast<unsigned*>(Ar + 64 + q * 4 + 2)  = h23;
            *reinterpret_cast<unsigned*>(Ar + 144 + q * 4)     = l01;
            *reinterpret_cast<unsigned*>(Ar + 144 + q * 4 + 2) = l23;
        }
        __syncthreads();

        unsigned a[10][4];
        {
            const __half* ap = sA + (rb + (lane & 15)) * LDA + (lane >> 4) * 8;
#pragma unroll
            for (int kb = 0; kb < 10; kb++)
                ldsm_x4(a[kb][0], a[kb][1], a[kb][2], a[kb][3], smaddr(ap + kb * 16));
        }

        float c1[4][4];
#pragma unroll
        for (int nt = 0; nt < 4; nt++)
#pragma unroll
            for (int j = 0; j < 4; j++) c1[nt][j] = 0.f;
#pragma unroll
        for (int nt = 0; nt < 4; nt++) {
#pragma unroll
            for (int k5 = 0; k5 < 5; k5++) {
                unsigned bh0, bh1, bl0, bl1;
                ldsm_x2t(bh0, bh1, smaddr(sW1h + (k5 * 16 + brow) * LDW + nt * 8));
                ldsm_x2t(bl0, bl1, smaddr(sW1l + (k5 * 16 + brow) * LDW + nt * 8));
                mma16816(c1[nt], a[k5][0], a[k5][1], a[k5][2], a[k5][3], bh0, bh1);
                mma16816(c1[nt], a[k5 + 5][0], a[k5 + 5][1], a[k5 + 5][2], a[k5 + 5][3], bh0, bh1);
                mma16816(c1[nt], a[k5][0], a[k5][1], a[k5][2], a[k5][3], bl0, bl1);
            }
        }

        unsigned ah[2][4], al[2][4];
#pragma unroll
        for (int p = 0; p < 2; p++) {
            split2(siluf(c1[2 * p][0]),     siluf(c1[2 * p][1]),     ah[p][0], al[p][0]);
            split2(siluf(c1[2 * p][2]),     siluf(c1[2 * p][3]),     ah[p][1], al[p][1]);
            split2(siluf(c1[2 * p + 1][0]), siluf(c1[2 * p + 1][1]), ah[p][2], al[p][2]);
            split2(siluf(c1[2 * p + 1][2]), siluf(c1[2 * p + 1][3]), ah[p][3], al[p][3]);
        }

        float c2[4][4];
#pragma unroll
        for (int nt = 0; nt < 4; nt++)
#pragma unroll
            for (int j = 0; j < 4; j++) c2[nt][j] = 0.f;
#pragma unroll
        for (int nt = 0; nt < 4; nt++) {
#pragma unroll
            for (int kb = 0; kb < 2; kb++) {
                unsigned bh0, bh1, bl0, bl1;
                ldsm_x2t(bh0, bh1, smaddr(sW2h + (kb * 16 + brow) * LDW + nt * 8));
                ldsm_x2t(bl0, bl1, smaddr(sW2l + (kb * 16 + brow) * LDW + nt * 8));
                mma16816(c2[nt], ah[kb][0], ah[kb][1], ah[kb][2], ah[kb][3], bh0, bh1);
                mma16816(c2[nt], al[kb][0], al[kb][1], al[kb][2], al[kb][3], bh0, bh1);
                mma16816(c2[nt], ah[kb][0], ah[kb][1], ah[kb][2], ah[kb][3], bl0, bl1);
            }
        }
#pragma unroll
        for (int p = 0; p < 2; p++) {
            split2(siluf(c2[2 * p][0]),     siluf(c2[2 * p][1]),     ah[p][0], al[p][0]);
            split2(siluf(c2[2 * p][2]),     siluf(c2[2 * p][3]),     ah[p][1], al[p][1]);
            split2(siluf(c2[2 * p + 1][0]), siluf(c2[2 * p + 1][1]), ah[p][2], al[p][2]);
            split2(siluf(c2[2 * p + 1][2]), siluf(c2[2 * p + 1][3]), ah[p][3], al[p][3]);
        }

        float c3[4][4];
#pragma unroll
        for (int nt = 0; nt < 4; nt++)
#pragma unroll
            for (int j = 0; j < 4; j++) c3[nt][j] = 0.f;
#pragma unroll
        for (int nt = 0; nt < 4; nt++) {
#pragma unroll
            for (int kb = 0; kb < 2; kb++) {
                unsigned bh0, bh1, bl0, bl1;
                ldsm_x2t(bh0, bh1, smaddr(sW3h + (kb * 16 + brow) * LDW + nt * 8));
                ldsm_x2t(bl0, bl1, smaddr(sW3l + (kb * 16 + brow) * LDW + nt * 8));
                mma16816(c3[nt], ah[kb][0], ah[kb][1], ah[kb][2], ah[kb][3], bh0, bh1);
                mma16816(c3[nt], al[kb][0], al[kb][1], al[kb][2], al[kb][3], bh0, bh1);
                mma16816(c3[nt], ah[kb][0], ah[kb][1], ah[kb][2], ah[kb][3], bl0, bl1);
            }
        }

        int r0 = rb + (lane >> 2);
        int e0 = eb + r0, e1 = e0 + 8;
        float env0 = 0.f, env1 = 0.f;
        if (e0 < E) {
            const float* vp = vectors + (size_t)e0 * 3;
            float u = sqrtf(vp[0] * vp[0] + vp[1] * vp[1] + vp[2] * vp[2]);
            if (u < 1.f) {
                float u2 = u * u, u6 = u2 * u2 * u2;
                env0 = 1.f + u6 * (-28.f + u * (48.f - 21.f * u));
            }
        }
        if (e1 < E) {
            const float* vp = vectors + (size_t)e1 * 3;
            float u = sqrtf(vp[0] * vp[0] + vp[1] * vp[1] + vp[2] * vp[2]);
            if (u < 1.f) {
                float u2 = u * u, u6 = u2 * u2 * u2;
                env1 = 1.f + u6 * (-28.f + u * (48.f - 21.f * u));
            }
        }
        int col0 = (lane & 3) * 2;
#pragma unroll
        for (int nt = 0; nt < 4; nt++) {
            int c = nt * 8 + col0;
            if (e0 < E) {
                float2 v = make_float2(env0 * c3[nt][0], env0 * c3[nt][1]);
                *reinterpret_cast<float2*>(out_x + (size_t)e0 * 32 + c) = v;
            }
            if (e1 < E) {
                float2 v = make_float2(env1 * c3[nt][2], env1 * c3[nt][3]);
                *reinterpret_cast<float2*>(out_x + (size_t)e1 * 32 + c) = v;
            }
        }

        for (int i = tid; i < 64 * 4; i += 128) {
            int e = eb + (i >> 2);
            if (e < E) {
                reinterpret_cast<float4*>(out_V)[(size_t)e * 4 + (i & 3)] =
                    reinterpret_cast<const float4*>(V)[(size_t)e * 4 + (i & 3)];
            }
        }
        __syncthreads();
    }
}

// ---------------------------------------------------------------------------
// Launch. Output layout: x_out[E*32] | V[E*16] | charges[N] | pot | vdw
// ---------------------------------------------------------------------------
extern "C" void kernel_launch(void* const* d_in, const int* in_sizes, int n_in,
                              void* d_out, int out_size) {
    const float* vectors = (const float*)d_in[0];
    const float* x       = (const float*)d_in[1];
    const float* V       = (const float*)d_in[2];
    const int*   senders = (const int*)d_in[3];
    const int*   species = (const int*)d_in[4];
    const float* radius  = (const float*)d_in[5];
    const float* hardness= (const float*)d_in[6];
    const float* cembed  = (const float*)d_in[7];
    const float* Wc1 = (const float*)d_in[8];
    const float* Ws1 = (const float*)d_in[10];
    const float* We1 = (const float*)d_in[12];
    const float* Ww1 = (const float*)d_in[14];
    const float* Wx1 = (const float*)d_in[15];
    const float* Wx2 = (const float*)d_in[16];
    const float* Wx3 = (const float*)d_in[17];

    const int E = in_sizes[3];
    const int N = in_sizes[4];

    cudaMemcpyToSymbolAsync(cWc2, d_in[9],  16 * 4, 0, cudaMemcpyDeviceToDevice, 0);
    cudaMemcpyToSymbolAsync(cWs2, d_in[11], 32 * 4, 0, cudaMemcpyDeviceToDevice, 0);
    cudaMemcpyToSymbolAsync(cWe2, d_in[13], 32 * 4, 0, cudaMemcpyDeviceToDevice, 0);
    cudaMemcpyToSymbolAsync(cWw1, Ww1, 17 * 16 * 4, 0, cudaMemcpyDeviceToDevice, 0);

    float* out = (float*)d_out;
    float* out_x       = out;
    float* out_V       = out + (size_t)E * 32;
    float* out_charges = out + (size_t)E * 48;
    float* out_pv      = out + (size_t)E * 48 + N;

    int nb_n  = (N + 255) / 256;
    int nb_e1 = (E + 64 * P1_TILES - 1) / (64 * P1_TILES);
    int nb_e3 = (E + 64 * TILES_PER_CTA - 1) / (64 * TILES_PER_CTA);

    k_zero<<<nb_n, 256>>>(N);
    k_prep<<<(5760 + 255) / 256, 256>>>(Wx1, Wx2, Wx3);
    k_prep1<<<(5632 + 255) / 256, 256>>>(Wc1, Ws1, We1);
    k_phase1<<<nb_e1, 128>>>(x, senders, E);
    k_nodes<<<nb_n, 256>>>(species, radius, hardness, cembed, out_charges, N);
    k_phase3<<<nb_e3, 128>>>(x, vectors, V, senders, out_x, out_V, out_pv, E);
}

// round 12
// speedup vs baseline: 2.0193x; 1.1109x over previous
#include <cuda_runtime.h>
#include <cuda_fp16.h>
#include <math.h>

#define MAXN 50000

// scratch (device globals — no allocation allowed)
__device__ float g_chis[MAXN];
__device__ float g_sigA[MAXN];
__device__ float g_epsA[MAXN];
__device__ float g_w[MAXN * 16];
__device__ float g_scal[2];   // pot, vdw

// pre-split phase3 weights: hi [0,5760), lo [5760,11520)
__device__ __half gWall[11520];
// pre-split phase1 combined W1 [k=64][h=80 pad 88] * 1/sqrt(64): hi/lo
__device__ __half gW1all[11264];

// ---- constant weights for epilogues / nodes ----
__constant__ float cWc2[16];
__constant__ float cWs2[32];
__constant__ float cWe2[32];
__constant__ float cWw1[17 * 16];

__device__ __forceinline__ float siluf(float z) {
    return __fdividef(z, 1.0f + __expf(-z));
}
__device__ __forceinline__ float sigmf(float z) {
    return __fdividef(1.0f, 1.0f + __expf(-z));
}

// ---- MMA helpers ----
__device__ __forceinline__ unsigned smaddr(const void* p) {
    unsigned a;
    asm("{ .reg .u64 t; cvta.to.shared.u64 t, %1; cvt.u32.u64 %0, t; }"
        : "=r"(a) : "l"(p));
    return a;
}
__device__ __forceinline__ void ldsm_x4(unsigned& r0, unsigned& r1,
                                        unsigned& r2, unsigned& r3, unsigned addr) {
    asm volatile("ldmatrix.sync.aligned.m8n8.x4.shared.b16 {%0,%1,%2,%3}, [%4];"
                 : "=r"(r0), "=r"(r1), "=r"(r2), "=r"(r3) : "r"(addr));
}
__device__ __forceinline__ void ldsm_x2t(unsigned& r0, unsigned& r1, unsigned addr) {
    asm volatile("ldmatrix.sync.aligned.m8n8.x2.trans.shared.b16 {%0,%1}, [%2];"
                 : "=r"(r0), "=r"(r1) : "r"(addr));
}
__device__ __forceinline__ void mma16816(float* c,
                                         unsigned a0, unsigned a1, unsigned a2, unsigned a3,
                                         unsigned b0, unsigned b1) {
    asm volatile(
        "mma.sync.aligned.m16n8k16.row.col.f32.f16.f16.f32 "
        "{%0,%1,%2,%3}, {%4,%5,%6,%7}, {%8,%9}, {%0,%1,%2,%3};"
        : "+f"(c[0]), "+f"(c[1]), "+f"(c[2]), "+f"(c[3])
        : "r"(a0), "r"(a1), "r"(a2), "r"(a3), "r"(b0), "r"(b1));
}
__device__ __forceinline__ void split2(float a, float b, unsigned& hi, unsigned& lo) {
    __half ha = __float2half_rn(a), hb = __float2half_rn(b);
    float ra = a - __half2float(ha);
    float rb = b - __half2float(hb);
    __half2 H = __halves2half2(ha, hb);
    __half2 L = __floats2half2_rn(ra, rb);
    hi = *reinterpret_cast<unsigned*>(&H);
    lo = *reinterpret_cast<unsigned*>(&L);
}

// ---------------------------------------------------------------------------
// Init: zero node accumulators + split both phase-weight banks (one launch).
// ---------------------------------------------------------------------------
__global__ void k_init(const float* __restrict__ Wx1, const float* __restrict__ Wx2,
                       const float* __restrict__ Wx3, const float* __restrict__ Wc1,
                       const float* __restrict__ Ws1, const float* __restrict__ We1,
                       int N) {
    int i = blockIdx.x * blockDim.x + threadIdx.x;
    if (i < N) { g_chis[i] = 0.f; g_sigA[i] = 0.f; g_epsA[i] = 0.f; }
    if (i < 2) g_scal[i] = 0.f;

    const float s80 = 0.11180339887498949f;
    const float s32 = 0.17677669529663689f;
    const float s64 = 0.125f;

    if (i < 5760) {
        int row = i / 40, n = i - row * 40;
        float v = 0.f;
        if (n < 32) {
            if (row < 80)       v = Wx1[row * 32 + n] * s80;
            else if (row < 112) v = Wx2[(row - 80) * 32 + n] * s32;
            else                v = Wx3[(row - 112) * 32 + n] * s32;
        }
        __half h = __float2half_rn(v);
        gWall[i] = h;
        gWall[5760 + i] = __float2half_rn(v - __half2float(h));
    }
    if (i < 5632) {
        int k = i / 88, h = i - k * 88;
        float v = 0.f;
        if (h < 16)      v = Wc1[k * 16 + h] * s64;
        else if (h < 48) v = Ws1[k * 32 + (h - 16)] * s64;
        else if (h < 80) v = We1[k * 32 + (h - 48)] * s64;
        __half hh = __float2half_rn(v);
        gW1all[i] = hh;
        gW1all[5632 + i] = __float2half_rn(v - __half2float(hh));
    }
}

// ---------------------------------------------------------------------------
// Phase 1 (tensor cores): warp = 16 rows x 10 nt, interleaved per-nt epilogue.
// Epilogue w2 table in smem (saves 20 regs); 5 CTAs/SM target.
// ---------------------------------------------------------------------------
#define LDA1 136
#define LDW1 88
#define P1_TILES 8

__global__ __launch_bounds__(128, 5) void k_phase1(
    const float* __restrict__ x, const int* __restrict__ senders, int E)
{
    __shared__ __align__(16) __half sA[64 * LDA1];
    __shared__ __align__(16) __half sW[11264];
    __shared__ float sw2s[80];

    int tid = threadIdx.x;
    {
        const uint4* src = reinterpret_cast<const uint4*>(gW1all);
        uint4* dst = reinterpret_cast<uint4*>(sW);
        for (int i = tid; i < 11264 / 8; i += 128) dst[i] = src[i];
    }
    if (tid < 80) {
        const float s32c = 0.17677669529663689f;
        float v;
        if (tid < 16)      v = cWc2[tid] * 0.25f;
        else if (tid < 48) v = cWs2[tid - 16] * s32c;
        else               v = cWe2[tid - 48] * s32c;
        sw2s[tid] = v;
    }
    const __half* sWh = sW;
    const __half* sWl = sW + 5632;

    int lane = tid & 31;
    int wid  = tid >> 5;
    int rb   = wid * 16;
    int brow = lane & 15;
    int col  = (lane & 3) * 2;

#pragma unroll 1
    for (int t = 0; t < P1_TILES; t++) {
        int eb = (blockIdx.x * P1_TILES + t) * 64;
        if (eb >= E) break;

        // ---- stage A: x (cols 0..63 hi, 64..127 lo) ----
        for (int i = tid; i < 64 * 16; i += 128) {
            int r = i >> 4, q = i & 15;
            int e = eb + r;
            float4 v = make_float4(0.f, 0.f, 0.f, 0.f);
            if (e < E) v = reinterpret_cast<const float4*>(x)[(size_t)e * 16 + q];
            unsigned h01, l01, h23, l23;
            split2(v.x, v.y, h01, l01);
            split2(v.z, v.w, h23, l23);
            __half* Ar = sA + r * LDA1;
            *reinterpret_cast<unsigned*>(Ar + q * 4)          = h01;
            *reinterpret_cast<unsigned*>(Ar + q * 4 + 2)      = h23;
            *reinterpret_cast<unsigned*>(Ar + 64 + q * 4)     = l01;
            *reinterpret_cast<unsigned*>(Ar + 64 + q * 4 + 2) = l23;
        }
        __syncthreads();

        // ---- A fragments: 8 k-blocks (0..3 hi, 4..7 lo) ----
        unsigned a[8][4];
        {
            const __half* ap = sA + (rb + (lane & 15)) * LDA1 + (lane >> 4) * 8;
#pragma unroll
            for (int kb = 0; kb < 8; kb++)
                ldsm_x4(a[kb][0], a[kb][1], a[kb][2], a[kb][3], smaddr(ap + kb * 16));
        }

        // ---- per-nt: MMA chain then immediate epilogue ----
        float sc0 = 0.f, sc1 = 0.f, ss0 = 0.f, ss1 = 0.f, se0 = 0.f, se1 = 0.f;
#pragma unroll
        for (int nt = 0; nt < 10; nt++) {
            float c[4] = {0.f, 0.f, 0.f, 0.f};
#pragma unroll
            for (int kb = 0; kb < 4; kb++) {
                unsigned bh0, bh1, bl0, bl1;
                ldsm_x2t(bh0, bh1, smaddr(sWh + (kb * 16 + brow) * LDW1 + nt * 8));
                ldsm_x2t(bl0, bl1, smaddr(sWl + (kb * 16 + brow) * LDW1 + nt * 8));
                mma16816(c, a[kb][0], a[kb][1], a[kb][2], a[kb][3], bh0, bh1);
                mma16816(c, a[kb + 4][0], a[kb + 4][1], a[kb + 4][2], a[kb + 4][3], bh0, bh1);
                mma16816(c, a[kb][0], a[kb][1], a[kb][2], a[kb][3], bl0, bl1);
            }
            float w0 = sw2s[nt * 8 + col];
            float w1 = sw2s[nt * 8 + col + 1];
            float v0 = siluf(c[0]) * w0 + siluf(c[1]) * w1;
            float v1 = siluf(c[2]) * w0 + siluf(c[3]) * w1;
            if (nt < 2)      { sc0 += v0; sc1 += v1; }
            else if (nt < 6) { ss0 += v0; ss1 += v1; }
            else             { se0 += v0; se1 += v1; }
        }

        // quad reduce
#pragma unroll
        for (int m = 1; m < 4; m <<= 1) {
            sc0 += __shfl_xor_sync(0xffffffffu, sc0, m);
            sc1 += __shfl_xor_sync(0xffffffffu, sc1, m);
            ss0 += __shfl_xor_sync(0xffffffffu, ss0, m);
            ss1 += __shfl_xor_sync(0xffffffffu, ss1, m);
            se0 += __shfl_xor_sync(0xffffffffu, se0, m);
            se1 += __shfl_xor_sync(0xffffffffu, se1, m);
        }
        if ((lane & 3) == 0) {
            int e0 = eb + rb + (lane >> 2);
            int e1 = e0 + 8;
            if (e0 < E) {
                int s = senders[e0];
                atomicAdd(&g_chis[s], sc0);
                atomicAdd(&g_sigA[s], ss0);
                atomicAdd(&g_epsA[s], se0);
            }
            if (e1 < E) {
                int s = senders[e1];
                atomicAdd(&g_chis[s], sc1);
                atomicAdd(&g_sigA[s], ss1);
                atomicAdd(&g_epsA[s], se1);
            }
        }
        __syncthreads();
    }
}

// ---------------------------------------------------------------------------
// Phase 2 (unchanged): per-node charges / pot / vdw / w embedding.
// ---------------------------------------------------------------------------
__global__ __launch_bounds__(256) void k_nodes(
    const int* __restrict__ species, const float* __restrict__ radius,
    const float* __restrict__ hardness, const float* __restrict__ charge_embed,
    float* __restrict__ out_charges, int N)
{
    int n = blockIdx.x * 256 + threadIdx.x;
    float potc = 0.f, vdwc = 0.f;
    if (n < N) {
        int sp = species[n];
        float gamma = fmaf(4.f, radius[sp], 0.5f);
        float hv = hardness[sp];
        float hard = fmaxf(hv, 0.f) + log1pf(__expf(-fabsf(hv)));
        float chis = g_chis[n];
        float q = -chis / hard;
        potc = 0.5f * (hard + 1.f / gamma) * q * q + chis * q;
        float sgv = sigmf(g_sigA[n]) * 0.15f + 0.15f;
        float epv = sigmf(g_epsA[n]) * 1.7f + 0.3f;
        vdwc = sgv * epv;
        out_charges[n] = q;

        const float s17 = 0.24253562503633297f;
        const float* ce = charge_embed + (size_t)sp * 16;
        float wv[16];
        float qs = q * s17;
#pragma unroll
        for (int j = 0; j < 16; j++) wv[j] = qs * cWw1[j];
#pragma unroll
        for (int i = 0; i < 16; i++) {
            float c = ce[i] * s17;
#pragma unroll
            for (int j = 0; j < 16; j++)
                wv[j] = fmaf(c, cWw1[(1 + i) * 16 + j], wv[j]);
        }
        float4* wout = reinterpret_cast<float4*>(g_w) + (size_t)n * 4;
#pragma unroll
        for (int j = 0; j < 4; j++)
            wout[j] = make_float4(wv[4 * j], wv[4 * j + 1], wv[4 * j + 2], wv[4 * j + 3]);
    }
#pragma unroll
    for (int off = 16; off > 0; off >>= 1) {
        potc += __shfl_down_sync(0xffffffffu, potc, off);
        vdwc += __shfl_down_sync(0xffffffffu, vdwc, off);
    }
    if ((threadIdx.x & 31) == 0) {
        atomicAdd(&g_scal[0], potc);
        atomicAdd(&g_scal[1], vdwc);
    }
}

// ---------------------------------------------------------------------------
// Phase 3: tensor cores, 8 tiles x 64 edges per CTA, 5-CTA/SM target.
// ---------------------------------------------------------------------------
#define LDA 168
#define LDW 40
#define TILES_PER_CTA 8

__global__ __launch_bounds__(128, 5) void k_phase3(
    const float* __restrict__ x, const float* __restrict__ vectors,
    const float* __restrict__ V, const int* __restrict__ senders,
    float* __restrict__ out_x, float* __restrict__ out_V,
    float* __restrict__ out_pv, int E)
{
    __shared__ __align__(16) __half sA[64 * LDA];
    __shared__ __align__(16) __half sW[11520];

    int tid = threadIdx.x;

    if (blockIdx.x == 0 && tid == 0) {
        out_pv[0] = g_scal[0];
        out_pv[1] = g_scal[1];
    }

    {
        const uint4* src = reinterpret_cast<const uint4*>(gWall);
        uint4* dst = reinterpret_cast<uint4*>(sW);
        for (int i = tid; i < 11520 / 8; i += 128) dst[i] = src[i];
    }

    const __half* sW1h = sW;
    const __half* sW2h = sW + 80 * LDW;
    const __half* sW3h = sW + 112 * LDW;
    const __half* sW1l = sW + 5760;
    const __half* sW2l = sW + 5760 + 80 * LDW;
    const __half* sW3l = sW + 5760 + 112 * LDW;

    int lane = tid & 31;
    int wid  = tid >> 5;
    int rb   = wid * 16;
    int brow = lane & 15;

#pragma unroll 1
    for (int t = 0; t < TILES_PER_CTA; t++) {
        int eb = (blockIdx.x * TILES_PER_CTA + t) * 64;
        if (eb >= E) break;

        for (int i = tid; i < 64 * 16; i += 128) {
            int r = i >> 4, q = i & 15;
            int e = eb + r;
            float4 v = make_float4(0.f, 0.f, 0.f, 0.f);
            if (e < E) v = reinterpret_cast<const float4*>(x)[(size_t)e * 16 + q];
            unsigned h01, l01, h23, l23;
            split2(v.x, v.y, h01, l01);
            split2(v.z, v.w, h23, l23);
            __half* Ar = sA + r * LDA;
            *reinterpret_cast<unsigned*>(Ar + q * 4)          = h01;
            *reinterpret_cast<unsigned*>(Ar + q * 4 + 2)      = h23;
            *reinterpret_cast<unsigned*>(Ar + 80 + q * 4)     = l01;
            *reinterpret_cast<unsigned*>(Ar + 80 + q * 4 + 2) = l23;
        }
        for (int i = tid; i < 64 * 4; i += 128) {
            int r = i >> 2, q = i & 3;
            int e = eb + r;
            float4 v = make_float4(0.f, 0.f, 0.f, 0.f);
            if (e < E) {
                int s = senders[e];
                v = reinterpret_cast<const float4*>(g_w)[(size_t)s * 4 + q];
            }
            unsigned h01, l01, h23, l23;
            split2(v.x, v.y, h01, l01);
            split2(v.z, v.w, h23, l23);
            __half* Ar = sA + r * LDA;
            *reinterpret_cast<unsigned*>(Ar + 64 + q * 4)      = h01;
            *reinterpret_cast<unsigned*>(Ar + 64 + q * 4 + 2)  = h23;
            *reinterpret_cast<unsigned*>(Ar + 144 + q * 4)     = l01;
            *reinterpret_cast<unsigned*>(Ar + 144 + q * 4 + 2) = l23;
        }
        __syncthreads();

        unsigned a[10][4];
        {
            const __half* ap = sA + (rb + (lane & 15)) * LDA + (lane >> 4) * 8;
#pragma unroll
            for (int kb = 0; kb < 10; kb++)
                ldsm_x4(a[kb][0], a[kb][1], a[kb][2], a[kb][3], smaddr(ap + kb * 16));
        }

        float c1[4][4];
#pragma unroll
        for (int nt = 0; nt < 4; nt++)
#pragma unroll
            for (int j = 0; j < 4; j++) c1[nt][j] = 0.f;
#pragma unroll
        for (int nt = 0; nt < 4; nt++) {
#pragma unroll
            for (int k5 = 0; k5 < 5; k5++) {
                unsigned bh0, bh1, bl0, bl1;
                ldsm_x2t(bh0, bh1, smaddr(sW1h + (k5 * 16 + brow) * LDW + nt * 8));
                ldsm_x2t(bl0, bl1, smaddr(sW1l + (k5 * 16 + brow) * LDW + nt * 8));
                mma16816(c1[nt], a[k5][0], a[k5][1], a[k5][2], a[k5][3], bh0, bh1);
                mma16816(c1[nt], a[k5 + 5][0], a[k5 + 5][1], a[k5 + 5][2], a[k5 + 5][3], bh0, bh1);
                mma16816(c1[nt], a[k5][0], a[k5][1], a[k5][2], a[k5][3], bl0, bl1);
            }
        }

        unsigned ah[2][4], al[2][4];
#pragma unroll
        for (int p = 0; p < 2; p++) {
            split2(siluf(c1[2 * p][0]),     siluf(c1[2 * p][1]),     ah[p][0], al[p][0]);
            split2(siluf(c1[2 * p][2]),     siluf(c1[2 * p][3]),     ah[p][1], al[p][1]);
            split2(siluf(c1[2 * p + 1][0]), siluf(c1[2 * p + 1][1]), ah[p][2], al[p][2]);
            split2(siluf(c1[2 * p + 1][2]), siluf(c1[2 * p + 1][3]), ah[p][3], al[p][3]);
        }

        float c2[4][4];
#pragma unroll
        for (int nt = 0; nt < 4; nt++)
#pragma unroll
            for (int j = 0; j < 4; j++) c2[nt][j] = 0.f;
#pragma unroll
        for (int nt = 0; nt < 4; nt++) {
#pragma unroll
            for (int kb = 0; kb < 2; kb++) {
                unsigned bh0, bh1, bl0, bl1;
                ldsm_x2t(bh0, bh1, smaddr(sW2h + (kb * 16 + brow) * LDW + nt * 8));
                ldsm_x2t(bl0, bl1, smaddr(sW2l + (kb * 16 + brow) * LDW + nt * 8));
                mma16816(c2[nt], ah[kb][0], ah[kb][1], ah[kb][2], ah[kb][3], bh0, bh1);
                mma16816(c2[nt], al[kb][0], al[kb][1], al[kb][2], al[kb][3], bh0, bh1);
                mma16816(c2[nt], ah[kb][0], ah[kb][1], ah[kb][2], ah[kb][3], bl0, bl1);
            }
        }
#pragma unroll
        for (int p = 0; p < 2; p++) {
            split2(siluf(c2[2 * p][0]),     siluf(c2[2 * p][1]),     ah[p][0], al[p][0]);
            split2(siluf(c2[2 * p][2]),     siluf(c2[2 * p][3]),     ah[p][1], al[p][1]);
            split2(siluf(c2[2 * p + 1][0]), siluf(c2[2 * p + 1][1]), ah[p][2], al[p][2]);
            split2(siluf(c2[2 * p + 1][2]), siluf(c2[2 * p + 1][3]), ah[p][3], al[p][3]);
        }

        float c3[4][4];
#pragma unroll
        for (int nt = 0; nt < 4; nt++)
#pragma unroll
            for (int j = 0; j < 4; j++) c3[nt][j] = 0.f;
#pragma unroll
        for (int nt = 0; nt < 4; nt++) {
#pragma unroll
            for (int kb = 0; kb < 2; kb++) {
                unsigned bh0, bh1, bl0, bl1;
                ldsm_x2t(bh0, bh1, smaddr(sW3h + (kb * 16 + brow) * LDW + nt * 8));
                ldsm_x2t(bl0, bl1, smaddr(sW3l + (kb * 16 + brow) * LDW + nt * 8));
                mma16816(c3[nt], ah[kb][0], ah[kb][1], ah[kb][2], ah[kb][3], bh0, bh1);
                mma16816(c3[nt], al[kb][0], al[kb][1], al[kb][2], al[kb][3], bh0, bh1);
                mma16816(c3[nt], ah[kb][0], ah[kb][1], ah[kb][2], ah[kb][3], bl0, bl1);
            }
        }

        int r0 = rb + (lane >> 2);
        int e0 = eb + r0, e1 = e0 + 8;
        float env0 = 0.f, env1 = 0.f;
        if (e0 < E) {
            const float* vp = vectors + (size_t)e0 * 3;
            float u = sqrtf(vp[0] * vp[0] + vp[1] * vp[1] + vp[2] * vp[2]);
            if (u < 1.f) {
                float u2 = u * u, u6 = u2 * u2 * u2;
                env0 = 1.f + u6 * (-28.f + u * (48.f - 21.f * u));
            }
        }
        if (e1 < E) {
            const float* vp = vectors + (size_t)e1 * 3;
            float u = sqrtf(vp[0] * vp[0] + vp[1] * vp[1] + vp[2] * vp[2]);
            if (u < 1.f) {
                float u2 = u * u, u6 = u2 * u2 * u2;
                env1 = 1.f + u6 * (-28.f + u * (48.f - 21.f * u));
            }
        }
        int col0 = (lane & 3) * 2;
#pragma unroll
        for (int nt = 0; nt < 4; nt++) {
            int c = nt * 8 + col0;
            if (e0 < E) {
                float2 v = make_float2(env0 * c3[nt][0], env0 * c3[nt][1]);
                *reinterpret_cast<float2*>(out_x + (size_t)e0 * 32 + c) = v;
            }
            if (e1 < E) {
                float2 v = make_float2(env1 * c3[nt][2], env1 * c3[nt][3]);
                *reinterpret_cast<float2*>(out_x + (size_t)e1 * 32 + c) = v;
            }
        }

        for (int i = tid; i < 64 * 4; i += 128) {
            int e = eb + (i >> 2);
            if (e < E) {
                reinterpret_cast<float4*>(out_V)[(size_t)e * 4 + (i & 3)] =
                    reinterpret_cast<const float4*>(V)[(size_t)e * 4 + (i & 3)];
            }
        }
        __syncthreads();
    }
}

// ---------------------------------------------------------------------------
// Launch. Output layout: x_out[E*32] | V[E*16] | charges[N] | pot | vdw
// ---------------------------------------------------------------------------
extern "C" void kernel_launch(void* const* d_in, const int* in_sizes, int n_in,
                              void* d_out, int out_size) {
    const float* vectors = (const float*)d_in[0];
    const float* x       = (const float*)d_in[1];
    const float* V       = (const float*)d_in[2];
    const int*   senders = (const int*)d_in[3];
    const int*   species = (const int*)d_in[4];
    const float* radius  = (const float*)d_in[5];
    const float* hardness= (const float*)d_in[6];
    const float* cembed  = (const float*)d_in[7];
    const float* Wc1 = (const float*)d_in[8];
    const float* Ws1 = (const float*)d_in[10];
    const float* We1 = (const float*)d_in[12];
    const float* Ww1 = (const float*)d_in[14];
    const float* Wx1 = (const float*)d_in[15];
    const float* Wx2 = (const float*)d_in[16];
    const float* Wx3 = (const float*)d_in[17];

    const int E = in_sizes[3];
    const int N = in_sizes[4];

    cudaMemcpyToSymbolAsync(cWc2, d_in[9],  16 * 4, 0, cudaMemcpyDeviceToDevice, 0);
    cudaMemcpyToSymbolAsync(cWs2, d_in[11], 32 * 4, 0, cudaMemcpyDeviceToDevice, 0);
    cudaMemcpyToSymbolAsync(cWe2, d_in[13], 32 * 4, 0, cudaMemcpyDeviceToDevice, 0);
    cudaMemcpyToSymbolAsync(cWw1, Ww1, 17 * 16 * 4, 0, cudaMemcpyDeviceToDevice, 0);

    float* out = (float*)d_out;
    float* out_x       = out;
    float* out_V       = out + (size_t)E * 32;
    float* out_charges = out + (size_t)E * 48;
    float* out_pv      = out + (size_t)E * 48 + N;

    int nb_n  = (N + 255) / 256;
    int nb_e1 = (E + 64 * P1_TILES - 1) / (64 * P1_TILES);
    int nb_e3 = (E + 64 * TILES_PER_CTA - 1) / (64 * TILES_PER_CTA);

    k_init<<<nb_n, 256>>>(Wx1, Wx2, Wx3, Wc1, Ws1, We1, N);
    k_phase1<<<nb_e1, 128>>>(x, senders, E);
    k_nodes<<<nb_n, 256>>>(species, radius, hardness, cembed, out_charges, N);
    k_phase3<<<nb_e3, 128>>>(x, vectors, V, senders, out_x, out_V, out_pv, E);
}

// round 13
// speedup vs baseline: 2.2445x; 1.1115x over previous
#include <cuda_runtime.h>
#include <cuda_fp16.h>
#include <math.h>

#define MAXN 50000

// scratch (device globals — no allocation allowed)
__device__ float g_chis[MAXN];
__device__ float g_sigA[MAXN];
__device__ float g_epsA[MAXN];
__device__ float g_w[MAXN * 16];
__device__ float g_scal[2];   // pot, vdw

// pre-split phase3 weights: hi [0,5760), lo [5760,11520)
__device__ __half gWall[11520];
// pre-split phase1 combined W1 [k=64][h=80 pad 88] * 1/sqrt(64): hi/lo
__device__ __half gW1all[11264];

// ---- constant weights for epilogues / nodes ----
__constant__ float cWc2[16];
__constant__ float cWs2[32];
__constant__ float cWe2[32];
__constant__ float cWw1[17 * 16];

__device__ __forceinline__ float siluf(float z) {
    return __fdividef(z, 1.0f + __expf(-z));
}
__device__ __forceinline__ float sigmf(float z) {
    return __fdividef(1.0f, 1.0f + __expf(-z));
}
__device__ __forceinline__ void prefetchL2(const void* p) {
    asm volatile("prefetch.global.L2 [%0];" :: "l"(p));
}

// ---- MMA helpers ----
__device__ __forceinline__ unsigned smaddr(const void* p) {
    unsigned a;
    asm("{ .reg .u64 t; cvta.to.shared.u64 t, %1; cvt.u32.u64 %0, t; }"
        : "=r"(a) : "l"(p));
    return a;
}
__device__ __forceinline__ void ldsm_x4(unsigned& r0, unsigned& r1,
                                        unsigned& r2, unsigned& r3, unsigned addr) {
    asm volatile("ldmatrix.sync.aligned.m8n8.x4.shared.b16 {%0,%1,%2,%3}, [%4];"
                 : "=r"(r0), "=r"(r1), "=r"(r2), "=r"(r3) : "r"(addr));
}
__device__ __forceinline__ void ldsm_x2t(unsigned& r0, unsigned& r1, unsigned addr) {
    asm volatile("ldmatrix.sync.aligned.m8n8.x2.trans.shared.b16 {%0,%1}, [%2];"
                 : "=r"(r0), "=r"(r1) : "r"(addr));
}
__device__ __forceinline__ void mma16816(float* c,
                                         unsigned a0, unsigned a1, unsigned a2, unsigned a3,
                                         unsigned b0, unsigned b1) {
    asm volatile(
        "mma.sync.aligned.m16n8k16.row.col.f32.f16.f16.f32 "
        "{%0,%1,%2,%3}, {%4,%5,%6,%7}, {%8,%9}, {%0,%1,%2,%3};"
        : "+f"(c[0]), "+f"(c[1]), "+f"(c[2]), "+f"(c[3])
        : "r"(a0), "r"(a1), "r"(a2), "r"(a3), "r"(b0), "r"(b1));
}
__device__ __forceinline__ void split2(float a, float b, unsigned& hi, unsigned& lo) {
    __half ha = __float2half_rn(a), hb = __float2half_rn(b);
    float ra = a - __half2float(ha);
    float rb = b - __half2float(hb);
    __half2 H = __halves2half2(ha, hb);
    __half2 L = __floats2half2_rn(ra, rb);
    hi = *reinterpret_cast<unsigned*>(&H);
    lo = *reinterpret_cast<unsigned*>(&L);
}

// ---------------------------------------------------------------------------
// Init: zero node accumulators + split both phase-weight banks (one launch).
// ---------------------------------------------------------------------------
__global__ void k_init(const float* __restrict__ Wx1, const float* __restrict__ Wx2,
                       const float* __restrict__ Wx3, const float* __restrict__ Wc1,
                       const float* __restrict__ Ws1, const float* __restrict__ We1,
                       int N) {
    int i = blockIdx.x * blockDim.x + threadIdx.x;
    if (i < N) { g_chis[i] = 0.f; g_sigA[i] = 0.f; g_epsA[i] = 0.f; }
    if (i < 2) g_scal[i] = 0.f;

    const float s80 = 0.11180339887498949f;
    const float s32 = 0.17677669529663689f;
    const float s64 = 0.125f;

    if (i < 5760) {
        int row = i / 40, n = i - row * 40;
        float v = 0.f;
        if (n < 32) {
            if (row < 80)       v = Wx1[row * 32 + n] * s80;
            else if (row < 112) v = Wx2[(row - 80) * 32 + n] * s32;
            else                v = Wx3[(row - 112) * 32 + n] * s32;
        }
        __half h = __float2half_rn(v);
        gWall[i] = h;
        gWall[5760 + i] = __float2half_rn(v - __half2float(h));
    }
    if (i < 5632) {
        int k = i / 88, h = i - k * 88;
        float v = 0.f;
        if (h < 16)      v = Wc1[k * 16 + h] * s64;
        else if (h < 48) v = Ws1[k * 32 + (h - 16)] * s64;
        else if (h < 80) v = We1[k * 32 + (h - 48)] * s64;
        __half hh = __float2half_rn(v);
        gW1all[i] = hh;
        gW1all[5632 + i] = __float2half_rn(v - __half2float(hh));
    }
}

// ---------------------------------------------------------------------------
// Phase 1 (tensor cores): warp = 16 rows x 10 nt, interleaved per-nt epilogue,
// smem w2 table, 5 CTAs/SM, next-tile L2 prefetch.
// ---------------------------------------------------------------------------
#define LDA1 136
#define LDW1 88
#define P1_TILES 8

__global__ __launch_bounds__(128, 5) void k_phase1(
    const float* __restrict__ x, const int* __restrict__ senders, int E)
{
    __shared__ __align__(16) __half sA[64 * LDA1];
    __shared__ __align__(16) __half sW[11264];
    __shared__ float sw2s[80];

    int tid = threadIdx.x;
    {
        const uint4* src = reinterpret_cast<const uint4*>(gW1all);
        uint4* dst = reinterpret_cast<uint4*>(sW);
        for (int i = tid; i < 11264 / 8; i += 128) dst[i] = src[i];
    }
    if (tid < 80) {
        const float s32c = 0.17677669529663689f;
        float v;
        if (tid < 16)      v = cWc2[tid] * 0.25f;
        else if (tid < 48) v = cWs2[tid - 16] * s32c;
        else               v = cWe2[tid - 48] * s32c;
        sw2s[tid] = v;
    }
    const __half* sWh = sW;
    const __half* sWl = sW + 5632;

    int lane = tid & 31;
    int wid  = tid >> 5;
    int rb   = wid * 16;
    int brow = lane & 15;
    int col  = (lane & 3) * 2;

#pragma unroll 1
    for (int t = 0; t < P1_TILES; t++) {
        int eb = (blockIdx.x * P1_TILES + t) * 64;
        if (eb >= E) break;

        // ---- stage A: x (cols 0..63 hi, 64..127 lo) ----
        for (int i = tid; i < 64 * 16; i += 128) {
            int r = i >> 4, q = i & 15;
            int e = eb + r;
            float4 v = make_float4(0.f, 0.f, 0.f, 0.f);
            if (e < E) v = reinterpret_cast<const float4*>(x)[(size_t)e * 16 + q];
            unsigned h01, l01, h23, l23;
            split2(v.x, v.y, h01, l01);
            split2(v.z, v.w, h23, l23);
            __half* Ar = sA + r * LDA1;
            *reinterpret_cast<unsigned*>(Ar + q * 4)          = h01;
            *reinterpret_cast<unsigned*>(Ar + q * 4 + 2)      = h23;
            *reinterpret_cast<unsigned*>(Ar + 64 + q * 4)     = l01;
            *reinterpret_cast<unsigned*>(Ar + 64 + q * 4 + 2) = l23;
        }
        __syncthreads();

        // ---- prefetch next tile into L2 (overlaps with MMA below) ----
        if (t + 1 < P1_TILES) {
            int ebn = eb + 64;
            if (ebn + (tid >> 1) < E)
                prefetchL2(x + (size_t)ebn * 64 + tid * 32);     // 128B/thread
            if (tid < 2 && ebn + tid * 32 < E)
                prefetchL2(senders + ebn + tid * 32);
        }

        // ---- A fragments: 8 k-blocks (0..3 hi, 4..7 lo) ----
        unsigned a[8][4];
        {
            const __half* ap = sA + (rb + (lane & 15)) * LDA1 + (lane >> 4) * 8;
#pragma unroll
            for (int kb = 0; kb < 8; kb++)
                ldsm_x4(a[kb][0], a[kb][1], a[kb][2], a[kb][3], smaddr(ap + kb * 16));
        }

        // ---- per-nt: MMA chain then immediate epilogue ----
        float sc0 = 0.f, sc1 = 0.f, ss0 = 0.f, ss1 = 0.f, se0 = 0.f, se1 = 0.f;
#pragma unroll
        for (int nt = 0; nt < 10; nt++) {
            float c[4] = {0.f, 0.f, 0.f, 0.f};
#pragma unroll
            for (int kb = 0; kb < 4; kb++) {
                unsigned bh0, bh1, bl0, bl1;
                ldsm_x2t(bh0, bh1, smaddr(sWh + (kb * 16 + brow) * LDW1 + nt * 8));
                ldsm_x2t(bl0, bl1, smaddr(sWl + (kb * 16 + brow) * LDW1 + nt * 8));
                mma16816(c, a[kb][0], a[kb][1], a[kb][2], a[kb][3], bh0, bh1);
                mma16816(c, a[kb + 4][0], a[kb + 4][1], a[kb + 4][2], a[kb + 4][3], bh0, bh1);
                mma16816(c, a[kb][0], a[kb][1], a[kb][2], a[kb][3], bl0, bl1);
            }
            float w0 = sw2s[nt * 8 + col];
            float w1 = sw2s[nt * 8 + col + 1];
            float v0 = siluf(c[0]) * w0 + siluf(c[1]) * w1;
            float v1 = siluf(c[2]) * w0 + siluf(c[3]) * w1;
            if (nt < 2)      { sc0 += v0; sc1 += v1; }
            else if (nt < 6) { ss0 += v0; ss1 += v1; }
            else             { se0 += v0; se1 += v1; }
        }

        // quad reduce
#pragma unroll
        for (int m = 1; m < 4; m <<= 1) {
            sc0 += __shfl_xor_sync(0xffffffffu, sc0, m);
            sc1 += __shfl_xor_sync(0xffffffffu, sc1, m);
            ss0 += __shfl_xor_sync(0xffffffffu, ss0, m);
            ss1 += __shfl_xor_sync(0xffffffffu, ss1, m);
            se0 += __shfl_xor_sync(0xffffffffu, se0, m);
            se1 += __shfl_xor_sync(0xffffffffu, se1, m);
        }
        if ((lane & 3) == 0) {
            int e0 = eb + rb + (lane >> 2);
            int e1 = e0 + 8;
            if (e0 < E) {
                int s = senders[e0];
                atomicAdd(&g_chis[s], sc0);
                atomicAdd(&g_sigA[s], ss0);
                atomicAdd(&g_epsA[s], se0);
            }
            if (e1 < E) {
                int s = senders[e1];
                atomicAdd(&g_chis[s], sc1);
                atomicAdd(&g_sigA[s], ss1);
                atomicAdd(&g_epsA[s], se1);
            }
        }
        __syncthreads();
    }
}

// ---------------------------------------------------------------------------
// Phase 2 (unchanged): per-node charges / pot / vdw / w embedding.
// ---------------------------------------------------------------------------
__global__ __launch_bounds__(256) void k_nodes(
    const int* __restrict__ species, const float* __restrict__ radius,
    const float* __restrict__ hardness, const float* __restrict__ charge_embed,
    float* __restrict__ out_charges, int N)
{
    int n = blockIdx.x * 256 + threadIdx.x;
    float potc = 0.f, vdwc = 0.f;
    if (n < N) {
        int sp = species[n];
        float gamma = fmaf(4.f, radius[sp], 0.5f);
        float hv = hardness[sp];
        float hard = fmaxf(hv, 0.f) + log1pf(__expf(-fabsf(hv)));
        float chis = g_chis[n];
        float q = -chis / hard;
        potc = 0.5f * (hard + 1.f / gamma) * q * q + chis * q;
        float sgv = sigmf(g_sigA[n]) * 0.15f + 0.15f;
        float epv = sigmf(g_epsA[n]) * 1.7f + 0.3f;
        vdwc = sgv * epv;
        out_charges[n] = q;

        const float s17 = 0.24253562503633297f;
        const float* ce = charge_embed + (size_t)sp * 16;
        float wv[16];
        float qs = q * s17;
#pragma unroll
        for (int j = 0; j < 16; j++) wv[j] = qs * cWw1[j];
#pragma unroll
        for (int i = 0; i < 16; i++) {
            float c = ce[i] * s17;
#pragma unroll
            for (int j = 0; j < 16; j++)
                wv[j] = fmaf(c, cWw1[(1 + i) * 16 + j], wv[j]);
        }
        float4* wout = reinterpret_cast<float4*>(g_w) + (size_t)n * 4;
#pragma unroll
        for (int j = 0; j < 4; j++)
            wout[j] = make_float4(wv[4 * j], wv[4 * j + 1], wv[4 * j + 2], wv[4 * j + 3]);
    }
#pragma unroll
    for (int off = 16; off > 0; off >>= 1) {
        potc += __shfl_down_sync(0xffffffffu, potc, off);
        vdwc += __shfl_down_sync(0xffffffffu, vdwc, off);
    }
    if ((threadIdx.x & 31) == 0) {
        atomicAdd(&g_scal[0], potc);
        atomicAdd(&g_scal[1], vdwc);
    }
}

// ---------------------------------------------------------------------------
// Phase 3: tensor cores, 8 tiles x 64 edges per CTA, 5 CTAs/SM,
// next-tile L2 prefetch incl. pre-resolved g_w gather.
// ---------------------------------------------------------------------------
#define LDA 168
#define LDW 40
#define TILES_PER_CTA 8

__global__ __launch_bounds__(128, 5) void k_phase3(
    const float* __restrict__ x, const float* __restrict__ vectors,
    const float* __restrict__ V, const int* __restrict__ senders,
    float* __restrict__ out_x, float* __restrict__ out_V,
    float* __restrict__ out_pv, int E)
{
    __shared__ __align__(16) __half sA[64 * LDA];
    __shared__ __align__(16) __half sW[11520];

    int tid = threadIdx.x;

    if (blockIdx.x == 0 && tid == 0) {
        out_pv[0] = g_scal[0];
        out_pv[1] = g_scal[1];
    }

    {
        const uint4* src = reinterpret_cast<const uint4*>(gWall);
        uint4* dst = reinterpret_cast<uint4*>(sW);
        for (int i = tid; i < 11520 / 8; i += 128) dst[i] = src[i];
    }

    const __half* sW1h = sW;
    const __half* sW2h = sW + 80 * LDW;
    const __half* sW3h = sW + 112 * LDW;
    const __half* sW1l = sW + 5760;
    const __half* sW2l = sW + 5760 + 80 * LDW;
    const __half* sW3l = sW + 5760 + 112 * LDW;

    int lane = tid & 31;
    int wid  = tid >> 5;
    int rb   = wid * 16;
    int brow = lane & 15;

#pragma unroll 1
    for (int t = 0; t < TILES_PER_CTA; t++) {
        int eb = (blockIdx.x * TILES_PER_CTA + t) * 64;
        if (eb >= E) break;

        // ---- prefetch current tile epilogue data (vectors, V) ----
        if (tid < 6) {
            int le = eb + (tid * 32) / 3;
            if (le < E) prefetchL2(vectors + (size_t)eb * 3 + tid * 32);
        }
        if (tid < 32 && eb + tid * 2 < E)
            prefetchL2(V + (size_t)eb * 16 + tid * 32);

        // ---- stage A: x + w-gather ----
        for (int i = tid; i < 64 * 16; i += 128) {
            int r = i >> 4, q = i & 15;
            int e = eb + r;
            float4 v = make_float4(0.f, 0.f, 0.f, 0.f);
            if (e < E) v = reinterpret_cast<const float4*>(x)[(size_t)e * 16 + q];
            unsigned h01, l01, h23, l23;
            split2(v.x, v.y, h01, l01);
            split2(v.z, v.w, h23, l23);
            __half* Ar = sA + r * LDA;
            *reinterpret_cast<unsigned*>(Ar + q * 4)          = h01;
            *reinterpret_cast<unsigned*>(Ar + q * 4 + 2)      = h23;
            *reinterpret_cast<unsigned*>(Ar + 80 + q * 4)     = l01;
            *reinterpret_cast<unsigned*>(Ar + 80 + q * 4 + 2) = l23;
        }
        for (int i = tid; i < 64 * 4; i += 128) {
            int r = i >> 2, q = i & 3;
            int e = eb + r;
            float4 v = make_float4(0.f, 0.f, 0.f, 0.f);
            if (e < E) {
                int s = senders[e];
                v = reinterpret_cast<const float4*>(g_w)[(size_t)s * 4 + q];
            }
            unsigned h01, l01, h23, l23;
            split2(v.x, v.y, h01, l01);
            split2(v.z, v.w, h23, l23);
            __half* Ar = sA + r * LDA;
            *reinterpret_cast<unsigned*>(Ar + 64 + q * 4)      = h01;
            *reinterpret_cast<unsigned*>(Ar + 64 + q * 4 + 2)  = h23;
            *reinterpret_cast<unsigned*>(Ar + 144 + q * 4)     = l01;
            *reinterpret_cast<unsigned*>(Ar + 144 + q * 4 + 2) = l23;
        }
        __syncthreads();

        // ---- prefetch next tile (x, senders, resolved g_w rows) ----
        if (t + 1 < TILES_PER_CTA) {
            int ebn = eb + 64;
            if (ebn + (tid >> 1) < E)
                prefetchL2(x + (size_t)ebn * 64 + tid * 32);
            if (tid < 2 && ebn + tid * 32 < E)
                prefetchL2(senders + ebn + tid * 32);
            // resolve next senders and prefetch g_w rows (kills 2-hop gather)
            if (tid < 64) {
                int e = ebn + tid;
                if (e < E) {
                    int sn = senders[e];
                    prefetchL2(g_w + (size_t)sn * 16);
                }
            }
        }

        unsigned a[10][4];
        {
            const __half* ap = sA + (rb + (lane & 15)) * LDA + (lane >> 4) * 8;
#pragma unroll
            for (int kb = 0; kb < 10; kb++)
                ldsm_x4(a[kb][0], a[kb][1], a[kb][2], a[kb][3], smaddr(ap + kb * 16));
        }

        float c1[4][4];
#pragma unroll
        for (int nt = 0; nt < 4; nt++)
#pragma unroll
            for (int j = 0; j < 4; j++) c1[nt][j] = 0.f;
#pragma unroll
        for (int nt = 0; nt < 4; nt++) {
#pragma unroll
            for (int k5 = 0; k5 < 5; k5++) {
                unsigned bh0, bh1, bl0, bl1;
                ldsm_x2t(bh0, bh1, smaddr(sW1h + (k5 * 16 + brow) * LDW + nt * 8));
                ldsm_x2t(bl0, bl1, smaddr(sW1l + (k5 * 16 + brow) * LDW + nt * 8));
                mma16816(c1[nt], a[k5][0], a[k5][1], a[k5][2], a[k5][3], bh0, bh1);
                mma16816(c1[nt], a[k5 + 5][0], a[k5 + 5][1], a[k5 + 5][2], a[k5 + 5][3], bh0, bh1);
                mma16816(c1[nt], a[k5][0], a[k5][1], a[k5][2], a[k5][3], bl0, bl1);
            }
        }

        unsigned ah[2][4], al[2][4];
#pragma unroll
        for (int p = 0; p < 2; p++) {
            split2(siluf(c1[2 * p][0]),     siluf(c1[2 * p][1]),     ah[p][0], al[p][0]);
            split2(siluf(c1[2 * p][2]),     siluf(c1[2 * p][3]),     ah[p][1], al[p][1]);
            split2(siluf(c1[2 * p + 1][0]), siluf(c1[2 * p + 1][1]), ah[p][2], al[p][2]);
            split2(siluf(c1[2 * p + 1][2]), siluf(c1[2 * p + 1][3]), ah[p][3], al[p][3]);
        }

        float c2[4][4];
#pragma unroll
        for (int nt = 0; nt < 4; nt++)
#pragma unroll
            for (int j = 0; j < 4; j++) c2[nt][j] = 0.f;
#pragma unroll
        for (int nt = 0; nt < 4; nt++) {
#pragma unroll
            for (int kb = 0; kb < 2; kb++) {
                unsigned bh0, bh1, bl0, bl1;
                ldsm_x2t(bh0, bh1, smaddr(sW2h + (kb * 16 + brow) * LDW + nt * 8));
                ldsm_x2t(bl0, bl1, smaddr(sW2l + (kb * 16 + brow) * LDW + nt * 8));
                mma16816(c2[nt], ah[kb][0], ah[kb][1], ah[kb][2], ah[kb][3], bh0, bh1);
                mma16816(c2[nt], al[kb][0], al[kb][1], al[kb][2], al[kb][3], bh0, bh1);
                mma16816(c2[nt], ah[kb][0], ah[kb][1], ah[kb][2], ah[kb][3], bl0, bl1);
            }
        }
#pragma unroll
        for (int p = 0; p < 2; p++) {
            split2(siluf(c2[2 * p][0]),     siluf(c2[2 * p][1]),     ah[p][0], al[p][0]);
            split2(siluf(c2[2 * p][2]),     siluf(c2[2 * p][3]),     ah[p][1], al[p][1]);
            split2(siluf(c2[2 * p + 1][0]), siluf(c2[2 * p + 1][1]), ah[p][2], al[p][2]);
            split2(siluf(c2[2 * p + 1][2]), siluf(c2[2 * p + 1][3]), ah[p][3], al[p][3]);
        }

        float c3[4][4];
#pragma unroll
        for (int nt = 0; nt < 4; nt++)
#pragma unroll
            for (int j = 0; j < 4; j++) c3[nt][j] = 0.f;
#pragma unroll
        for (int nt = 0; nt < 4; nt++) {
#pragma unroll
            for (int kb = 0; kb < 2; kb++) {
                unsigned bh0, bh1, bl0, bl1;
                ldsm_x2t(bh0, bh1, smaddr(sW3h + (kb * 16 + brow) * LDW + nt * 8));
                ldsm_x2t(bl0, bl1, smaddr(sW3l + (kb * 16 + brow) * LDW + nt * 8));
                mma16816(c3[nt], ah[kb][0], ah[kb][1], ah[kb][2], ah[kb][3], bh0, bh1);
                mma16816(c3[nt], al[kb][0], al[kb][1], al[kb][2], al[kb][3], bh0, bh1);
                mma16816(c3[nt], ah[kb][0], ah[kb][1], ah[kb][2], ah[kb][3], bl0, bl1);
            }
        }

        int r0 = rb + (lane >> 2);
        int e0 = eb + r0, e1 = e0 + 8;
        float env0 = 0.f, env1 = 0.f;
        if (e0 < E) {
            const float* vp = vectors + (size_t)e0 * 3;
            float u = sqrtf(vp[0] * vp[0] + vp[1] * vp[1] + vp[2] * vp[2]);
            if (u < 1.f) {
                float u2 = u * u, u6 = u2 * u2 * u2;
                env0 = 1.f + u6 * (-28.f + u * (48.f - 21.f * u));
            }
        }
        if (e1 < E) {
            const float* vp = vectors + (size_t)e1 * 3;
            float u = sqrtf(vp[0] * vp[0] + vp[1] * vp[1] + vp[2] * vp[2]);
            if (u < 1.f) {
                float u2 = u * u, u6 = u2 * u2 * u2;
                env1 = 1.f + u6 * (-28.f + u * (48.f - 21.f * u));
            }
        }
        int col0 = (lane & 3) * 2;
#pragma unroll
        for (int nt = 0; nt < 4; nt++) {
            int c = nt * 8 + col0;
            if (e0 < E) {
                float2 v = make_float2(env0 * c3[nt][0], env0 * c3[nt][1]);
                *reinterpret_cast<float2*>(out_x + (size_t)e0 * 32 + c) = v;
            }
            if (e1 < E) {
                float2 v = make_float2(env1 * c3[nt][2], env1 * c3[nt][3]);
                *reinterpret_cast<float2*>(out_x + (size_t)e1 * 32 + c) = v;
            }
        }

        for (int i = tid; i < 64 * 4; i += 128) {
            int e = eb + (i >> 2);
            if (e < E) {
                reinterpret_cast<float4*>(out_V)[(size_t)e * 4 + (i & 3)] =
                    reinterpret_cast<const float4*>(V)[(size_t)e * 4 + (i & 3)];
            }
        }
        __syncthreads();
    }
}

// ---------------------------------------------------------------------------
// Launch. Output layout: x_out[E*32] | V[E*16] | charges[N] | pot | vdw
// ---------------------------------------------------------------------------
extern "C" void kernel_launch(void* const* d_in, const int* in_sizes, int n_in,
                              void* d_out, int out_size) {
    const float* vectors = (const float*)d_in[0];
    const float* x       = (const float*)d_in[1];
    const float* V       = (const float*)d_in[2];
    const int*   senders = (const int*)d_in[3];
    const int*   species = (const int*)d_in[4];
    const float* radius  = (const float*)d_in[5];
    const float* hardness= (const float*)d_in[6];
    const float* cembed  = (const float*)d_in[7];
    const float* Wc1 = (const float*)d_in[8];
    const float* Ws1 = (const float*)d_in[10];
    const float* We1 = (const float*)d_in[12];
    const float* Ww1 = (const float*)d_in[14];
    const float* Wx1 = (const float*)d_in[15];
    const float* Wx2 = (const float*)d_in[16];
    const float* Wx3 = (const float*)d_in[17];

    const int E = in_sizes[3];
    const int N = in_sizes[4];

    cudaMemcpyToSymbolAsync(cWc2, d_in[9],  16 * 4, 0, cudaMemcpyDeviceToDevice, 0);
    cudaMemcpyToSymbolAsync(cWs2, d_in[11], 32 * 4, 0, cudaMemcpyDeviceToDevice, 0);
    cudaMemcpyToSymbolAsync(cWe2, d_in[13], 32 * 4, 0, cudaMemcpyDeviceToDevice, 0);
    cudaMemcpyToSymbolAsync(cWw1, Ww1, 17 * 16 * 4, 0, cudaMemcpyDeviceToDevice, 0);

    float* out = (float*)d_out;
    float* out_x       = out;
    float* out_V       = out + (size_t)E * 32;
    float* out_charges = out + (size_t)E * 48;
    float* out_pv      = out + (size_t)E * 48 + N;

    int nb_n  = (N + 255) / 256;
    int nb_e1 = (E + 64 * P1_TILES - 1) / (64 * P1_TILES);
    int nb_e3 = (E + 64 * TILES_PER_CTA - 1) / (64 * TILES_PER_CTA);

    k_init<<<nb_n, 256>>>(Wx1, Wx2, Wx3, Wc1, Ws1, We1, N);
    k_phase1<<<nb_e1, 128>>>(x, senders, E);
    k_nodes<<<nb_n, 256>>>(species, radius, hardness, cembed, out_charges, N);
    k_phase3<<<nb_e3, 128>>>(x, vectors, V, senders, out_x, out_V, out_pv, E);
}

// round 15
// speedup vs baseline: 2.3948x; 1.0670x over previous
#include <cuda_runtime.h>
#include <cuda_fp16.h>
#include <math.h>

#define MAXN 50000

// scratch (device globals — no allocation allowed)
__device__ float g_chis[MAXN];
__device__ float g_sigA[MAXN];
__device__ float g_epsA[MAXN];
__device__ float g_w[MAXN * 16];
__device__ float g_scal[2];   // pot, vdw

// pre-split phase3 weights: hi [0,5760), lo [5760,11520)
__device__ __half gWall[11520];
// pre-split phase1 combined W1 [k=64][h=80 pad 88] * 1/sqrt(64): hi/lo
__device__ __half gW1all[11264];

// ---- constant weights for epilogues / nodes ----
__constant__ float cWc2[16];
__constant__ float cWs2[32];
__constant__ float cWe2[32];
__constant__ float cWw1[17 * 16];

__device__ __forceinline__ float siluf(float z) {
    return __fdividef(z, 1.0f + __expf(-z));
}
__device__ __forceinline__ float sigmf(float z) {
    return __fdividef(1.0f, 1.0f + __expf(-z));
}
__device__ __forceinline__ void prefetchL2(const void* p) {
    asm volatile("prefetch.global.L2 [%0];" :: "l"(p));
}

// ---- MMA helpers ----
__device__ __forceinline__ unsigned smaddr(const void* p) {
    unsigned a;
    asm("{ .reg .u64 t; cvta.to.shared.u64 t, %1; cvt.u32.u64 %0, t; }"
        : "=r"(a) : "l"(p));
    return a;
}
__device__ __forceinline__ void ldsm_x4(unsigned& r0, unsigned& r1,
                                        unsigned& r2, unsigned& r3, unsigned addr) {
    asm volatile("ldmatrix.sync.aligned.m8n8.x4.shared.b16 {%0,%1,%2,%3}, [%4];"
                 : "=r"(r0), "=r"(r1), "=r"(r2), "=r"(r3) : "r"(addr));
}
__device__ __forceinline__ void ldsm_x2t(unsigned& r0, unsigned& r1, unsigned addr) {
    asm volatile("ldmatrix.sync.aligned.m8n8.x2.trans.shared.b16 {%0,%1}, [%2];"
                 : "=r"(r0), "=r"(r1) : "r"(addr));
}
__device__ __forceinline__ void mma16816(float* c,
                                         unsigned a0, unsigned a1, unsigned a2, unsigned a3,
                                         unsigned b0, unsigned b1) {
    asm volatile(
        "mma.sync.aligned.m16n8k16.row.col.f32.f16.f16.f32 "
        "{%0,%1,%2,%3}, {%4,%5,%6,%7}, {%8,%9}, {%0,%1,%2,%3};"
        : "+f"(c[0]), "+f"(c[1]), "+f"(c[2]), "+f"(c[3])
        : "r"(a0), "r"(a1), "r"(a2), "r"(a3), "r"(b0), "r"(b1));
}
__device__ __forceinline__ void split2(float a, float b, unsigned& hi, unsigned& lo) {
    __half ha = __float2half_rn(a), hb = __float2half_rn(b);
    float ra = a - __half2float(ha);
    float rb = b - __half2float(hb);
    __half2 H = __halves2half2(ha, hb);
    __half2 L = __floats2half2_rn(ra, rb);
    hi = *reinterpret_cast<unsigned*>(&H);
    lo = *reinterpret_cast<unsigned*>(&L);
}

// ---------------------------------------------------------------------------
// Init: zero node accumulators + split both phase-weight banks (one launch).
// ---------------------------------------------------------------------------
__global__ void k_init(const float* __restrict__ Wx1, const float* __restrict__ Wx2,
                       const float* __restrict__ Wx3, const float* __restrict__ Wc1,
                       const float* __restrict__ Ws1, const float* __restrict__ We1,
                       int N) {
    int i = blockIdx.x * blockDim.x + threadIdx.x;
    if (i < N) { g_chis[i] = 0.f; g_sigA[i] = 0.f; g_epsA[i] = 0.f; }
    if (i < 2) g_scal[i] = 0.f;

    const float s80 = 0.11180339887498949f;
    const float s32 = 0.17677669529663689f;
    const float s64 = 0.125f;

    if (i < 5760) {
        int row = i / 40, n = i - row * 40;
        float v = 0.f;
        if (n < 32) {
            if (row < 80)       v = Wx1[row * 32 + n] * s80;
            else if (row < 112) v = Wx2[(row - 80) * 32 + n] * s32;
            else                v = Wx3[(row - 112) * 32 + n] * s32;
        }
        __half h = __float2half_rn(v);
        gWall[i] = h;
        gWall[5760 + i] = __float2half_rn(v - __half2float(h));
    }
    if (i < 5632) {
        int k = i / 88, h = i - k * 88;
        float v = 0.f;
        if (h < 16)      v = Wc1[k * 16 + h] * s64;
        else if (h < 48) v = Ws1[k * 32 + (h - 16)] * s64;
        else if (h < 80) v = We1[k * 32 + (h - 48)] * s64;
        __half hh = __float2half_rn(v);
        gW1all[i] = hh;
        gW1all[5632 + i] = __float2half_rn(v - __half2float(hh));
    }
}

// ---------------------------------------------------------------------------
// Phase 1 (tensor cores): 256 threads, 8 warps x 16 rows = 128-edge tiles.
// Dynamic smem; 3 CTAs/SM (24 warps). Per-nt interleaved epilogue.
// ---------------------------------------------------------------------------
#define LDA1 136
#define LDW1 88
#define P1_TILES 4
#define P1_SMEM (128 * LDA1 * 2 + 11264 * 2 + 320)

__global__ __launch_bounds__(256, 3) void k_phase1(
    const float* __restrict__ x, const int* __restrict__ senders, int E)
{
    extern __shared__ __align__(16) char dyn1[];
    __half* sA = reinterpret_cast<__half*>(dyn1);
    __half* sW = sA + 128 * LDA1;
    float* sw2s = reinterpret_cast<float*>(sW + 11264);

    int tid = threadIdx.x;
    {
        const uint4* src = reinterpret_cast<const uint4*>(gW1all);
        uint4* dst = reinterpret_cast<uint4*>(sW);
        for (int i = tid; i < 11264 / 8; i += 256) dst[i] = src[i];
    }
    if (tid < 80) {
        const float s32c = 0.17677669529663689f;
        float v;
        if (tid < 16)      v = cWc2[tid] * 0.25f;
        else if (tid < 48) v = cWs2[tid - 16] * s32c;
        else               v = cWe2[tid - 48] * s32c;
        sw2s[tid] = v;
    }
    const __half* sWh = sW;
    const __half* sWl = sW + 5632;

    int lane = tid & 31;
    int wid  = tid >> 5;
    int rb   = wid * 16;
    int brow = lane & 15;
    int col  = (lane & 3) * 2;

#pragma unroll 1
    for (int t = 0; t < P1_TILES; t++) {
        int eb = (blockIdx.x * P1_TILES + t) * 128;
        if (eb >= E) break;

        // ---- stage A: x (cols 0..63 hi, 64..127 lo) ----
        for (int i = tid; i < 128 * 16; i += 256) {
            int r = i >> 4, q = i & 15;
            int e = eb + r;
            float4 v = make_float4(0.f, 0.f, 0.f, 0.f);
            if (e < E) v = reinterpret_cast<const float4*>(x)[(size_t)e * 16 + q];
            unsigned h01, l01, h23, l23;
            split2(v.x, v.y, h01, l01);
            split2(v.z, v.w, h23, l23);
            __half* Ar = sA + r * LDA1;
            *reinterpret_cast<unsigned*>(Ar + q * 4)          = h01;
            *reinterpret_cast<unsigned*>(Ar + q * 4 + 2)      = h23;
            *reinterpret_cast<unsigned*>(Ar + 64 + q * 4)     = l01;
            *reinterpret_cast<unsigned*>(Ar + 64 + q * 4 + 2) = l23;
        }
        __syncthreads();

        // ---- prefetch next tile into L2 (overlaps with MMA below) ----
        if (t + 1 < P1_TILES) {
            int ebn = eb + 128;
            if (ebn + (tid >> 1) < E)
                prefetchL2(x + (size_t)ebn * 64 + tid * 32);     // 128B/thread
            if (tid < 4 && ebn + tid * 32 < E)
                prefetchL2(senders + ebn + tid * 32);
        }

        // ---- A fragments: 8 k-blocks (0..3 hi, 4..7 lo) ----
        unsigned a[8][4];
        {
            const __half* ap = sA + (rb + (lane & 15)) * LDA1 + (lane >> 4) * 8;
#pragma unroll
            for (int kb = 0; kb < 8; kb++)
                ldsm_x4(a[kb][0], a[kb][1], a[kb][2], a[kb][3], smaddr(ap + kb * 16));
        }

        // ---- per-nt: MMA chain then immediate epilogue ----
        float sc0 = 0.f, sc1 = 0.f, ss0 = 0.f, ss1 = 0.f, se0 = 0.f, se1 = 0.f;
#pragma unroll
        for (int nt = 0; nt < 10; nt++) {
            float c[4] = {0.f, 0.f, 0.f, 0.f};
#pragma unroll
            for (int kb = 0; kb < 4; kb++) {
                unsigned bh0, bh1, bl0, bl1;
                ldsm_x2t(bh0, bh1, smaddr(sWh + (kb * 16 + brow) * LDW1 + nt * 8));
                ldsm_x2t(bl0, bl1, smaddr(sWl + (kb * 16 + brow) * LDW1 + nt * 8));
                mma16816(c, a[kb][0], a[kb][1], a[kb][2], a[kb][3], bh0, bh1);
                mma16816(c, a[kb + 4][0], a[kb + 4][1], a[kb + 4][2], a[kb + 4][3], bh0, bh1);
                mma16816(c, a[kb][0], a[kb][1], a[kb][2], a[kb][3], bl0, bl1);
            }
            float w0 = sw2s[nt * 8 + col];
            float w1 = sw2s[nt * 8 + col + 1];
            float v0 = siluf(c[0]) * w0 + siluf(c[1]) * w1;
            float v1 = siluf(c[2]) * w0 + siluf(c[3]) * w1;
            if (nt < 2)      { sc0 += v0; sc1 += v1; }
            else if (nt < 6) { ss0 += v0; ss1 += v1; }
            else             { se0 += v0; se1 += v1; }
        }

        // quad reduce
#pragma unroll
        for (int m = 1; m < 4; m <<= 1) {
            sc0 += __shfl_xor_sync(0xffffffffu, sc0, m);
            sc1 += __shfl_xor_sync(0xffffffffu, sc1, m);
            ss0 += __shfl_xor_sync(0xffffffffu, ss0, m);
            ss1 += __shfl_xor_sync(0xffffffffu, ss1, m);
            se0 += __shfl_xor_sync(0xffffffffu, se0, m);
            se1 += __shfl_xor_sync(0xffffffffu, se1, m);
        }
        if ((lane & 3) == 0) {
            int e0 = eb + rb + (lane >> 2);
            int e1 = e0 + 8;
            if (e0 < E) {
                int s = senders[e0];
                atomicAdd(&g_chis[s], sc0);
                atomicAdd(&g_sigA[s], ss0);
                atomicAdd(&g_epsA[s], se0);
            }
            if (e1 < E) {
                int s = senders[e1];
                atomicAdd(&g_chis[s], sc1);
                atomicAdd(&g_sigA[s], ss1);
                atomicAdd(&g_epsA[s], se1);
            }
        }
        __syncthreads();
    }
}

// ---------------------------------------------------------------------------
// Phase 2 (unchanged): per-node charges / pot / vdw / w embedding.
// ---------------------------------------------------------------------------
__global__ __launch_bounds__(256) void k_nodes(
    const int* __restrict__ species, const float* __restrict__ radius,
    const float* __restrict__ hardness, const float* __restrict__ charge_embed,
    float* __restrict__ out_charges, int N)
{
    int n = blockIdx.x * 256 + threadIdx.x;
    float potc = 0.f, vdwc = 0.f;
    if (n < N) {
        int sp = species[n];
        float gamma = fmaf(4.f, radius[sp], 0.5f);
        float hv = hardness[sp];
        float hard = fmaxf(hv, 0.f) + log1pf(__expf(-fabsf(hv)));
        float chis = g_chis[n];
        float q = -chis / hard;
        potc = 0.5f * (hard + 1.f / gamma) * q * q + chis * q;
        float sgv = sigmf(g_sigA[n]) * 0.15f + 0.15f;
        float epv = sigmf(g_epsA[n]) * 1.7f + 0.3f;
        vdwc = sgv * epv;
        out_charges[n] = q;

        const float s17 = 0.24253562503633297f;
        const float* ce = charge_embed + (size_t)sp * 16;
        float wv[16];
        float qs = q * s17;
#pragma unroll
        for (int j = 0; j < 16; j++) wv[j] = qs * cWw1[j];
#pragma unroll
        for (int i = 0; i < 16; i++) {
            float c = ce[i] * s17;
#pragma unroll
            for (int j = 0; j < 16; j++)
                wv[j] = fmaf(c, cWw1[(1 + i) * 16 + j], wv[j]);
        }
        float4* wout = reinterpret_cast<float4*>(g_w) + (size_t)n * 4;
#pragma unroll
        for (int j = 0; j < 4; j++)
            wout[j] = make_float4(wv[4 * j], wv[4 * j + 1], wv[4 * j + 2], wv[4 * j + 3]);
    }
#pragma unroll
    for (int off = 16; off > 0; off >>= 1) {
        potc += __shfl_down_sync(0xffffffffu, potc, off);
        vdwc += __shfl_down_sync(0xffffffffu, vdwc, off);
    }
    if ((threadIdx.x & 31) == 0) {
        atomicAdd(&g_scal[0], potc);
        atomicAdd(&g_scal[1], vdwc);
    }
}

// ---------------------------------------------------------------------------
// Phase 3: tensor cores, 256 threads, 8 warps x 16 rows = 128-edge tiles,
// dynamic smem, 3 CTAs/SM, prefetch pipeline.
// ---------------------------------------------------------------------------
#define LDA 168
#define LDW 40
#define P3_TILES 4
#define P3_SMEM (128 * LDA * 2 + 11520 * 2)

__global__ __launch_bounds__(256, 3) void k_phase3(
    const float* __restrict__ x, const float* __restrict__ vectors,
    const float* __restrict__ V, const int* __restrict__ senders,
    float* __restrict__ out_x, float* __restrict__ out_V,
    float* __restrict__ out_pv, int E)
{
    extern __shared__ __align__(16) char dyn3[];
    __half* sA = reinterpret_cast<__half*>(dyn3);
    __half* sW = sA + 128 * LDA;

    int tid = threadIdx.x;

    if (blockIdx.x == 0 && tid == 0) {
        out_pv[0] = g_scal[0];
        out_pv[1] = g_scal[1];
    }

    {
        const uint4* src = reinterpret_cast<const uint4*>(gWall);
        uint4* dst = reinterpret_cast<uint4*>(sW);
        for (int i = tid; i < 11520 / 8; i += 256) dst[i] = src[i];
    }

    const __half* sW1h = sW;
    const __half* sW2h = sW + 80 * LDW;
    const __half* sW3h = sW + 112 * LDW;
    const __half* sW1l = sW + 5760;
    const __half* sW2l = sW + 5760 + 80 * LDW;
    const __half* sW3l = sW + 5760 + 112 * LDW;

    int lane = tid & 31;
    int wid  = tid >> 5;
    int rb   = wid * 16;
    int brow = lane & 15;

#pragma unroll 1
    for (int t = 0; t < P3_TILES; t++) {
        int eb = (blockIdx.x * P3_TILES + t) * 128;
        if (eb >= E) break;

        // ---- prefetch current tile epilogue data (vectors, V) ----
        if (tid < 12 && eb + tid * 10 < E)
            prefetchL2(vectors + (size_t)eb * 3 + tid * 32);
        if (tid < 64 && eb + tid * 2 < E)
            prefetchL2(V + (size_t)eb * 16 + tid * 32);

        // ---- stage A: x + w-gather ----
        for (int i = tid; i < 128 * 16; i += 256) {
            int r = i >> 4, q = i & 15;
            int e = eb + r;
            float4 v = make_float4(0.f, 0.f, 0.f, 0.f);
            if (e < E) v = reinterpret_cast<const float4*>(x)[(size_t)e * 16 + q];
            unsigned h01, l01, h23, l23;
            split2(v.x, v.y, h01, l01);
            split2(v.z, v.w, h23, l23);
            __half* Ar = sA + r * LDA;
            *reinterpret_cast<unsigned*>(Ar + q * 4)          = h01;
            *reinterpret_cast<unsigned*>(Ar + q * 4 + 2)      = h23;
            *reinterpret_cast<unsigned*>(Ar + 80 + q * 4)     = l01;
            *reinterpret_cast<unsigned*>(Ar + 80 + q * 4 + 2) = l23;
        }
        for (int i = tid; i < 128 * 4; i += 256) {
            int r = i >> 2, q = i & 3;
            int e = eb + r;
            float4 v = make_float4(0.f, 0.f, 0.f, 0.f);
            if (e < E) {
                int s = senders[e];
                v = reinterpret_cast<const float4*>(g_w)[(size_t)s * 4 + q];
            }
            unsigned h01, l01, h23, l23;
            split2(v.x, v.y, h01, l01);
            split2(v.z, v.w, h23, l23);
            __half* Ar = sA + r * LDA;
            *reinterpret_cast<unsigned*>(Ar + 64 + q * 4)      = h01;
            *reinterpret_cast<unsigned*>(Ar + 64 + q * 4 + 2)  = h23;
            *reinterpret_cast<unsigned*>(Ar + 144 + q * 4)     = l01;
            *reinterpret_cast<unsigned*>(Ar + 144 + q * 4 + 2) = l23;
        }
        __syncthreads();

        // ---- prefetch next tile (x, senders, resolved g_w rows) ----
        if (t + 1 < P3_TILES) {
            int ebn = eb + 128;
            if (ebn + (tid >> 1) < E)
                prefetchL2(x + (size_t)ebn * 64 + tid * 32);
            if (tid < 4 && ebn + tid * 32 < E)
                prefetchL2(senders + ebn + tid * 32);
            if (tid < 128) {
                int e = ebn + tid;
                if (e < E) {
                    int sn = senders[e];
                    prefetchL2(g_w + (size_t)sn * 16);
                }
            }
        }

        unsigned a[10][4];
        {
            const __half* ap = sA + (rb + (lane & 15)) * LDA + (lane >> 4) * 8;
#pragma unroll
            for (int kb = 0; kb < 10; kb++)
                ldsm_x4(a[kb][0], a[kb][1], a[kb][2], a[kb][3], smaddr(ap + kb * 16));
        }

        float c1[4][4];
#pragma unroll
        for (int nt = 0; nt < 4; nt++)
#pragma unroll
            for (int j = 0; j < 4; j++) c1[nt][j] = 0.f;
#pragma unroll
        for (int nt = 0; nt < 4; nt++) {
#pragma unroll
            for (int k5 = 0; k5 < 5; k5++) {
                unsigned bh0, bh1, bl0, bl1;
                ldsm_x2t(bh0, bh1, smaddr(sW1h + (k5 * 16 + brow) * LDW + nt * 8));
                ldsm_x2t(bl0, bl1, smaddr(sW1l + (k5 * 16 + brow) * LDW + nt * 8));
                mma16816(c1[nt], a[k5][0], a[k5][1], a[k5][2], a[k5][3], bh0, bh1);
                mma16816(c1[nt], a[k5 + 5][0], a[k5 + 5][1], a[k5 + 5][2], a[k5 + 5][3], bh0, bh1);
                mma16816(c1[nt], a[k5][0], a[k5][1], a[k5][2], a[k5][3], bl0, bl1);
            }
        }

        unsigned ah[2][4], al[2][4];
#pragma unroll
        for (int p = 0; p < 2; p++) {
            split2(siluf(c1[2 * p][0]),     siluf(c1[2 * p][1]),     ah[p][0], al[p][0]);
            split2(siluf(c1[2 * p][2]),     siluf(c1[2 * p][3]),     ah[p][1], al[p][1]);
            split2(siluf(c1[2 * p + 1][0]), siluf(c1[2 * p + 1][1]), ah[p][2], al[p][2]);
            split2(siluf(c1[2 * p + 1][2]), siluf(c1[2 * p + 1][3]), ah[p][3], al[p][3]);
        }

        float c2[4][4];
#pragma unroll
        for (int nt = 0; nt < 4; nt++)
#pragma unroll
            for (int j = 0; j < 4; j++) c2[nt][j] = 0.f;
#pragma unroll
        for (int nt = 0; nt < 4; nt++) {
#pragma unroll
            for (int kb = 0; kb < 2; kb++) {
                unsigned bh0, bh1, bl0, bl1;
                ldsm_x2t(bh0, bh1, smaddr(sW2h + (kb * 16 + brow) * LDW + nt * 8));
                ldsm_x2t(bl0, bl1, smaddr(sW2l + (kb * 16 + brow) * LDW + nt * 8));
                mma16816(c2[nt], ah[kb][0], ah[kb][1], ah[kb][2], ah[kb][3], bh0, bh1);
                mma16816(c2[nt], al[kb][0], al[kb][1], al[kb][2], al[kb][3], bh0, bh1);
                mma16816(c2[nt], ah[kb][0], ah[kb][1], ah[kb][2], ah[kb][3], bl0, bl1);
            }
        }
#pragma unroll
        for (int p = 0; p < 2; p++) {
            split2(siluf(c2[2 * p][0]),     siluf(c2[2 * p][1]),     ah[p][0], al[p][0]);
            split2(siluf(c2[2 * p][2]),     siluf(c2[2 * p][3]),     ah[p][1], al[p][1]);
            split2(siluf(c2[2 * p + 1][0]), siluf(c2[2 * p + 1][1]), ah[p][2], al[p][2]);
            split2(siluf(c2[2 * p + 1][2]), siluf(c2[2 * p + 1][3]), ah[p][3], al[p][3]);
        }

        float c3[4][4];
#pragma unroll
        for (int nt = 0; nt < 4; nt++)
#pragma unroll
            for (int j = 0; j < 4; j++) c3[nt][j] = 0.f;
#pragma unroll
        for (int nt = 0; nt < 4; nt++) {
#pragma unroll
            for (int kb = 0; kb < 2; kb++) {
                unsigned bh0, bh1, bl0, bl1;
                ldsm_x2t(bh0, bh1, smaddr(sW3h + (kb * 16 + brow) * LDW + nt * 8));
                ldsm_x2t(bl0, bl1, smaddr(sW3l + (kb * 16 + brow) * LDW + nt * 8));
                mma16816(c3[nt], ah[kb][0], ah[kb][1], ah[kb][2], ah[kb][3], bh0, bh1);
                mma16816(c3[nt], al[kb][0], al[kb][1], al[kb][2], al[kb][3], bh0, bh1);
                mma16816(c3[nt], ah[kb][0], ah[kb][1], ah[kb][2], ah[kb][3], bl0, bl1);
            }
        }

        int r0 = rb + (lane >> 2);
        int e0 = eb + r0, e1 = e0 + 8;
        float env0 = 0.f, env1 = 0.f;
        if (e0 < E) {
            const float* vp = vectors + (size_t)e0 * 3;
            float u = sqrtf(vp[0] * vp[0] + vp[1] * vp[1] + vp[2] * vp[2]);
            if (u < 1.f) {
                float u2 = u * u, u6 = u2 * u2 * u2;
                env0 = 1.f + u6 * (-28.f + u * (48.f - 21.f * u));
            }
        }
        if (e1 < E) {
            const float* vp = vectors + (size_t)e1 * 3;
            float u = sqrtf(vp[0] * vp[0] + vp[1] * vp[1] + vp[2] * vp[2]);
            if (u < 1.f) {
                float u2 = u * u, u6 = u2 * u2 * u2;
                env1 = 1.f + u6 * (-28.f + u * (48.f - 21.f * u));
            }
        }
        int col0 = (lane & 3) * 2;
#pragma unroll
        for (int nt = 0; nt < 4; nt++) {
            int c = nt * 8 + col0;
            if (e0 < E) {
                float2 v = make_float2(env0 * c3[nt][0], env0 * c3[nt][1]);
                *reinterpret_cast<float2*>(out_x + (size_t)e0 * 32 + c) = v;
            }
            if (e1 < E) {
                float2 v = make_float2(env1 * c3[nt][2], env1 * c3[nt][3]);
                *reinterpret_cast<float2*>(out_x + (size_t)e1 * 32 + c) = v;
            }
        }

        for (int i = tid; i < 128 * 4; i += 256) {
            int e = eb + (i >> 2);
            if (e < E) {
                reinterpret_cast<float4*>(out_V)[(size_t)e * 4 + (i & 3)] =
                    reinterpret_cast<const float4*>(V)[(size_t)e * 4 + (i & 3)];
            }
        }
        __syncthreads();
    }
}

// ---------------------------------------------------------------------------
// Launch. Output layout: x_out[E*32] | V[E*16] | charges[N] | pot | vdw
// No static state: attributes set unconditionally every call (idempotent).
// ---------------------------------------------------------------------------
extern "C" void kernel_launch(void* const* d_in, const int* in_sizes, int n_in,
                              void* d_out, int out_size) {
    const float* vectors = (const float*)d_in[0];
    const float* x       = (const float*)d_in[1];
    const float* V       = (const float*)d_in[2];
    const int*   senders = (const int*)d_in[3];
    const int*   species = (const int*)d_in[4];
    const float* radius  = (const float*)d_in[5];
    const float* hardness= (const float*)d_in[6];
    const float* cembed  = (const float*)d_in[7];
    const float* Wc1 = (const float*)d_in[8];
    const float* Ws1 = (const float*)d_in[10];
    const float* We1 = (const float*)d_in[12];
    const float* Ww1 = (const float*)d_in[14];
    const float* Wx1 = (const float*)d_in[15];
    const float* Wx2 = (const float*)d_in[16];
    const float* Wx3 = (const float*)d_in[17];

    const int E = in_sizes[3];
    const int N = in_sizes[4];

    cudaFuncSetAttribute(k_phase1, cudaFuncAttributeMaxDynamicSharedMemorySize, P1_SMEM);
    cudaFuncSetAttribute(k_phase3, cudaFuncAttributeMaxDynamicSharedMemorySize, P3_SMEM);

    cudaMemcpyToSymbolAsync(cWc2, d_in[9],  16 * 4, 0, cudaMemcpyDeviceToDevice, 0);
    cudaMemcpyToSymbolAsync(cWs2, d_in[11], 32 * 4, 0, cudaMemcpyDeviceToDevice, 0);
    cudaMemcpyToSymbolAsync(cWe2, d_in[13], 32 * 4, 0, cudaMemcpyDeviceToDevice, 0);
    cudaMemcpyToSymbolAsync(cWw1, Ww1, 17 * 16 * 4, 0, cudaMemcpyDeviceToDevice, 0);

    float* out = (float*)d_out;
    float* out_x       = out;
    float* out_V       = out + (size_t)E * 32;
    float* out_charges = out + (size_t)E * 48;
    float* out_pv      = out + (size_t)E * 48 + N;

    int nb_n  = (N + 255) / 256;
    int nb_e1 = (E + 128 * P1_TILES - 1) / (128 * P1_TILES);
    int nb_e3 = (E + 128 * P3_TILES - 1) / (128 * P3_TILES);

    k_init<<<nb_n, 256>>>(Wx1, Wx2, Wx3, Wc1, Ws1, We1, N);
    k_phase1<<<nb_e1, 256, P1_SMEM>>>(x, senders, E);
    k_nodes<<<nb_n, 256>>>(species, radius, hardness, cembed, out_charges, N);
    k_phase3<<<nb_e3, 256, P3_SMEM>>>(x, vectors, V, senders, out_x, out_V, out_pv, E);
}

// round 16
// speedup vs baseline: 2.4354x; 1.0170x over previous
#include <cuda_runtime.h>
#include <cuda_fp16.h>
#include <math.h>

#define MAXN 50000

// scratch (device globals — no allocation allowed)
__device__ float g_chis[MAXN];
__device__ float g_sigA[MAXN];
__device__ float g_epsA[MAXN];
__device__ float g_w[MAXN * 16];
__device__ float g_scal[2];   // pot, vdw

// pre-split phase3 weights: hi [0,5760), lo [5760,11520)
__device__ __half gWall[11520];
// pre-split phase1 combined W1 [k=64][h=80 pad 88] * 1/sqrt(64): hi/lo
__device__ __half gW1all[11264];

// ---- constant weights for epilogues / nodes ----
__constant__ float cWc2[16];
__constant__ float cWs2[32];
__constant__ float cWe2[32];
__constant__ float cWw1[17 * 16];

__device__ __forceinline__ float siluf(float z) {
    return __fdividef(z, 1.0f + __expf(-z));
}
__device__ __forceinline__ float sigmf(float z) {
    return __fdividef(1.0f, 1.0f + __expf(-z));
}
__device__ __forceinline__ void prefetchL2(const void* p) {
    asm volatile("prefetch.global.L2 [%0];" :: "l"(p));
}

// ---- MMA helpers ----
__device__ __forceinline__ unsigned smaddr(const void* p) {
    unsigned a;
    asm("{ .reg .u64 t; cvta.to.shared.u64 t, %1; cvt.u32.u64 %0, t; }"
        : "=r"(a) : "l"(p));
    return a;
}
__device__ __forceinline__ void ldsm_x4(unsigned& r0, unsigned& r1,
                                        unsigned& r2, unsigned& r3, unsigned addr) {
    asm volatile("ldmatrix.sync.aligned.m8n8.x4.shared.b16 {%0,%1,%2,%3}, [%4];"
                 : "=r"(r0), "=r"(r1), "=r"(r2), "=r"(r3) : "r"(addr));
}
__device__ __forceinline__ void ldsm_x2t(unsigned& r0, unsigned& r1, unsigned addr) {
    asm volatile("ldmatrix.sync.aligned.m8n8.x2.trans.shared.b16 {%0,%1}, [%2];"
                 : "=r"(r0), "=r"(r1) : "r"(addr));
}
// x4 trans: rows = lane 0..31; (r0,r1) = fragment for rows 0-15, (r2,r3) rows 16-31
__device__ __forceinline__ void ldsm_x4t(unsigned& r0, unsigned& r1,
                                         unsigned& r2, unsigned& r3, unsigned addr) {
    asm volatile("ldmatrix.sync.aligned.m8n8.x4.trans.shared.b16 {%0,%1,%2,%3}, [%4];"
                 : "=r"(r0), "=r"(r1), "=r"(r2), "=r"(r3) : "r"(addr));
}
__device__ __forceinline__ void mma16816(float* c,
                                         unsigned a0, unsigned a1, unsigned a2, unsigned a3,
                                         unsigned b0, unsigned b1) {
    asm volatile(
        "mma.sync.aligned.m16n8k16.row.col.f32.f16.f16.f32 "
        "{%0,%1,%2,%3}, {%4,%5,%6,%7}, {%8,%9}, {%0,%1,%2,%3};"
        : "+f"(c[0]), "+f"(c[1]), "+f"(c[2]), "+f"(c[3])
        : "r"(a0), "r"(a1), "r"(a2), "r"(a3), "r"(b0), "r"(b1));
}
// packed split: hi = f16x2(a,b) (a low), lo = f16x2 residuals
__device__ __forceinline__ void split2(float a, float b, unsigned& hi, unsigned& lo) {
    asm("cvt.rn.f16x2.f32 %0, %1, %2;" : "=r"(hi) : "f"(b), "f"(a));
    __half2 hh = *reinterpret_cast<__half2*>(&hi);
    float2 f = __half22float2(hh);
    float ra = a - f.x, rb = b - f.y;
    asm("cvt.rn.f16x2.f32 %0, %1, %2;" : "=r"(lo) : "f"(rb), "f"(ra));
}
__device__ __forceinline__ unsigned long long pk64(unsigned lo32, unsigned hi32) {
    return ((unsigned long long)hi32 << 32) | lo32;
}

// ---------------------------------------------------------------------------
// Init: zero node accumulators + split both phase-weight banks (one launch).
// ---------------------------------------------------------------------------
__global__ void k_init(const float* __restrict__ Wx1, const float* __restrict__ Wx2,
                       const float* __restrict__ Wx3, const float* __restrict__ Wc1,
                       const float* __restrict__ Ws1, const float* __restrict__ We1,
                       int N) {
    int i = blockIdx.x * blockDim.x + threadIdx.x;
    if (i < N) { g_chis[i] = 0.f; g_sigA[i] = 0.f; g_epsA[i] = 0.f; }
    if (i < 2) g_scal[i] = 0.f;

    const float s80 = 0.11180339887498949f;
    const float s32 = 0.17677669529663689f;
    const float s64 = 0.125f;

    if (i < 5760) {
        int row = i / 40, n = i - row * 40;
        float v = 0.f;
        if (n < 32) {
            if (row < 80)       v = Wx1[row * 32 + n] * s80;
            else if (row < 112) v = Wx2[(row - 80) * 32 + n] * s32;
            else                v = Wx3[(row - 112) * 32 + n] * s32;
        }
        __half h = __float2half_rn(v);
        gWall[i] = h;
        gWall[5760 + i] = __float2half_rn(v - __half2float(h));
    }
    if (i < 5632) {
        int k = i / 88, h = i - k * 88;
        float v = 0.f;
        if (h < 16)      v = Wc1[k * 16 + h] * s64;
        else if (h < 48) v = Ws1[k * 32 + (h - 16)] * s64;
        else if (h < 80) v = We1[k * 32 + (h - 48)] * s64;
        __half hh = __float2half_rn(v);
        gW1all[i] = hh;
        gW1all[5632 + i] = __float2half_rn(v - __half2float(hh));
    }
}

// ---------------------------------------------------------------------------
// Phase 1 (tensor cores): 256 threads, 128-edge tiles, 3 CTAs/SM.
// x4t B-ldsm batching; V copy folded in (independent work, DRAM headroom).
// ---------------------------------------------------------------------------
#define LDA1 136
#define LDW1 88
#define P1_TILES 4
#define P1_SMEM (128 * LDA1 * 2 + 11264 * 2 + 320)

__global__ __launch_bounds__(256, 3) void k_phase1(
    const float* __restrict__ x, const int* __restrict__ senders,
    const float* __restrict__ V, float* __restrict__ out_V, int E)
{
    extern __shared__ __align__(16) char dyn1[];
    __half* sA = reinterpret_cast<__half*>(dyn1);
    __half* sW = sA + 128 * LDA1;
    float* sw2s = reinterpret_cast<float*>(sW + 11264);

    int tid = threadIdx.x;
    {
        const uint4* src = reinterpret_cast<const uint4*>(gW1all);
        uint4* dst = reinterpret_cast<uint4*>(sW);
        for (int i = tid; i < 11264 / 8; i += 256) dst[i] = src[i];
    }
    if (tid < 80) {
        const float s32c = 0.17677669529663689f;
        float v;
        if (tid < 16)      v = cWc2[tid] * 0.25f;
        else if (tid < 48) v = cWs2[tid - 16] * s32c;
        else               v = cWe2[tid - 48] * s32c;
        sw2s[tid] = v;
    }
    const __half* sWh = sW;
    const __half* sWl = sW + 5632;

    int lane = tid & 31;
    int wid  = tid >> 5;
    int rb   = wid * 16;
    int col  = (lane & 3) * 2;

#pragma unroll 1
    for (int t = 0; t < P1_TILES; t++) {
        int eb = (blockIdx.x * P1_TILES + t) * 128;
        if (eb >= E) break;

        // ---- stage A: x (cols 0..63 hi, 64..127 lo), ST.64 ----
        for (int i = tid; i < 128 * 16; i += 256) {
            int r = i >> 4, q = i & 15;
            int e = eb + r;
            float4 v = make_float4(0.f, 0.f, 0.f, 0.f);
            if (e < E) v = reinterpret_cast<const float4*>(x)[(size_t)e * 16 + q];
            unsigned h01, l01, h23, l23;
            split2(v.x, v.y, h01, l01);
            split2(v.z, v.w, h23, l23);
            __half* Ar = sA + r * LDA1;
            *reinterpret_cast<unsigned long long*>(Ar + q * 4)      = pk64(h01, h23);
            *reinterpret_cast<unsigned long long*>(Ar + 64 + q * 4) = pk64(l01, l23);
        }
        __syncthreads();

        // ---- prefetch next tile into L2 ----
        if (t + 1 < P1_TILES) {
            int ebn = eb + 128;
            if (ebn + (tid >> 1) < E)
                prefetchL2(x + (size_t)ebn * 64 + tid * 32);
            if (tid < 4 && ebn + tid * 32 < E)
                prefetchL2(senders + ebn + tid * 32);
        }

        // ---- A fragments: 8 k-blocks (0..3 hi, 4..7 lo) ----
        unsigned a[8][4];
        {
            const __half* ap = sA + (rb + (lane & 15)) * LDA1 + (lane >> 4) * 8;
#pragma unroll
            for (int kb = 0; kb < 8; kb++)
                ldsm_x4(a[kb][0], a[kb][1], a[kb][2], a[kb][3], smaddr(ap + kb * 16));
        }

        // ---- per-nt: MMA chain (x4t B loads) then immediate epilogue ----
        float sc0 = 0.f, sc1 = 0.f, ss0 = 0.f, ss1 = 0.f, se0 = 0.f, se1 = 0.f;
#pragma unroll
        for (int nt = 0; nt < 10; nt++) {
            float c[4] = {0.f, 0.f, 0.f, 0.f};
#pragma unroll
            for (int kb2 = 0; kb2 < 2; kb2++) {
                unsigned bh0, bh1, bh2, bh3, bl0, bl1, bl2, bl3;
                ldsm_x4t(bh0, bh1, bh2, bh3,
                         smaddr(sWh + (kb2 * 32 + lane) * LDW1 + nt * 8));
                ldsm_x4t(bl0, bl1, bl2, bl3,
                         smaddr(sWl + (kb2 * 32 + lane) * LDW1 + nt * 8));
                int kb = kb2 * 2;
                mma16816(c, a[kb][0], a[kb][1], a[kb][2], a[kb][3], bh0, bh1);
                mma16816(c, a[kb + 4][0], a[kb + 4][1], a[kb + 4][2], a[kb + 4][3], bh0, bh1);
                mma16816(c, a[kb][0], a[kb][1], a[kb][2], a[kb][3], bl0, bl1);
                mma16816(c, a[kb + 1][0], a[kb + 1][1], a[kb + 1][2], a[kb + 1][3], bh2, bh3);
                mma16816(c, a[kb + 5][0], a[kb + 5][1], a[kb + 5][2], a[kb + 5][3], bh2, bh3);
                mma16816(c, a[kb + 1][0], a[kb + 1][1], a[kb + 1][2], a[kb + 1][3], bl2, bl3);
            }
            float w0 = sw2s[nt * 8 + col];
            float w1 = sw2s[nt * 8 + col + 1];
            float v0 = siluf(c[0]) * w0 + siluf(c[1]) * w1;
            float v1 = siluf(c[2]) * w0 + siluf(c[3]) * w1;
            if (nt < 2)      { sc0 += v0; sc1 += v1; }
            else if (nt < 6) { ss0 += v0; ss1 += v1; }
            else             { se0 += v0; se1 += v1; }
        }

        // quad reduce
#pragma unroll
        for (int m = 1; m < 4; m <<= 1) {
            sc0 += __shfl_xor_sync(0xffffffffu, sc0, m);
            sc1 += __shfl_xor_sync(0xffffffffu, sc1, m);
            ss0 += __shfl_xor_sync(0xffffffffu, ss0, m);
            ss1 += __shfl_xor_sync(0xffffffffu, ss1, m);
            se0 += __shfl_xor_sync(0xffffffffu, se0, m);
            se1 += __shfl_xor_sync(0xffffffffu, se1, m);
        }
        if ((lane & 3) == 0) {
            int e0 = eb + rb + (lane >> 2);
            int e1 = e0 + 8;
            if (e0 < E) {
                int s = senders[e0];
                atomicAdd(&g_chis[s], sc0);
                atomicAdd(&g_sigA[s], ss0);
                atomicAdd(&g_epsA[s], se0);
            }
            if (e1 < E) {
                int s = senders[e1];
                atomicAdd(&g_chis[s], sc1);
                atomicAdd(&g_sigA[s], ss1);
                atomicAdd(&g_epsA[s], se1);
            }
        }

        // ---- V copy (independent; balances DRAM between phases) ----
        for (int i = tid; i < 128 * 4; i += 256) {
            int e = eb + (i >> 2);
            if (e < E) {
                reinterpret_cast<float4*>(out_V)[(size_t)e * 4 + (i & 3)] =
                    reinterpret_cast<const float4*>(V)[(size_t)e * 4 + (i & 3)];
            }
        }
        __syncthreads();
    }
}

// ---------------------------------------------------------------------------
// Phase 2 (unchanged): per-node charges / pot / vdw / w embedding.
// ---------------------------------------------------------------------------
__global__ __launch_bounds__(256) void k_nodes(
    const int* __restrict__ species, const float* __restrict__ radius,
    const float* __restrict__ hardness, const float* __restrict__ charge_embed,
    float* __restrict__ out_charges, int N)
{
    int n = blockIdx.x * 256 + threadIdx.x;
    float potc = 0.f, vdwc = 0.f;
    if (n < N) {
        int sp = species[n];
        float gamma = fmaf(4.f, radius[sp], 0.5f);
        float hv = hardness[sp];
        float hard = fmaxf(hv, 0.f) + log1pf(__expf(-fabsf(hv)));
        float chis = g_chis[n];
        float q = -chis / hard;
        potc = 0.5f * (hard + 1.f / gamma) * q * q + chis * q;
        float sgv = sigmf(g_sigA[n]) * 0.15f + 0.15f;
        float epv = sigmf(g_epsA[n]) * 1.7f + 0.3f;
        vdwc = sgv * epv;
        out_charges[n] = q;

        const float s17 = 0.24253562503633297f;
        const float* ce = charge_embed + (size_t)sp * 16;
        float wv[16];
        float qs = q * s17;
#pragma unroll
        for (int j = 0; j < 16; j++) wv[j] = qs * cWw1[j];
#pragma unroll
        for (int i = 0; i < 16; i++) {
            float c = ce[i] * s17;
#pragma unroll
            for (int j = 0; j < 16; j++)
                wv[j] = fmaf(c, cWw1[(1 + i) * 16 + j], wv[j]);
        }
        float4* wout = reinterpret_cast<float4*>(g_w) + (size_t)n * 4;
#pragma unroll
        for (int j = 0; j < 4; j++)
            wout[j] = make_float4(wv[4 * j], wv[4 * j + 1], wv[4 * j + 2], wv[4 * j + 3]);
    }
#pragma unroll
    for (int off = 16; off > 0; off >>= 1) {
        potc += __shfl_down_sync(0xffffffffu, potc, off);
        vdwc += __shfl_down_sync(0xffffffffu, vdwc, off);
    }
    if ((threadIdx.x & 31) == 0) {
        atomicAdd(&g_scal[0], potc);
        atomicAdd(&g_scal[1], vdwc);
    }
}

// ---------------------------------------------------------------------------
// Phase 3: tensor cores, 256 threads, 128-edge tiles, 3 CTAs/SM,
// x4t B-ldsm batching, prefetch pipeline. V copy moved out.
// ---------------------------------------------------------------------------
#define LDA 168
#define LDW 40
#define P3_TILES 4
#define P3_SMEM (128 * LDA * 2 + 11520 * 2)

__global__ __launch_bounds__(256, 3) void k_phase3(
    const float* __restrict__ x, const float* __restrict__ vectors,
    const int* __restrict__ senders,
    float* __restrict__ out_x, float* __restrict__ out_pv, int E)
{
    extern __shared__ __align__(16) char dyn3[];
    __half* sA = reinterpret_cast<__half*>(dyn3);
    __half* sW = sA + 128 * LDA;

    int tid = threadIdx.x;

    if (blockIdx.x == 0 && tid == 0) {
        out_pv[0] = g_scal[0];
        out_pv[1] = g_scal[1];
    }

    {
        const uint4* src = reinterpret_cast<const uint4*>(gWall);
        uint4* dst = reinterpret_cast<uint4*>(sW);
        for (int i = tid; i < 11520 / 8; i += 256) dst[i] = src[i];
    }

    const __half* sW1h = sW;
    const __half* sW2h = sW + 80 * LDW;
    const __half* sW3h = sW + 112 * LDW;
    const __half* sW1l = sW + 5760;
    const __half* sW2l = sW + 5760 + 80 * LDW;
    const __half* sW3l = sW + 5760 + 112 * LDW;

    int lane = tid & 31;
    int wid  = tid >> 5;
    int rb   = wid * 16;
    int brow = lane & 15;

#pragma unroll 1
    for (int t = 0; t < P3_TILES; t++) {
        int eb = (blockIdx.x * P3_TILES + t) * 128;
        if (eb >= E) break;

        // ---- prefetch current tile epilogue data (vectors) ----
        if (tid < 12 && eb + tid * 10 < E)
            prefetchL2(vectors + (size_t)eb * 3 + tid * 32);

        // ---- stage A: x + w-gather (ST.64) ----
        for (int i = tid; i < 128 * 16; i += 256) {
            int r = i >> 4, q = i & 15;
            int e = eb + r;
            float4 v = make_float4(0.f, 0.f, 0.f, 0.f);
            if (e < E) v = reinterpret_cast<const float4*>(x)[(size_t)e * 16 + q];
            unsigned h01, l01, h23, l23;
            split2(v.x, v.y, h01, l01);
            split2(v.z, v.w, h23, l23);
            __half* Ar = sA + r * LDA;
            *reinterpret_cast<unsigned long long*>(Ar + q * 4)      = pk64(h01, h23);
            *reinterpret_cast<unsigned long long*>(Ar + 80 + q * 4) = pk64(l01, l23);
        }
        for (int i = tid; i < 128 * 4; i += 256) {
            int r = i >> 2, q = i & 3;
            int e = eb + r;
            float4 v = make_float4(0.f, 0.f, 0.f, 0.f);
            if (e < E) {
                int s = senders[e];
                v = reinterpret_cast<const float4*>(g_w)[(size_t)s * 4 + q];
            }
            unsigned h01, l01, h23, l23;
            split2(v.x, v.y, h01, l01);
            split2(v.z, v.w, h23, l23);
            __half* Ar = sA + r * LDA;
            *reinterpret_cast<unsigned long long*>(Ar + 64 + q * 4)  = pk64(h01, h23);
            *reinterpret_cast<unsigned long long*>(Ar + 144 + q * 4) = pk64(l01, l23);
        }
        __syncthreads();

        // ---- prefetch next tile (x, senders, resolved g_w rows) ----
        if (t + 1 < P3_TILES) {
            int ebn = eb + 128;
            if (ebn + (tid >> 1) < E)
                prefetchL2(x + (size_t)ebn * 64 + tid * 32);
            if (tid < 4 && ebn + tid * 32 < E)
                prefetchL2(senders + ebn + tid * 32);
            if (tid < 128) {
                int e = ebn + tid;
                if (e < E) {
                    int sn = senders[e];
                    prefetchL2(g_w + (size_t)sn * 16);
                }
            }
        }

        unsigned a[10][4];
        {
            const __half* ap = sA + (rb + (lane & 15)) * LDA + (lane >> 4) * 8;
#pragma unroll
            for (int kb = 0; kb < 10; kb++)
                ldsm_x4(a[kb][0], a[kb][1], a[kb][2], a[kb][3], smaddr(ap + kb * 16));
        }

        // ---- layer 1: kb2 x4t pairs + k5=4 tail x2t ----
        float c1[4][4];
#pragma unroll
        for (int nt = 0; nt < 4; nt++)
#pragma unroll
            for (int j = 0; j < 4; j++) c1[nt][j] = 0.f;
#pragma unroll
        for (int nt = 0; nt < 4; nt++) {
#pragma unroll
            for (int kb2 = 0; kb2 < 2; kb2++) {
                unsigned bh0, bh1, bh2, bh3, bl0, bl1, bl2, bl3;
                ldsm_x4t(bh0, bh1, bh2, bh3,
                         smaddr(sW1h + (kb2 * 32 + lane) * LDW + nt * 8));
                ldsm_x4t(bl0, bl1, bl2, bl3,
                         smaddr(sW1l + (kb2 * 32 + lane) * LDW + nt * 8));
                int k5 = kb2 * 2;
                mma16816(c1[nt], a[k5][0], a[k5][1], a[k5][2], a[k5][3], bh0, bh1);
                mma16816(c1[nt], a[k5 + 5][0], a[k5 + 5][1], a[k5 + 5][2], a[k5 + 5][3], bh0, bh1);
                mma16816(c1[nt], a[k5][0], a[k5][1], a[k5][2], a[k5][3], bl0, bl1);
                mma16816(c1[nt], a[k5 + 1][0], a[k5 + 1][1], a[k5 + 1][2], a[k5 + 1][3], bh2, bh3);
                mma16816(c1[nt], a[k5 + 6][0], a[k5 + 6][1], a[k5 + 6][2], a[k5 + 6][3], bh2, bh3);
                mma16816(c1[nt], a[k5 + 1][0], a[k5 + 1][1], a[k5 + 1][2], a[k5 + 1][3], bl2, bl3);
            }
            {
                unsigned bh0, bh1, bl0, bl1;
                ldsm_x2t(bh0, bh1, smaddr(sW1h + (64 + brow) * LDW + nt * 8));
                ldsm_x2t(bl0, bl1, smaddr(sW1l + (64 + brow) * LDW + nt * 8));
                mma16816(c1[nt], a[4][0], a[4][1], a[4][2], a[4][3], bh0, bh1);
                mma16816(c1[nt], a[9][0], a[9][1], a[9][2], a[9][3], bh0, bh1);
                mma16816(c1[nt], a[4][0], a[4][1], a[4][2], a[4][3], bl0, bl1);
            }
        }

        unsigned ah[2][4], al[2][4];
#pragma unroll
        for (int p = 0; p < 2; p++) {
            split2(siluf(c1[2 * p][0]),     siluf(c1[2 * p][1]),     ah[p][0], al[p][0]);
            split2(siluf(c1[2 * p][2]),     siluf(c1[2 * p][3]),     ah[p][1], al[p][1]);
            split2(siluf(c1[2 * p + 1][0]), siluf(c1[2 * p + 1][1]), ah[p][2], al[p][2]);
            split2(siluf(c1[2 * p + 1][2]), siluf(c1[2 * p + 1][3]), ah[p][3], al[p][3]);
        }

        // ---- layer 2 (one x4t covers all 32 k-rows) ----
        float c2[4][4];
#pragma unroll
        for (int nt = 0; nt < 4; nt++)
#pragma unroll
            for (int j = 0; j < 4; j++) c2[nt][j] = 0.f;
#pragma unroll
        for (int nt = 0; nt < 4; nt++) {
            unsigned bh0, bh1, bh2, bh3, bl0, bl1, bl2, bl3;
            ldsm_x4t(bh0, bh1, bh2, bh3, smaddr(sW2h + lane * LDW + nt * 8));
            ldsm_x4t(bl0, bl1, bl2, bl3, smaddr(sW2l + lane * LDW + nt * 8));
            mma16816(c2[nt], ah[0][0], ah[0][1], ah[0][2], ah[0][3], bh0, bh1);
            mma16816(c2[nt], al[0][0], al[0][1], al[0][2], al[0][3], bh0, bh1);
            mma16816(c2[nt], ah[0][0], ah[0][1], ah[0][2], ah[0][3], bl0, bl1);
            mma16816(c2[nt], ah[1][0], ah[1][1], ah[1][2], ah[1][3], bh2, bh3);
            mma16816(c2[nt], al[1][0], al[1][1], al[1][2], al[1][3], bh2, bh3);
            mma16816(c2[nt], ah[1][0], ah[1][1], ah[1][2], ah[1][3], bl2, bl3);
        }
#pragma unroll
        for (int p = 0; p < 2; p++) {
            split2(siluf(c2[2 * p][0]),     siluf(c2[2 * p][1]),     ah[p][0], al[p][0]);
            split2(siluf(c2[2 * p][2]),     siluf(c2[2 * p][3]),     ah[p][1], al[p][1]);
            split2(siluf(c2[2 * p + 1][0]), siluf(c2[2 * p + 1][1]), ah[p][2], al[p][2]);
            split2(siluf(c2[2 * p + 1][2]), siluf(c2[2 * p + 1][3]), ah[p][3], al[p][3]);
        }

        // ---- layer 3 (no activation) ----
        float c3[4][4];
#pragma unroll
        for (int nt = 0; nt < 4; nt++)
#pragma unroll
            for (int j = 0; j < 4; j++) c3[nt][j] = 0.f;
#pragma unroll
        for (int nt = 0; nt < 4; nt++) {
            unsigned bh0, bh1, bh2, bh3, bl0, bl1, bl2, bl3;
            ldsm_x4t(bh0, bh1, bh2, bh3, smaddr(sW3h + lane * LDW + nt * 8));
            ldsm_x4t(bl0, bl1, bl2, bl3, smaddr(sW3l + lane * LDW + nt * 8));
            mma16816(c3[nt], ah[0][0], ah[0][1], ah[0][2], ah[0][3], bh0, bh1);
            mma16816(c3[nt], al[0][0], al[0][1], al[0][2], al[0][3], bh0, bh1);
            mma16816(c3[nt], ah[0][0], ah[0][1], ah[0][2], ah[0][3], bl0, bl1);
            mma16816(c3[nt], ah[1][0], ah[1][1], ah[1][2], ah[1][3], bh2, bh3);
            mma16816(c3[nt], al[1][0], al[1][1], al[1][2], al[1][3], bh2, bh3);
            mma16816(c3[nt], ah[1][0], ah[1][1], ah[1][2], ah[1][3], bl2, bl3);
        }

        int r0 = rb + (lane >> 2);
        int e0 = eb + r0, e1 = e0 + 8;
        float env0 = 0.f, env1 = 0.f;
        if (e0 < E) {
            const float* vp = vectors + (size_t)e0 * 3;
            float u = sqrtf(vp[0] * vp[0] + vp[1] * vp[1] + vp[2] * vp[2]);
            if (u < 1.f) {
                float u2 = u * u, u6 = u2 * u2 * u2;
                env0 = 1.f + u6 * (-28.f + u * (48.f - 21.f * u));
            }
        }
        if (e1 < E) {
            const float* vp = vectors + (size_t)e1 * 3;
            float u = sqrtf(vp[0] * vp[0] + vp[1] * vp[1] + vp[2] * vp[2]);
            if (u < 1.f) {
                float u2 = u * u, u6 = u2 * u2 * u2;
                env1 = 1.f + u6 * (-28.f + u * (48.f - 21.f * u));
            }
        }
        int col0 = (lane & 3) * 2;
#pragma unroll
        for (int nt = 0; nt < 4; nt++) {
            int c = nt * 8 + col0;
            if (e0 < E) {
                float2 v = make_float2(env0 * c3[nt][0], env0 * c3[nt][1]);
                *reinterpret_cast<float2*>(out_x + (size_t)e0 * 32 + c) = v;
            }
            if (e1 < E) {
                float2 v = make_float2(env1 * c3[nt][2], env1 * c3[nt][3]);
                *reinterpret_cast<float2*>(out_x + (size_t)e1 * 32 + c) = v;
            }
        }
        __syncthreads();
    }
}

// ---------------------------------------------------------------------------
// Launch. Output layout: x_out[E*32] | V[E*16] | charges[N] | pot | vdw
// ---------------------------------------------------------------------------
extern "C" void kernel_launch(void* const* d_in, const int* in_sizes, int n_in,
                              void* d_out, int out_size) {
    const float* vectors = (const float*)d_in[0];
    const float* x       = (const float*)d_in[1];
    const float* V       = (const float*)d_in[2];
    const int*   senders = (const int*)d_in[3];
    const int*   species = (const int*)d_in[4];
    const float* radius  = (const float*)d_in[5];
    const float* hardness= (const float*)d_in[6];
    const float* cembed  = (const float*)d_in[7];
    const float* Wc1 = (const float*)d_in[8];
    const float* Ws1 = (const float*)d_in[10];
    const float* We1 = (const float*)d_in[12];
    const float* Ww1 = (const float*)d_in[14];
    const float* Wx1 = (const float*)d_in[15];
    const float* Wx2 = (const float*)d_in[16];
    const float* Wx3 = (const float*)d_in[17];

    const int E = in_sizes[3];
    const int N = in_sizes[4];

    cudaFuncSetAttribute(k_phase1, cudaFuncAttributeMaxDynamicSharedMemorySize, P1_SMEM);
    cudaFuncSetAttribute(k_phase3, cudaFuncAttributeMaxDynamicSharedMemorySize, P3_SMEM);

    cudaMemcpyToSymbolAsync(cWc2, d_in[9],  16 * 4, 0, cudaMemcpyDeviceToDevice, 0);
    cudaMemcpyToSymbolAsync(cWs2, d_in[11], 32 * 4, 0, cudaMemcpyDeviceToDevice, 0);
    cudaMemcpyToSymbolAsync(cWe2, d_in[13], 32 * 4, 0, cudaMemcpyDeviceToDevice, 0);
    cudaMemcpyToSymbolAsync(cWw1, Ww1, 17 * 16 * 4, 0, cudaMemcpyDeviceToDevice, 0);

    float* out = (float*)d_out;
    float* out_x       = out;
    float* out_V       = out + (size_t)E * 32;
    float* out_charges = out + (size_t)E * 48;
    float* out_pv      = out + (size_t)E * 48 + N;

    int nb_n  = (N + 255) / 256;
    int nb_e1 = (E + 128 * P1_TILES - 1) / (128 * P1_TILES);
    int nb_e3 = (E + 128 * P3_TILES - 1) / (128 * P3_TILES);

    k_init<<<nb_n, 256>>>(Wx1, Wx2, Wx3, Wc1, Ws1, We1, N);
    k_phase1<<<nb_e1, 256, P1_SMEM>>>(x, senders, V, out_V, E);
    k_nodes<<<nb_n, 256>>>(species, radius, hardness, cembed, out_charges, N);
    k_phase3<<<nb_e3, 256, P3_SMEM>>>(x, vectors, senders, out_x, out_pv, E);
}